// round 9
// baseline (speedup 1.0000x reference)
#include <cuda_runtime.h>
#include <cuda_bf16.h>
#include <cstddef>

// ---------------------------------------------------------------------------
// CUTSEncoder: conv1 (FFMA) -> conv2/conv3 (bf16 m16n8k16 implicit GEMM,
// 3-term hi/lo split, pre-packed operands, 2 CTAs/SM, B double-buffered,
// term-major mma ordering to break accumulator RAW chains) ->
// BN finalize -> point epilogue.
// ---------------------------------------------------------------------------

namespace {
constexpr int Bsz  = 16;
constexpr int Himg = 256;
constexpr int Wimg = 256;
constexpr int C0 = 3, C1 = 32, C2 = 64, C3 = 128;
constexpr float EPSV  = 1e-5f;
constexpr float SLOPE = 0.01f;
constexpr float NPIX  = 16.0f * 256.0f * 256.0f;

// conv1 (FFMA) tiling
constexpr int TILE  = 32;
constexpr int KOUT  = 16;
constexpr int NSLOT1 = 8 * 8 * Bsz;

// TC conv tiling: 128 pixels (4 rows x 32 cols), K chunk = 16 ch x 9 taps
constexpr int TCH = 4, TCW = 32;
constexpr int HR  = TCH + 2;            // 6 halo rows
constexpr int CCH = 16, KC = 144, KSTEPS = 9;
constexpr int ASTRW = 148;              // A row stride in 32-bit words
constexpr int BROW = 36;
constexpr int BCH  = HR * BROW;         // 216 words per halo channel
constexpr int NSLOT_TC = 8 * 64 * Bsz;  // 8192 slots

// output layout
constexpr int OFF_XA = 0;
constexpr int OFF_XR = Bsz * 147;
constexpr int OFF_ZA = OFF_XR + Bsz * 147;
constexpr int OFF_ZP = OFF_ZA + Bsz * C3;
}

// ------------------------- scratch (device globals) -------------------------
__device__ float    g_y1[(size_t)Bsz * C1 * Himg * Wimg];
__device__ float    g_y2[(size_t)Bsz * C2 * Himg * Wimg];
__device__ __align__(16) unsigned g_y1pk[(size_t)Bsz * C1 * Himg * Wimg];
__device__ __align__(16) unsigned g_y2pk[(size_t)Bsz * C2 * Himg * Wimg];

__device__ __align__(16) unsigned g_w2pk[(C1 / CCH) * C2 * ASTRW];
__device__ __align__(16) unsigned g_w3pk[(C2 / CCH) * C3 * ASTRW];

__device__ float g_ps1[C1 * NSLOT1],   g_pq1[C1 * NSLOT1];
__device__ float g_ps2[C2 * NSLOT_TC], g_pq2[C2 * NSLOT_TC];
__device__ float g_ps3[C3 * NSLOT_TC], g_pq3[C3 * NSLOT_TC];

__device__ float g_scale1[C1], g_shift1[C1];
__device__ float g_scale2[C2], g_shift2[C2];
__device__ float g_scale3[C3], g_shift3[C3];

// ------------------------------- helpers ------------------------------------
__device__ __forceinline__ unsigned bf16x2pack(float hi, float lo) {
    unsigned w;
    asm("cvt.rn.bf16x2.f32 %0, %1, %2;" : "=r"(w) : "f"(hi), "f"(lo));
    return w;
}

__device__ __forceinline__ unsigned prmt(unsigned a, unsigned b, unsigned sel) {
    unsigned r;
    asm("prmt.b32 %0, %1, %2, %3;" : "=r"(r) : "r"(a), "r"(b), "r"(sel));
    return r;
}

__device__ __forceinline__ void mma_bf16(float* d, const unsigned* a,
                                         unsigned b0, unsigned b1) {
    asm volatile(
        "mma.sync.aligned.m16n8k16.row.col.f32.bf16.bf16.f32 "
        "{%0,%1,%2,%3}, {%4,%5,%6,%7}, {%8,%9}, {%0,%1,%2,%3};"
        : "+f"(d[0]), "+f"(d[1]), "+f"(d[2]), "+f"(d[3])
        : "r"(a[0]), "r"(a[1]), "r"(a[2]), "r"(a[3]), "r"(b0), "r"(b1));
}

__device__ __forceinline__ void cp_async16(void* smem, const void* gmem) {
    unsigned saddr = (unsigned)__cvta_generic_to_shared(smem);
    asm volatile("cp.async.cg.shared.global [%0], [%1], 16;"
                 :: "r"(saddr), "l"(gmem));
}

__device__ __forceinline__ void cp_async4z(void* smem, const void* gmem, int sz) {
    unsigned saddr = (unsigned)__cvta_generic_to_shared(smem);
    asm volatile("cp.async.ca.shared.global [%0], [%1], 4, %2;"
                 :: "r"(saddr), "l"(gmem), "r"(sz));
}

// --------------------- weight pre-pack (hi/lo mma layout) --------------------
__global__ void prep_weights(const float* __restrict__ w, int CIN, int M,
                             unsigned* __restrict__ dst)
{
    int idx = blockIdx.x * blockDim.x + threadIdx.x;
    int NCH = CIN / CCH;
    int tot = NCH * M * (KC / 2);
    if (idx >= tot) return;
    int cc  = idx / (M * (KC / 2));
    int rem = idx - cc * M * (KC / 2);
    int m   = rem / (KC / 2);
    int pr  = rem - m * (KC / 2);
    int ks = pr >> 3, j = pr & 7, kh = j >> 2, qq = j & 3;
    int ke = ks * 16 + kh * 8 + 2 * qq;
    int c0 = cc * CCH;
    float we = w[((size_t)m * CIN + c0 + ke / 9) * 9 + (ke % 9)];
    float wo = w[((size_t)m * CIN + c0 + (ke + 1) / 9) * 9 + ((ke + 1) % 9)];
    float heF = __bfloat162float(__float2bfloat16(we));
    float hoF = __bfloat162float(__float2bfloat16(wo));
    size_t base = ((size_t)cc * M + m) * ASTRW + ks * 16 + qq * 4;
    dst[base + kh]     = bf16x2pack(wo, we);
    dst[base + 2 + kh] = bf16x2pack(wo - hoF, we - heF);
}

// ----------------- bnpack: raw y -> packed BN+LReLU (hi,lo) ------------------
__global__ void __launch_bounds__(256) bnpack_kernel(
    const float* __restrict__ raw,
    const float* __restrict__ scale, const float* __restrict__ shift,
    unsigned* __restrict__ dst, int C, long long total4)
{
    long long i4 = (long long)blockIdx.x * blockDim.x + threadIdx.x;
    if (i4 >= total4) return;
    float4 v = ((const float4*)raw)[i4];
    int c = (int)((i4 * 4) >> 16) % C;
    float sc = __ldg(&scale[c]), sh = __ldg(&shift[c]);
    uint4 o;
    {
        float z = v.x * sc + sh; z = z >= 0.f ? z : SLOPE * z;
        float hf = __bfloat162float(__float2bfloat16(z));
        o.x = bf16x2pack(z, z - hf);
    }
    {
        float z = v.y * sc + sh; z = z >= 0.f ? z : SLOPE * z;
        float hf = __bfloat162float(__float2bfloat16(z));
        o.y = bf16x2pack(z, z - hf);
    }
    {
        float z = v.z * sc + sh; z = z >= 0.f ? z : SLOPE * z;
        float hf = __bfloat162float(__float2bfloat16(z));
        o.z = bf16x2pack(z, z - hf);
    }
    {
        float z = v.w * sc + sh; z = z >= 0.f ? z : SLOPE * z;
        float hf = __bfloat162float(__float2bfloat16(z));
        o.w = bf16x2pack(z, z - hf);
    }
    ((uint4*)dst)[i4] = o;
}

// ---------------- TC conv3x3 (bf16 3-term split, term-major order) -----------
// 256 threads = 8 warps = 2 M-warps x 4 N-warps, 2 CTAs/SM.
template <int CIN, int M, bool STORE>
__global__ void __launch_bounds__(256, 2) conv_tc_kernel(
    const unsigned* __restrict__ in,    // packed (hi,lo) activations
    const unsigned* __restrict__ wpk,   // packed weights [chunk][M][ASTRW]
    const float* __restrict__ bias,
    float* __restrict__ out_raw,
    float* __restrict__ psum,
    float* __restrict__ psq)
{
    constexpr int NMT = M / 32;
    constexpr int NCH = CIN / CCH;
    constexpr int ASZ = M * ASTRW;      // words, single A buffer
    constexpr int BSZ = CCH * BCH;      // words per B buffer

    extern __shared__ unsigned char smem_raw[];
    unsigned* Apk = (unsigned*)smem_raw;          // ASZ
    unsigned* Bp  = Apk + ASZ;                    // 2 * BSZ
    int*   koff  = (int*)(Bp + 2 * BSZ);          // KC
    float* red_s = (float*)(koff + KC);           // 4*M
    float* red_q = red_s + 4 * M;

    const int tid = threadIdx.x;
    const int lane = tid & 31, wid = tid >> 5;
    const int mw = wid >> 2, nw = wid & 3;
    const int q = lane & 3, g = lane >> 2;
    const int bx = blockIdx.x, by = blockIdx.y, b = blockIdx.z;
    const int h0 = by * TCH, w0 = bx * TCW;

    auto stageB = [&](int cc) {
        const int c0 = cc * CCH;
        unsigned* Bd = Bp + (cc & 1) * BSZ;
        for (int idx = tid; idx < CCH * HR * 34; idx += 256) {
            int c   = idx / (HR * 34);
            int rem = idx - c * (HR * 34);
            int r   = rem / 34;
            int col = rem - r * 34;
            int gh = h0 + r - 1, gw = w0 + col - 1;
            bool ok = (unsigned)gh < (unsigned)Himg && (unsigned)gw < (unsigned)Wimg;
            const unsigned* src = ok
                ? &in[(((size_t)b * CIN + c0 + c) * Himg + gh) * Wimg + gw] : in;
            cp_async4z(Bd + c * BCH + r * BROW + col, src, ok ? 4 : 0);
        }
        asm volatile("cp.async.commit_group;" ::: "memory");
    };

    // prefetch B(0) before anything else
    stageB(0);

    if (tid < KC) {
        int c = tid / 9, tap = tid - c * 9;
        koff[tid] = c * BCH + (tap / 3) * BROW + (tap % 3);
    }

    float acc[NMT][4][4];
#pragma unroll
    for (int t = 0; t < NMT; ++t)
#pragma unroll
        for (int nt = 0; nt < 4; ++nt)
#pragma unroll
            for (int i = 0; i < 4; ++i) acc[t][nt][i] = 0.f;

    const int poffbase = nw * BROW + g;

#pragma unroll 1
    for (int cc = 0; cc < NCH; ++cc) {
        // A(cc): single-buffer cp.async from L2-hot packed weights
        {
            const unsigned* srcA = wpk + (size_t)cc * ASZ;
            for (int idx = tid; idx < ASZ / 4; idx += 256)
                cp_async16(Apk + idx * 4, srcA + idx * 4);
            asm volatile("cp.async.commit_group;" ::: "memory");
        }
        if (cc + 1 < NCH) {
            stageB(cc + 1);
            // wait for A(cc) and B(cc); leave B(cc+1) in flight
            asm volatile("cp.async.wait_group 1;" ::: "memory");
        } else {
            asm volatile("cp.async.wait_group 0;" ::: "memory");
        }
        __syncthreads();

        const unsigned* Bb = Bp + (cc & 1) * BSZ;

#pragma unroll
        for (int ks = 0; ks < KSTEPS; ++ks) {
            const int kb = ks * 16;
            // ---- load ALL A fragments for this kstep first ----
            unsigned ah[NMT][4], al[NMT][4];
#pragma unroll
            for (int t = 0; t < NMT; ++t) {
                const int r0w = (mw * (M / 2) + t * 16 + g) * ASTRW + kb + q * 4;
                const int r1w = r0w + 8 * ASTRW;
                uint2 xh = *(const uint2*)(Apk + r0w);
                uint2 yh = *(const uint2*)(Apk + r1w);
                uint2 xl = *(const uint2*)(Apk + r0w + 2);
                uint2 yl = *(const uint2*)(Apk + r1w + 2);
                ah[t][0] = xh.x; ah[t][1] = yh.x; ah[t][2] = xh.y; ah[t][3] = yh.y;
                al[t][0] = xl.x; al[t][1] = yl.x; al[t][2] = xl.y; al[t][3] = yl.y;
            }
            const int ko0 = koff[kb + 2 * q];
            const int ko1 = koff[kb + 2 * q + 1];
            const int ko2 = koff[kb + 2 * q + 8];
            const int ko3 = koff[kb + 2 * q + 9];
            // ---- per n-tile: build B, then term-major mma (chains 4 apart) --
#pragma unroll
            for (int nt = 0; nt < 4; ++nt) {
                const int p = poffbase + nt * 8;
                unsigned w0r = Bb[ko0 + p], w1r = Bb[ko1 + p];
                unsigned w2r = Bb[ko2 + p], w3r = Bb[ko3 + p];
                unsigned bh0 = prmt(w0r, w1r, 0x7632u);
                unsigned bh1 = prmt(w2r, w3r, 0x7632u);
                unsigned bl0 = prmt(w0r, w1r, 0x5410u);
                unsigned bl1 = prmt(w2r, w3r, 0x5410u);
#pragma unroll
                for (int t = 0; t < NMT; ++t)
                    mma_bf16(acc[t][nt], ah[t], bh0, bh1);
#pragma unroll
                for (int t = 0; t < NMT; ++t)
                    mma_bf16(acc[t][nt], al[t], bh0, bh1);
#pragma unroll
                for (int t = 0; t < NMT; ++t)
                    mma_bf16(acc[t][nt], ah[t], bl0, bl1);
            }
        }
        __syncthreads();
    }

    // ---- epilogue: bias, optional store, per-channel stats ----
#pragma unroll
    for (int t = 0; t < NMT; ++t) {
        const int r0 = mw * (M / 2) + t * 16 + g, r1 = r0 + 8;
        const float bv0 = __ldg(&bias[r0]), bv1 = __ldg(&bias[r1]);
        float s0 = 0.f, q0 = 0.f, s1 = 0.f, q1 = 0.f;
#pragma unroll
        for (int nt = 0; nt < 4; ++nt) {
            float v0 = acc[t][nt][0] + bv0, v1 = acc[t][nt][1] + bv0;
            float v2 = acc[t][nt][2] + bv1, v3 = acc[t][nt][3] + bv1;
            if (STORE) {
                int wcol = w0 + nt * 8 + 2 * q;
                int hrow = h0 + nw;
                *(float2*)(out_raw + (((size_t)b * M + r0) * Himg + hrow) * Wimg + wcol) =
                    make_float2(v0, v1);
                *(float2*)(out_raw + (((size_t)b * M + r1) * Himg + hrow) * Wimg + wcol) =
                    make_float2(v2, v3);
            }
            s0 += v0 + v1; q0 += v0 * v0 + v1 * v1;
            s1 += v2 + v3; q1 += v2 * v2 + v3 * v3;
        }
        s0 += __shfl_xor_sync(0xffffffffu, s0, 1);
        s0 += __shfl_xor_sync(0xffffffffu, s0, 2);
        q0 += __shfl_xor_sync(0xffffffffu, q0, 1);
        q0 += __shfl_xor_sync(0xffffffffu, q0, 2);
        s1 += __shfl_xor_sync(0xffffffffu, s1, 1);
        s1 += __shfl_xor_sync(0xffffffffu, s1, 2);
        q1 += __shfl_xor_sync(0xffffffffu, q1, 1);
        q1 += __shfl_xor_sync(0xffffffffu, q1, 2);
        if (q == 0) {
            red_s[nw * M + r0] = s0; red_q[nw * M + r0] = q0;
            red_s[nw * M + r1] = s1; red_q[nw * M + r1] = q1;
        }
    }
    __syncthreads();
    if (tid < M) {
        float s = 0.f, qq = 0.f;
#pragma unroll
        for (int w = 0; w < 4; ++w) { s += red_s[w * M + tid]; qq += red_q[w * M + tid]; }
        int slot = (b * 64 + by) * 8 + bx;
        psum[tid * NSLOT_TC + slot] = s;
        psq [tid * NSLOT_TC + slot] = qq;
    }
}

// -------------------------- conv1 (FFMA, cin=3) ------------------------------
template <int CIN, int CCHUNK>
__global__ void __launch_bounds__(256) conv1_kernel(
    const float* __restrict__ in,
    const float* __restrict__ wgt,
    const float* __restrict__ bias,
    float* __restrict__ out_raw,
    float* __restrict__ psum,
    float* __restrict__ psq,
    int nCoutBlk)
{
    __shared__ float s_in[CCHUNK][TILE + 2][TILE + 2];
    __shared__ float s_w[KOUT * CCHUNK * 9];
    __shared__ float s_rs[KOUT][8];
    __shared__ float s_rq[KOUT][8];

    const int tid = threadIdx.x;
    const int tx = tid & 15, ty = tid >> 4;
    const int bx = blockIdx.x, by = blockIdx.y;
    const int b = blockIdx.z / nCoutBlk;
    const int coutBase = (blockIdx.z % nCoutBlk) * KOUT;
    const int Cout = nCoutBlk * KOUT;
    const int px = tx * 2, py = ty * 2;
    const int h0 = by * TILE, w0 = bx * TILE;

    float acc[KOUT][4];
#pragma unroll
    for (int co = 0; co < KOUT; ++co) {
        acc[co][0] = 0.f; acc[co][1] = 0.f; acc[co][2] = 0.f; acc[co][3] = 0.f;
    }

    for (int idx = tid; idx < CCHUNK * (TILE + 2) * (TILE + 2); idx += 256) {
        int c   = idx / ((TILE + 2) * (TILE + 2));
        int rem = idx - c * (TILE + 2) * (TILE + 2);
        int r   = rem / (TILE + 2);
        int col = rem - r * (TILE + 2);
        int gh = h0 + r - 1, gw = w0 + col - 1;
        float v = 0.f;
        if ((unsigned)gh < (unsigned)Himg && (unsigned)gw < (unsigned)Wimg)
            v = in[(((size_t)b * CIN + c) * Himg + gh) * Wimg + gw];
        (&s_in[0][0][0])[idx] = v;
    }
    for (int idx = tid; idx < KOUT * CCHUNK * 9; idx += 256) {
        int co  = idx / (CCHUNK * 9);
        int rem = idx - co * (CCHUNK * 9);
        s_w[idx] = wgt[((size_t)(coutBase + co) * CIN) * 9 + rem];
    }
    __syncthreads();

#pragma unroll
    for (int c = 0; c < CCHUNK; ++c)
#pragma unroll
        for (int dy = 0; dy < 3; ++dy)
#pragma unroll
            for (int dx = 0; dx < 3; ++dx) {
                float i00 = s_in[c][py + dy][px + dx];
                float i01 = s_in[c][py + dy][px + dx + 1];
                float i10 = s_in[c][py + dy + 1][px + dx];
                float i11 = s_in[c][py + dy + 1][px + dx + 1];
#pragma unroll
                for (int co = 0; co < KOUT; ++co) {
                    float wv = s_w[(co * CCHUNK + c) * 9 + dy * 3 + dx];
                    acc[co][0] = fmaf(i00, wv, acc[co][0]);
                    acc[co][1] = fmaf(i01, wv, acc[co][1]);
                    acc[co][2] = fmaf(i10, wv, acc[co][2]);
                    acc[co][3] = fmaf(i11, wv, acc[co][3]);
                }
            }

    const int lane = tid & 31, wrp = tid >> 5;
#pragma unroll 1
    for (int co = 0; co < KOUT; ++co) {
        float bv = __ldg(&bias[coutBase + co]);
        float v0 = acc[co][0] + bv, v1 = acc[co][1] + bv;
        float v2 = acc[co][2] + bv, v3 = acc[co][3] + bv;
        size_t rowb = ((size_t)b * Cout + coutBase + co) * Himg;
        out_raw[(rowb + h0 + py) * Wimg + w0 + px]         = v0;
        out_raw[(rowb + h0 + py) * Wimg + w0 + px + 1]     = v1;
        out_raw[(rowb + h0 + py + 1) * Wimg + w0 + px]     = v2;
        out_raw[(rowb + h0 + py + 1) * Wimg + w0 + px + 1] = v3;
        float s = v0 + v1 + v2 + v3;
        float qv = v0 * v0 + v1 * v1 + v2 * v2 + v3 * v3;
#pragma unroll
        for (int o = 16; o > 0; o >>= 1) {
            s  += __shfl_down_sync(0xffffffffu, s, o);
            qv += __shfl_down_sync(0xffffffffu, qv, o);
        }
        if (lane == 0) { s_rs[co][wrp] = s; s_rq[co][wrp] = qv; }
    }
    __syncthreads();
    if (tid < KOUT) {
        float s = 0.f, qv = 0.f;
#pragma unroll
        for (int w = 0; w < 8; ++w) { s += s_rs[tid][w]; qv += s_rq[tid][w]; }
        int slot = (by * gridDim.x + bx) * Bsz + b;
        psum[(coutBase + tid) * NSLOT1 + slot] = s;
        psq [(coutBase + tid) * NSLOT1 + slot] = qv;
    }
}

// ------------------------- BN stats finalize ---------------------------------
__global__ void __launch_bounds__(256) bnfin_kernel(
    const float* __restrict__ psum, const float* __restrict__ psq,
    const float* __restrict__ gamma, const float* __restrict__ beta,
    float* __restrict__ scale, float* __restrict__ shift, int nslot)
{
    __shared__ float ss[256], sq[256];
    int c = blockIdx.x;
    float s = 0.f, q = 0.f;
    for (int i = threadIdx.x; i < nslot; i += 256) {
        s += psum[c * nslot + i];
        q += psq [c * nslot + i];
    }
    ss[threadIdx.x] = s; sq[threadIdx.x] = q;
    __syncthreads();
    for (int o = 128; o > 0; o >>= 1) {
        if (threadIdx.x < o) {
            ss[threadIdx.x] += ss[threadIdx.x + o];
            sq[threadIdx.x] += sq[threadIdx.x + o];
        }
        __syncthreads();
    }
    if (threadIdx.x == 0) {
        float mean = ss[0] / NPIX;
        float var  = sq[0] / NPIX - mean * mean;
        float sc   = gamma[c] * rsqrtf(var + EPSV);
        scale[c] = sc;
        shift[c] = beta[c] - mean * sc;
    }
}

// ---------------- final: 32 point z3 vectors + recon + patches ---------------
__global__ void __launch_bounds__(160) points_kernel(
    const float* __restrict__ x,
    const int* __restrict__ anchors,
    const int* __restrict__ positives,
    const float* __restrict__ w3, const float* __restrict__ b3,
    const float* __restrict__ recon_w, const float* __restrict__ recon_b,
    float* __restrict__ out)
{
    __shared__ float s_in[C2 * 9];
    __shared__ float s_z[C3];
    const int kind = blockIdx.x & 1;
    const int b = blockIdx.x >> 1;
    const int* pts = kind ? positives : anchors;
    const int h = pts[b * 8 + 6];
    const int w = pts[b * 8 + 7];
    const int tid = threadIdx.x;

    for (int idx = tid; idx < C2 * 9; idx += 160) {
        int c = idx / 9, tap = idx - c * 9;
        int dy = tap / 3, dx = tap - dy * 3;
        unsigned wv = g_y2pk[(((size_t)b * C2 + c) * Himg + (h + dy - 1)) * Wimg + (w + dx - 1)];
        float hi = __uint_as_float(wv & 0xffff0000u);
        float lo = __uint_as_float(wv << 16);
        s_in[idx] = hi + lo;
    }
    __syncthreads();

    if (tid < C3) {
        float a = b3[tid];
        const float* wr = w3 + (size_t)tid * C2 * 9;
#pragma unroll 4
        for (int i = 0; i < C2 * 9; ++i) a = fmaf(s_in[i], __ldg(&wr[i]), a);
        float z = a * g_scale3[tid] + g_shift3[tid];
        z = z >= 0.f ? z : SLOPE * z;
        s_z[tid] = z;
        out[(kind ? OFF_ZP : OFF_ZA) + b * C3 + tid] = z;
    }
    __syncthreads();

    if (kind == 0) {
        for (int j = tid; j < 147; j += 160) {
            float r = recon_b[j];
            const float* wr = recon_w + (size_t)j * C3;
#pragma unroll 4
            for (int k = 0; k < C3; ++k) r = fmaf(s_z[k], __ldg(&wr[k]), r);
            out[OFF_XR + b * 147 + j] = r;
        }
        for (int idx = tid; idx < 147; idx += 160) {
            int c = idx / 49, rem = idx - c * 49;
            int pyy = rem / 7, pxx = rem - pyy * 7;
            out[OFF_XA + b * 147 + idx] =
                x[(((size_t)b * C0 + c) * Himg + (h - 3 + pyy)) * Wimg + (w - 3 + pxx)];
        }
    }
}

// --------------------------------- launch ------------------------------------
extern "C" void kernel_launch(void* const* d_in, const int* in_sizes, int n_in,
                              void* d_out, int out_size)
{
    const float* x        = (const float*)d_in[0];
    const int*   anchors  = (const int*)  d_in[1];
    const int*   positives= (const int*)  d_in[2];
    const float* c1w = (const float*)d_in[3];
    const float* c1b = (const float*)d_in[4];
    const float* g1  = (const float*)d_in[5];
    const float* be1 = (const float*)d_in[6];
    const float* c2w = (const float*)d_in[7];
    const float* c2b = (const float*)d_in[8];
    const float* g2  = (const float*)d_in[9];
    const float* be2 = (const float*)d_in[10];
    const float* c3w = (const float*)d_in[11];
    const float* c3b = (const float*)d_in[12];
    const float* g3  = (const float*)d_in[13];
    const float* be3 = (const float*)d_in[14];
    const float* rw  = (const float*)d_in[15];
    const float* rb  = (const float*)d_in[16];
    float* out = (float*)d_out;

    float *y1p, *y2p; unsigned *y1pk, *y2pk, *w2pk, *w3pk;
    float *ps1, *pq1, *ps2, *pq2, *ps3, *pq3;
    float *sc1, *sh1, *sc2, *sh2, *sc3, *sh3;
    cudaGetSymbolAddress((void**)&y1p, g_y1);
    cudaGetSymbolAddress((void**)&y2p, g_y2);
    cudaGetSymbolAddress((void**)&y1pk, g_y1pk);
    cudaGetSymbolAddress((void**)&y2pk, g_y2pk);
    cudaGetSymbolAddress((void**)&w2pk, g_w2pk);
    cudaGetSymbolAddress((void**)&w3pk, g_w3pk);
    cudaGetSymbolAddress((void**)&ps1, g_ps1);
    cudaGetSymbolAddress((void**)&pq1, g_pq1);
    cudaGetSymbolAddress((void**)&ps2, g_ps2);
    cudaGetSymbolAddress((void**)&pq2, g_pq2);
    cudaGetSymbolAddress((void**)&ps3, g_ps3);
    cudaGetSymbolAddress((void**)&pq3, g_pq3);
    cudaGetSymbolAddress((void**)&sc1, g_scale1);
    cudaGetSymbolAddress((void**)&sh1, g_shift1);
    cudaGetSymbolAddress((void**)&sc2, g_scale2);
    cudaGetSymbolAddress((void**)&sh2, g_shift2);
    cudaGetSymbolAddress((void**)&sc3, g_scale3);
    cudaGetSymbolAddress((void**)&sh3, g_shift3);

    // dynamic smem: A + 2*B + koff + reductions (words)
    const int smem2 = (C2 * ASTRW + 2 * CCH * BCH + KC + 8 * C2) * 4;
    const int smem3 = (C3 * ASTRW + 2 * CCH * BCH + KC + 8 * C3) * 4;
    cudaFuncSetAttribute(conv_tc_kernel<C1, C2, true>,
                         cudaFuncAttributeMaxDynamicSharedMemorySize, smem2);
    cudaFuncSetAttribute(conv_tc_kernel<C2, C3, false>,
                         cudaFuncAttributeMaxDynamicSharedMemorySize, smem3);

    // weight pre-pack
    {
        int tot2 = (C1 / CCH) * C2 * (KC / 2);
        int tot3 = (C2 / CCH) * C3 * (KC / 2);
        prep_weights<<<(tot2 + 255) / 256, 256>>>(c2w, C1, C2, w2pk);
        prep_weights<<<(tot3 + 255) / 256, 256>>>(c3w, C2, C3, w3pk);
    }

    // conv1 -> raw y1 + stats
    dim3 grid1(8, 8, Bsz * (C1 / KOUT));
    conv1_kernel<C0, 3><<<grid1, 256>>>(x, c1w, c1b, y1p, ps1, pq1, C1 / KOUT);
    bnfin_kernel<<<C1, 256>>>(ps1, pq1, g1, be1, sc1, sh1, NSLOT1);

    // pack bn1(lrelu(y1))
    {
        long long t4 = (long long)Bsz * C1 * Himg * Wimg / 4;
        bnpack_kernel<<<(unsigned)((t4 + 255) / 256), 256>>>(y1p, sc1, sh1, y1pk, C1, t4);
    }

    // conv2 -> raw y2 + stats
    dim3 gridTC(Wimg / TCW, Himg / TCH, Bsz);   // 8 x 64 x 16
    conv_tc_kernel<C1, C2, true><<<gridTC, 256, smem2>>>(
        y1pk, w2pk, c2b, y2p, ps2, pq2);
    bnfin_kernel<<<C2, 256>>>(ps2, pq2, g2, be2, sc2, sh2, NSLOT_TC);

    // pack bn2(lrelu(y2))
    {
        long long t4 = (long long)Bsz * C2 * Himg * Wimg / 4;
        bnpack_kernel<<<(unsigned)((t4 + 255) / 256), 256>>>(y2p, sc2, sh2, y2pk, C2, t4);
    }

    // conv3 -> stats only
    conv_tc_kernel<C2, C3, false><<<gridTC, 256, smem3>>>(
        y2pk, w3pk, c3b, nullptr, ps3, pq3);
    bnfin_kernel<<<C3, 256>>>(ps3, pq3, g3, be3, sc3, sh3, NSLOT_TC);

    // final epilogue
    points_kernel<<<32, 160>>>(x, anchors, positives, c3w, c3b, rw, rb, out);
}

// round 11
// speedup vs baseline: 1.1979x; 1.1979x over previous
#include <cuda_runtime.h>
#include <cuda_fp16.h>
#include <cstddef>

// ---------------------------------------------------------------------------
// CUTSEncoder: conv1 (FFMA) -> conv2/conv3 (fp16 m16n8k16 implicit GEMM,
// 2-term hi/lo split: W exactly split to fp16 hi+lo, activations single fp16.
// D = Wh*Xh + Wl*Xh  (dropped term Wh*Xl ~ 2^-12 -> rel_err ~1e-4).
// Pre-packed operands, 2 CTAs/SM, B halo double-buffered via cp.async) ->
// BN finalize -> point epilogue.
// ---------------------------------------------------------------------------

namespace {
constexpr int Bsz  = 16;
constexpr int Himg = 256;
constexpr int Wimg = 256;
constexpr int C0 = 3, C1 = 32, C2 = 64, C3 = 128;
constexpr float EPSV  = 1e-5f;
constexpr float SLOPE = 0.01f;
constexpr float NPIX  = 16.0f * 256.0f * 256.0f;

// conv1 (FFMA) tiling
constexpr int TILE  = 32;
constexpr int KOUT  = 16;
constexpr int NSLOT1 = 8 * 8 * Bsz;

// TC conv tiling: 128 pixels (4 rows x 32 cols), K chunk = 16 ch x 9 taps
constexpr int TCH = 4, TCW = 32;
constexpr int HR  = TCH + 2;            // 6 halo rows
constexpr int CCH = 16, KC = 144, KSTEPS = 9;
constexpr int ASTRW = 148;              // A row stride in 32-bit words
constexpr int BROW = 36;
constexpr int BCH  = HR * BROW;         // 216 words per halo channel
constexpr int NSLOT_TC = 8 * 64 * Bsz;  // 8192 slots

// output layout
constexpr int OFF_XA = 0;
constexpr int OFF_XR = Bsz * 147;
constexpr int OFF_ZA = OFF_XR + Bsz * 147;
constexpr int OFF_ZP = OFF_ZA + Bsz * C3;
}

// ------------------------- scratch (device globals) -------------------------
__device__ float    g_y1[(size_t)Bsz * C1 * Himg * Wimg];
__device__ float    g_y2[(size_t)Bsz * C2 * Himg * Wimg];
__device__ __align__(16) unsigned g_y1pk[(size_t)Bsz * C1 * Himg * Wimg]; // {f16 hi, f16 lo}
__device__ __align__(16) unsigned g_y2pk[(size_t)Bsz * C2 * Himg * Wimg];

__device__ __align__(16) unsigned g_w2pk[(C1 / CCH) * C2 * ASTRW];
__device__ __align__(16) unsigned g_w3pk[(C2 / CCH) * C3 * ASTRW];

__device__ float g_ps1[C1 * NSLOT1],   g_pq1[C1 * NSLOT1];
__device__ float g_ps2[C2 * NSLOT_TC], g_pq2[C2 * NSLOT_TC];
__device__ float g_ps3[C3 * NSLOT_TC], g_pq3[C3 * NSLOT_TC];

__device__ float g_scale1[C1], g_shift1[C1];
__device__ float g_scale2[C2], g_shift2[C2];
__device__ float g_scale3[C3], g_shift3[C3];

// ------------------------------- helpers ------------------------------------
// pack {[31:16]=f16(a), [15:0]=f16(b)} into one 32-bit word
__device__ __forceinline__ unsigned f16x2pack(float a, float b) {
    unsigned w;
    asm("cvt.rn.f16x2.f32 %0, %1, %2;" : "=r"(w) : "f"(a), "f"(b));
    return w;
}

__device__ __forceinline__ unsigned prmt(unsigned a, unsigned b, unsigned sel) {
    unsigned r;
    asm("prmt.b32 %0, %1, %2, %3;" : "=r"(r) : "r"(a), "r"(b), "r"(sel));
    return r;
}

__device__ __forceinline__ void mma_f16(float* d, const unsigned* a,
                                        unsigned b0, unsigned b1) {
    asm volatile(
        "mma.sync.aligned.m16n8k16.row.col.f32.f16.f16.f32 "
        "{%0,%1,%2,%3}, {%4,%5,%6,%7}, {%8,%9}, {%0,%1,%2,%3};"
        : "+f"(d[0]), "+f"(d[1]), "+f"(d[2]), "+f"(d[3])
        : "r"(a[0]), "r"(a[1]), "r"(a[2]), "r"(a[3]), "r"(b0), "r"(b1));
}

__device__ __forceinline__ void cp_async16(void* smem, const void* gmem) {
    unsigned saddr = (unsigned)__cvta_generic_to_shared(smem);
    asm volatile("cp.async.cg.shared.global [%0], [%1], 16;"
                 :: "r"(saddr), "l"(gmem));
}

__device__ __forceinline__ void cp_async4z(void* smem, const void* gmem, int sz) {
    unsigned saddr = (unsigned)__cvta_generic_to_shared(smem);
    asm volatile("cp.async.ca.shared.global [%0], [%1], 4, %2;"
                 :: "r"(saddr), "l"(gmem), "r"(sz));
}

// --------------------- weight pre-pack (fp16 hi/lo mma layout) ---------------
__global__ void prep_weights(const float* __restrict__ w, int CIN, int M,
                             unsigned* __restrict__ dst)
{
    int idx = blockIdx.x * blockDim.x + threadIdx.x;
    int NCH = CIN / CCH;
    int tot = NCH * M * (KC / 2);
    if (idx >= tot) return;
    int cc  = idx / (M * (KC / 2));
    int rem = idx - cc * M * (KC / 2);
    int m   = rem / (KC / 2);
    int pr  = rem - m * (KC / 2);
    int ks = pr >> 3, j = pr & 7, kh = j >> 2, qq = j & 3;
    int ke = ks * 16 + kh * 8 + 2 * qq;
    int c0 = cc * CCH;
    float we = w[((size_t)m * CIN + c0 + ke / 9) * 9 + (ke % 9)];
    float wo = w[((size_t)m * CIN + c0 + (ke + 1) / 9) * 9 + ((ke + 1) % 9)];
    float heF = __half2float(__float2half_rn(we));
    float hoF = __half2float(__float2half_rn(wo));
    size_t base = ((size_t)cc * M + m) * ASTRW + ks * 16 + qq * 4;
    dst[base + kh]     = f16x2pack(wo, we);               // hi pair
    dst[base + 2 + kh] = f16x2pack(wo - hoF, we - heF);   // lo pair
}

// ----------------- bnpack: raw y -> packed BN+LReLU (f16 hi,lo) --------------
__global__ void __launch_bounds__(256) bnpack_kernel(
    const float* __restrict__ raw,
    const float* __restrict__ scale, const float* __restrict__ shift,
    unsigned* __restrict__ dst, int C, long long total4)
{
    long long i4 = (long long)blockIdx.x * blockDim.x + threadIdx.x;
    if (i4 >= total4) return;
    float4 v = ((const float4*)raw)[i4];
    int c = (int)((i4 * 4) >> 16) % C;
    float sc = __ldg(&scale[c]), sh = __ldg(&shift[c]);
    uint4 o;
    {
        float z = v.x * sc + sh; z = z >= 0.f ? z : SLOPE * z;
        float hf = __half2float(__float2half_rn(z));
        o.x = f16x2pack(z, z - hf);
    }
    {
        float z = v.y * sc + sh; z = z >= 0.f ? z : SLOPE * z;
        float hf = __half2float(__float2half_rn(z));
        o.y = f16x2pack(z, z - hf);
    }
    {
        float z = v.z * sc + sh; z = z >= 0.f ? z : SLOPE * z;
        float hf = __half2float(__float2half_rn(z));
        o.z = f16x2pack(z, z - hf);
    }
    {
        float z = v.w * sc + sh; z = z >= 0.f ? z : SLOPE * z;
        float hf = __half2float(__float2half_rn(z));
        o.w = f16x2pack(z, z - hf);
    }
    ((uint4*)dst)[i4] = o;
}

// ---------------- TC conv3x3 (fp16 2-term split, B double-buffered) ----------
// 256 threads = 8 warps = 2 M-warps x 4 N-warps, 2 CTAs/SM.
// Per kstep: build bh (hi halves only), per m-tile load {ah, al}, then
// mma(acc, ah, bh) + mma(acc, al, bh).
template <int CIN, int M, bool STORE>
__global__ void __launch_bounds__(256, 2) conv_tc_kernel(
    const unsigned* __restrict__ in,    // packed (hi,lo) fp16 activations
    const unsigned* __restrict__ wpk,   // packed fp16 weights [chunk][M][ASTRW]
    const float* __restrict__ bias,
    float* __restrict__ out_raw,
    float* __restrict__ psum,
    float* __restrict__ psq)
{
    constexpr int NMT = M / 32;
    constexpr int NCH = CIN / CCH;
    constexpr int ASZ = M * ASTRW;      // words, single A buffer
    constexpr int BSZ = CCH * BCH;      // words per B buffer

    extern __shared__ unsigned char smem_raw[];
    unsigned* Apk = (unsigned*)smem_raw;          // ASZ
    unsigned* Bp  = Apk + ASZ;                    // 2 * BSZ
    int*   koff  = (int*)(Bp + 2 * BSZ);          // KC
    float* red_s = (float*)(koff + KC);           // 4*M
    float* red_q = red_s + 4 * M;

    const int tid = threadIdx.x;
    const int lane = tid & 31, wid = tid >> 5;
    const int mw = wid >> 2, nw = wid & 3;
    const int q = lane & 3, g = lane >> 2;
    const int bx = blockIdx.x, by = blockIdx.y, b = blockIdx.z;
    const int h0 = by * TCH, w0 = bx * TCW;

    auto stageB = [&](int cc) {
        const int c0 = cc * CCH;
        unsigned* Bd = Bp + (cc & 1) * BSZ;
        for (int idx = tid; idx < CCH * HR * 34; idx += 256) {
            int c   = idx / (HR * 34);
            int rem = idx - c * (HR * 34);
            int r   = rem / 34;
            int col = rem - r * 34;
            int gh = h0 + r - 1, gw = w0 + col - 1;
            bool ok = (unsigned)gh < (unsigned)Himg && (unsigned)gw < (unsigned)Wimg;
            const unsigned* src = ok
                ? &in[(((size_t)b * CIN + c0 + c) * Himg + gh) * Wimg + gw] : in;
            cp_async4z(Bd + c * BCH + r * BROW + col, src, ok ? 4 : 0);
        }
        asm volatile("cp.async.commit_group;" ::: "memory");
    };

    // prefetch B(0) before anything else
    stageB(0);

    if (tid < KC) {
        int c = tid / 9, tap = tid - c * 9;
        koff[tid] = c * BCH + (tap / 3) * BROW + (tap % 3);
    }

    float acc[NMT][4][4];
#pragma unroll
    for (int t = 0; t < NMT; ++t)
#pragma unroll
        for (int nt = 0; nt < 4; ++nt)
#pragma unroll
            for (int i = 0; i < 4; ++i) acc[t][nt][i] = 0.f;

    const int poffbase = nw * BROW + g;

#pragma unroll 1
    for (int cc = 0; cc < NCH; ++cc) {
        // A(cc): single-buffer cp.async from L2-hot packed weights
        {
            const unsigned* srcA = wpk + (size_t)cc * ASZ;
            for (int idx = tid; idx < ASZ / 4; idx += 256)
                cp_async16(Apk + idx * 4, srcA + idx * 4);
            asm volatile("cp.async.commit_group;" ::: "memory");
        }
        if (cc + 1 < NCH) {
            stageB(cc + 1);
            // wait for A(cc) and B(cc); leave B(cc+1) in flight
            asm volatile("cp.async.wait_group 1;" ::: "memory");
        } else {
            asm volatile("cp.async.wait_group 0;" ::: "memory");
        }
        __syncthreads();

        const unsigned* Bb = Bp + (cc & 1) * BSZ;

#pragma unroll
        for (int ks = 0; ks < KSTEPS; ++ks) {
            const int kb = ks * 16;
            const int ko0 = koff[kb + 2 * q];
            const int ko1 = koff[kb + 2 * q + 1];
            const int ko2 = koff[kb + 2 * q + 8];
            const int ko3 = koff[kb + 2 * q + 9];
            unsigned bh[4][2];
#pragma unroll
            for (int nt = 0; nt < 4; ++nt) {
                const int p = poffbase + nt * 8;
                unsigned w0r = Bb[ko0 + p], w1r = Bb[ko1 + p];
                unsigned w2r = Bb[ko2 + p], w3r = Bb[ko3 + p];
                bh[nt][0] = prmt(w0r, w1r, 0x7632u);   // hi halves (k, k+1)
                bh[nt][1] = prmt(w2r, w3r, 0x7632u);
            }
#pragma unroll
            for (int t = 0; t < NMT; ++t) {
                const int r0w = (mw * (M / 2) + t * 16 + g) * ASTRW + kb + q * 4;
                const int r1w = r0w + 8 * ASTRW;
                uint2 xh = *(const uint2*)(Apk + r0w);
                uint2 yh = *(const uint2*)(Apk + r1w);
                uint2 xl = *(const uint2*)(Apk + r0w + 2);
                uint2 yl = *(const uint2*)(Apk + r1w + 2);
                unsigned ah[4] = {xh.x, yh.x, xh.y, yh.y};
                unsigned al[4] = {xl.x, yl.x, xl.y, yl.y};
#pragma unroll
                for (int nt = 0; nt < 4; ++nt) {
                    mma_f16(acc[t][nt], ah, bh[nt][0], bh[nt][1]);
                    mma_f16(acc[t][nt], al, bh[nt][0], bh[nt][1]);
                }
            }
        }
        __syncthreads();
    }

    // ---- epilogue: bias, optional store, per-channel stats ----
#pragma unroll
    for (int t = 0; t < NMT; ++t) {
        const int r0 = mw * (M / 2) + t * 16 + g, r1 = r0 + 8;
        const float bv0 = __ldg(&bias[r0]), bv1 = __ldg(&bias[r1]);
        float s0 = 0.f, q0 = 0.f, s1 = 0.f, q1 = 0.f;
#pragma unroll
        for (int nt = 0; nt < 4; ++nt) {
            float v0 = acc[t][nt][0] + bv0, v1 = acc[t][nt][1] + bv0;
            float v2 = acc[t][nt][2] + bv1, v3 = acc[t][nt][3] + bv1;
            if (STORE) {
                int wcol = w0 + nt * 8 + 2 * q;
                int hrow = h0 + nw;
                *(float2*)(out_raw + (((size_t)b * M + r0) * Himg + hrow) * Wimg + wcol) =
                    make_float2(v0, v1);
                *(float2*)(out_raw + (((size_t)b * M + r1) * Himg + hrow) * Wimg + wcol) =
                    make_float2(v2, v3);
            }
            s0 += v0 + v1; q0 += v0 * v0 + v1 * v1;
            s1 += v2 + v3; q1 += v2 * v2 + v3 * v3;
        }
        s0 += __shfl_xor_sync(0xffffffffu, s0, 1);
        s0 += __shfl_xor_sync(0xffffffffu, s0, 2);
        q0 += __shfl_xor_sync(0xffffffffu, q0, 1);
        q0 += __shfl_xor_sync(0xffffffffu, q0, 2);
        s1 += __shfl_xor_sync(0xffffffffu, s1, 1);
        s1 += __shfl_xor_sync(0xffffffffu, s1, 2);
        q1 += __shfl_xor_sync(0xffffffffu, q1, 1);
        q1 += __shfl_xor_sync(0xffffffffu, q1, 2);
        if (q == 0) {
            red_s[nw * M + r0] = s0; red_q[nw * M + r0] = q0;
            red_s[nw * M + r1] = s1; red_q[nw * M + r1] = q1;
        }
    }
    __syncthreads();
    if (tid < M) {
        float s = 0.f, qq = 0.f;
#pragma unroll
        for (int w = 0; w < 4; ++w) { s += red_s[w * M + tid]; qq += red_q[w * M + tid]; }
        int slot = (b * 64 + by) * 8 + bx;
        psum[tid * NSLOT_TC + slot] = s;
        psq [tid * NSLOT_TC + slot] = qq;
    }
}

// -------------------------- conv1 (FFMA, cin=3) ------------------------------
template <int CIN, int CCHUNK>
__global__ void __launch_bounds__(256) conv1_kernel(
    const float* __restrict__ in,
    const float* __restrict__ wgt,
    const float* __restrict__ bias,
    float* __restrict__ out_raw,
    float* __restrict__ psum,
    float* __restrict__ psq,
    int nCoutBlk)
{
    __shared__ float s_in[CCHUNK][TILE + 2][TILE + 2];
    __shared__ float s_w[KOUT * CCHUNK * 9];
    __shared__ float s_rs[KOUT][8];
    __shared__ float s_rq[KOUT][8];

    const int tid = threadIdx.x;
    const int tx = tid & 15, ty = tid >> 4;
    const int bx = blockIdx.x, by = blockIdx.y;
    const int b = blockIdx.z / nCoutBlk;
    const int coutBase = (blockIdx.z % nCoutBlk) * KOUT;
    const int Cout = nCoutBlk * KOUT;
    const int px = tx * 2, py = ty * 2;
    const int h0 = by * TILE, w0 = bx * TILE;

    float acc[KOUT][4];
#pragma unroll
    for (int co = 0; co < KOUT; ++co) {
        acc[co][0] = 0.f; acc[co][1] = 0.f; acc[co][2] = 0.f; acc[co][3] = 0.f;
    }

    for (int idx = tid; idx < CCHUNK * (TILE + 2) * (TILE + 2); idx += 256) {
        int c   = idx / ((TILE + 2) * (TILE + 2));
        int rem = idx - c * (TILE + 2) * (TILE + 2);
        int r   = rem / (TILE + 2);
        int col = rem - r * (TILE + 2);
        int gh = h0 + r - 1, gw = w0 + col - 1;
        float v = 0.f;
        if ((unsigned)gh < (unsigned)Himg && (unsigned)gw < (unsigned)Wimg)
            v = in[(((size_t)b * CIN + c) * Himg + gh) * Wimg + gw];
        (&s_in[0][0][0])[idx] = v;
    }
    for (int idx = tid; idx < KOUT * CCHUNK * 9; idx += 256) {
        int co  = idx / (CCHUNK * 9);
        int rem = idx - co * (CCHUNK * 9);
        s_w[idx] = wgt[((size_t)(coutBase + co) * CIN) * 9 + rem];
    }
    __syncthreads();

#pragma unroll
    for (int c = 0; c < CCHUNK; ++c)
#pragma unroll
        for (int dy = 0; dy < 3; ++dy)
#pragma unroll
            for (int dx = 0; dx < 3; ++dx) {
                float i00 = s_in[c][py + dy][px + dx];
                float i01 = s_in[c][py + dy][px + dx + 1];
                float i10 = s_in[c][py + dy + 1][px + dx];
                float i11 = s_in[c][py + dy + 1][px + dx + 1];
#pragma unroll
                for (int co = 0; co < KOUT; ++co) {
                    float wv = s_w[(co * CCHUNK + c) * 9 + dy * 3 + dx];
                    acc[co][0] = fmaf(i00, wv, acc[co][0]);
                    acc[co][1] = fmaf(i01, wv, acc[co][1]);
                    acc[co][2] = fmaf(i10, wv, acc[co][2]);
                    acc[co][3] = fmaf(i11, wv, acc[co][3]);
                }
            }

    const int lane = tid & 31, wrp = tid >> 5;
#pragma unroll 1
    for (int co = 0; co < KOUT; ++co) {
        float bv = __ldg(&bias[coutBase + co]);
        float v0 = acc[co][0] + bv, v1 = acc[co][1] + bv;
        float v2 = acc[co][2] + bv, v3 = acc[co][3] + bv;
        size_t rowb = ((size_t)b * Cout + coutBase + co) * Himg;
        out_raw[(rowb + h0 + py) * Wimg + w0 + px]         = v0;
        out_raw[(rowb + h0 + py) * Wimg + w0 + px + 1]     = v1;
        out_raw[(rowb + h0 + py + 1) * Wimg + w0 + px]     = v2;
        out_raw[(rowb + h0 + py + 1) * Wimg + w0 + px + 1] = v3;
        float s = v0 + v1 + v2 + v3;
        float qv = v0 * v0 + v1 * v1 + v2 * v2 + v3 * v3;
#pragma unroll
        for (int o = 16; o > 0; o >>= 1) {
            s  += __shfl_down_sync(0xffffffffu, s, o);
            qv += __shfl_down_sync(0xffffffffu, qv, o);
        }
        if (lane == 0) { s_rs[co][wrp] = s; s_rq[co][wrp] = qv; }
    }
    __syncthreads();
    if (tid < KOUT) {
        float s = 0.f, qv = 0.f;
#pragma unroll
        for (int w = 0; w < 8; ++w) { s += s_rs[tid][w]; qv += s_rq[tid][w]; }
        int slot = (by * gridDim.x + bx) * Bsz + b;
        psum[(coutBase + tid) * NSLOT1 + slot] = s;
        psq [(coutBase + tid) * NSLOT1 + slot] = qv;
    }
}

// ------------------------- BN stats finalize ---------------------------------
__global__ void __launch_bounds__(256) bnfin_kernel(
    const float* __restrict__ psum, const float* __restrict__ psq,
    const float* __restrict__ gamma, const float* __restrict__ beta,
    float* __restrict__ scale, float* __restrict__ shift, int nslot)
{
    __shared__ float ss[256], sq[256];
    int c = blockIdx.x;
    float s = 0.f, q = 0.f;
    for (int i = threadIdx.x; i < nslot; i += 256) {
        s += psum[c * nslot + i];
        q += psq [c * nslot + i];
    }
    ss[threadIdx.x] = s; sq[threadIdx.x] = q;
    __syncthreads();
    for (int o = 128; o > 0; o >>= 1) {
        if (threadIdx.x < o) {
            ss[threadIdx.x] += ss[threadIdx.x + o];
            sq[threadIdx.x] += sq[threadIdx.x + o];
        }
        __syncthreads();
    }
    if (threadIdx.x == 0) {
        float mean = ss[0] / NPIX;
        float var  = sq[0] / NPIX - mean * mean;
        float sc   = gamma[c] * rsqrtf(var + EPSV);
        scale[c] = sc;
        shift[c] = beta[c] - mean * sc;
    }
}

// ---------------- final: 32 point z3 vectors + recon + patches ---------------
__global__ void __launch_bounds__(160) points_kernel(
    const float* __restrict__ x,
    const int* __restrict__ anchors,
    const int* __restrict__ positives,
    const float* __restrict__ w3, const float* __restrict__ b3,
    const float* __restrict__ recon_w, const float* __restrict__ recon_b,
    float* __restrict__ out)
{
    __shared__ float s_in[C2 * 9];
    __shared__ float s_z[C3];
    const int kind = blockIdx.x & 1;
    const int b = blockIdx.x >> 1;
    const int* pts = kind ? positives : anchors;
    const int h = pts[b * 8 + 6];
    const int w = pts[b * 8 + 7];
    const int tid = threadIdx.x;

    for (int idx = tid; idx < C2 * 9; idx += 160) {
        int c = idx / 9, tap = idx - c * 9;
        int dy = tap / 3, dx = tap - dy * 3;
        unsigned wv = g_y2pk[(((size_t)b * C2 + c) * Himg + (h + dy - 1)) * Wimg + (w + dx - 1)];
        float hi = __half2float(__ushort_as_half((unsigned short)(wv >> 16)));
        float lo = __half2float(__ushort_as_half((unsigned short)(wv & 0xffffu)));
        s_in[idx] = hi + lo;
    }
    __syncthreads();

    if (tid < C3) {
        float a = b3[tid];
        const float* wr = w3 + (size_t)tid * C2 * 9;
#pragma unroll 4
        for (int i = 0; i < C2 * 9; ++i) a = fmaf(s_in[i], __ldg(&wr[i]), a);
        float z = a * g_scale3[tid] + g_shift3[tid];
        z = z >= 0.f ? z : SLOPE * z;
        s_z[tid] = z;
        out[(kind ? OFF_ZP : OFF_ZA) + b * C3 + tid] = z;
    }
    __syncthreads();

    if (kind == 0) {
        for (int j = tid; j < 147; j += 160) {
            float r = recon_b[j];
            const float* wr = recon_w + (size_t)j * C3;
#pragma unroll 4
            for (int k = 0; k < C3; ++k) r = fmaf(s_z[k], __ldg(&wr[k]), r);
            out[OFF_XR + b * 147 + j] = r;
        }
        for (int idx = tid; idx < 147; idx += 160) {
            int c = idx / 49, rem = idx - c * 49;
            int pyy = rem / 7, pxx = rem - pyy * 7;
            out[OFF_XA + b * 147 + idx] =
                x[(((size_t)b * C0 + c) * Himg + (h - 3 + pyy)) * Wimg + (w - 3 + pxx)];
        }
    }
}

// --------------------------------- launch ------------------------------------
extern "C" void kernel_launch(void* const* d_in, const int* in_sizes, int n_in,
                              void* d_out, int out_size)
{
    const float* x        = (const float*)d_in[0];
    const int*   anchors  = (const int*)  d_in[1];
    const int*   positives= (const int*)  d_in[2];
    const float* c1w = (const float*)d_in[3];
    const float* c1b = (const float*)d_in[4];
    const float* g1  = (const float*)d_in[5];
    const float* be1 = (const float*)d_in[6];
    const float* c2w = (const float*)d_in[7];
    const float* c2b = (const float*)d_in[8];
    const float* g2  = (const float*)d_in[9];
    const float* be2 = (const float*)d_in[10];
    const float* c3w = (const float*)d_in[11];
    const float* c3b = (const float*)d_in[12];
    const float* g3  = (const float*)d_in[13];
    const float* be3 = (const float*)d_in[14];
    const float* rw  = (const float*)d_in[15];
    const float* rb  = (const float*)d_in[16];
    float* out = (float*)d_out;

    float *y1p, *y2p; unsigned *y1pk, *y2pk, *w2pk, *w3pk;
    float *ps1, *pq1, *ps2, *pq2, *ps3, *pq3;
    float *sc1, *sh1, *sc2, *sh2, *sc3, *sh3;
    cudaGetSymbolAddress((void**)&y1p, g_y1);
    cudaGetSymbolAddress((void**)&y2p, g_y2);
    cudaGetSymbolAddress((void**)&y1pk, g_y1pk);
    cudaGetSymbolAddress((void**)&y2pk, g_y2pk);
    cudaGetSymbolAddress((void**)&w2pk, g_w2pk);
    cudaGetSymbolAddress((void**)&w3pk, g_w3pk);
    cudaGetSymbolAddress((void**)&ps1, g_ps1);
    cudaGetSymbolAddress((void**)&pq1, g_pq1);
    cudaGetSymbolAddress((void**)&ps2, g_ps2);
    cudaGetSymbolAddress((void**)&pq2, g_pq2);
    cudaGetSymbolAddress((void**)&ps3, g_ps3);
    cudaGetSymbolAddress((void**)&pq3, g_pq3);
    cudaGetSymbolAddress((void**)&sc1, g_scale1);
    cudaGetSymbolAddress((void**)&sh1, g_shift1);
    cudaGetSymbolAddress((void**)&sc2, g_scale2);
    cudaGetSymbolAddress((void**)&sh2, g_shift2);
    cudaGetSymbolAddress((void**)&sc3, g_scale3);
    cudaGetSymbolAddress((void**)&sh3, g_shift3);

    // dynamic smem: A + 2*B + koff + reductions (words)
    const int smem2 = (C2 * ASTRW + 2 * CCH * BCH + KC + 8 * C2) * 4;
    const int smem3 = (C3 * ASTRW + 2 * CCH * BCH + KC + 8 * C3) * 4;
    cudaFuncSetAttribute(conv_tc_kernel<C1, C2, true>,
                         cudaFuncAttributeMaxDynamicSharedMemorySize, smem2);
    cudaFuncSetAttribute(conv_tc_kernel<C2, C3, false>,
                         cudaFuncAttributeMaxDynamicSharedMemorySize, smem3);

    // weight pre-pack
    {
        int tot2 = (C1 / CCH) * C2 * (KC / 2);
        int tot3 = (C2 / CCH) * C3 * (KC / 2);
        prep_weights<<<(tot2 + 255) / 256, 256>>>(c2w, C1, C2, w2pk);
        prep_weights<<<(tot3 + 255) / 256, 256>>>(c3w, C2, C3, w3pk);
    }

    // conv1 -> raw y1 + stats
    dim3 grid1(8, 8, Bsz * (C1 / KOUT));
    conv1_kernel<C0, 3><<<grid1, 256>>>(x, c1w, c1b, y1p, ps1, pq1, C1 / KOUT);
    bnfin_kernel<<<C1, 256>>>(ps1, pq1, g1, be1, sc1, sh1, NSLOT1);

    // pack bn1(lrelu(y1))
    {
        long long t4 = (long long)Bsz * C1 * Himg * Wimg / 4;
        bnpack_kernel<<<(unsigned)((t4 + 255) / 256), 256>>>(y1p, sc1, sh1, y1pk, C1, t4);
    }

    // conv2 -> raw y2 + stats
    dim3 gridTC(Wimg / TCW, Himg / TCH, Bsz);   // 8 x 64 x 16
    conv_tc_kernel<C1, C2, true><<<gridTC, 256, smem2>>>(
        y1pk, w2pk, c2b, y2p, ps2, pq2);
    bnfin_kernel<<<C2, 256>>>(ps2, pq2, g2, be2, sc2, sh2, NSLOT_TC);

    // pack bn2(lrelu(y2))
    {
        long long t4 = (long long)Bsz * C2 * Himg * Wimg / 4;
        bnpack_kernel<<<(unsigned)((t4 + 255) / 256), 256>>>(y2p, sc2, sh2, y2pk, C2, t4);
    }

    // conv3 -> stats only
    conv_tc_kernel<C2, C3, false><<<gridTC, 256, smem3>>>(
        y2pk, w3pk, c3b, nullptr, ps3, pq3);
    bnfin_kernel<<<C3, 256>>>(ps3, pq3, g3, be3, sc3, sh3, NSLOT_TC);

    // final epilogue
    points_kernel<<<32, 160>>>(x, anchors, positives, c3w, c3b, rw, rb, out);
}

// round 12
// speedup vs baseline: 1.5451x; 1.2899x over previous
#include <cuda_runtime.h>
#include <cuda_fp16.h>
#include <cstddef>

// ---------------------------------------------------------------------------
// CUTSEncoder: conv1 (FFMA) -> conv2/conv3 (fp16 m16n8k16 implicit GEMM,
// 2-term weight split Wh*Xh + Wl*Xh; activations stored as fp16 channel-pair
// words so each mma B operand is one LDS.32; tap-major k ordering; 2 CTAs/SM;
// B halo double-buffered via cp.async) -> BN finalize -> point epilogue.
// ---------------------------------------------------------------------------

namespace {
constexpr int Bsz  = 16;
constexpr int Himg = 256;
constexpr int Wimg = 256;
constexpr int C0 = 3, C1 = 32, C2 = 64, C3 = 128;
constexpr float EPSV  = 1e-5f;
constexpr float SLOPE = 0.01f;
constexpr float NPIX  = 16.0f * 256.0f * 256.0f;

// conv1 (FFMA) tiling
constexpr int TILE  = 32;
constexpr int KOUT  = 16;
constexpr int NSLOT1 = 8 * 8 * Bsz;

// TC conv tiling: 128 pixels (4 rows x 32 cols), K chunk = 16 ch x 9 taps
constexpr int TCH = 4, TCW = 32;
constexpr int HR  = TCH + 2;            // 6 halo rows
constexpr int CCH = 16, KC = 144, KSTEPS = 9;
constexpr int CP  = CCH / 2;            // 8 channel-pair planes per chunk
constexpr int ASTRW = 148;              // A row stride in 32-bit words
constexpr int BROW = 36;
constexpr int BCHp = HR * BROW;         // 216 words per pair-plane
constexpr int NSLOT_TC = 8 * 64 * Bsz;  // 8192 slots

// output layout
constexpr int OFF_XA = 0;
constexpr int OFF_XR = Bsz * 147;
constexpr int OFF_ZA = OFF_XR + Bsz * 147;
constexpr int OFF_ZP = OFF_ZA + Bsz * C3;
}

// ------------------------- scratch (device globals) -------------------------
__device__ float    g_y1[(size_t)Bsz * C1 * Himg * Wimg];
__device__ float    g_y2[(size_t)Bsz * C2 * Himg * Wimg];
// packed fp16 channel-pair activations: [(b*C/2+cp)*HW + pix] = {c+1, c}
__device__ __align__(16) unsigned g_y1pk[(size_t)Bsz * (C1 / 2) * Himg * Wimg];
__device__ __align__(16) unsigned g_y2pk[(size_t)Bsz * (C2 / 2) * Himg * Wimg];

__device__ __align__(16) unsigned g_w2pk[(C1 / CCH) * C2 * ASTRW];
__device__ __align__(16) unsigned g_w3pk[(C2 / CCH) * C3 * ASTRW];

__device__ float g_ps1[C1 * NSLOT1],   g_pq1[C1 * NSLOT1];
__device__ float g_ps2[C2 * NSLOT_TC], g_pq2[C2 * NSLOT_TC];
__device__ float g_ps3[C3 * NSLOT_TC], g_pq3[C3 * NSLOT_TC];

__device__ float g_scale1[C1], g_shift1[C1];
__device__ float g_scale2[C2], g_shift2[C2];
__device__ float g_scale3[C3], g_shift3[C3];

// ------------------------------- helpers ------------------------------------
// pack {[31:16]=f16(a), [15:0]=f16(b)}
__device__ __forceinline__ unsigned f16x2pack(float a, float b) {
    unsigned w;
    asm("cvt.rn.f16x2.f32 %0, %1, %2;" : "=r"(w) : "f"(a), "f"(b));
    return w;
}

__device__ __forceinline__ void mma_f16(float* d, const unsigned* a,
                                        unsigned b0, unsigned b1) {
    asm volatile(
        "mma.sync.aligned.m16n8k16.row.col.f32.f16.f16.f32 "
        "{%0,%1,%2,%3}, {%4,%5,%6,%7}, {%8,%9}, {%0,%1,%2,%3};"
        : "+f"(d[0]), "+f"(d[1]), "+f"(d[2]), "+f"(d[3])
        : "r"(a[0]), "r"(a[1]), "r"(a[2]), "r"(a[3]), "r"(b0), "r"(b1));
}

__device__ __forceinline__ void cp_async16(void* smem, const void* gmem) {
    unsigned saddr = (unsigned)__cvta_generic_to_shared(smem);
    asm volatile("cp.async.cg.shared.global [%0], [%1], 16;"
                 :: "r"(saddr), "l"(gmem));
}

__device__ __forceinline__ void cp_async4z(void* smem, const void* gmem, int sz) {
    unsigned saddr = (unsigned)__cvta_generic_to_shared(smem);
    asm volatile("cp.async.ca.shared.global [%0], [%1], 4, %2;"
                 :: "r"(saddr), "l"(gmem), "r"(sz));
}

// --------------- weight pre-pack (fp16 hi/lo, tap-major k) -------------------
// k = tap*16 + c  (within a 16-channel chunk); pairs are channel pairs.
__global__ void prep_weights(const float* __restrict__ w, int CIN, int M,
                             unsigned* __restrict__ dst)
{
    int idx = blockIdx.x * blockDim.x + threadIdx.x;
    int NCH = CIN / CCH;
    int tot = NCH * M * (KC / 2);
    if (idx >= tot) return;
    int cc  = idx / (M * (KC / 2));
    int rem = idx - cc * M * (KC / 2);
    int m   = rem / (KC / 2);
    int pr  = rem - m * (KC / 2);
    int ks = pr >> 3, j = pr & 7, kh = j >> 2, qq = j & 3;
    int ke = ks * 16 + kh * 8 + 2 * qq;      // even k; tap = ke>>4, c = ke&15
    int tap = ke >> 4;
    int c   = ke & 15;
    int cg  = cc * CCH + c;
    float we = w[((size_t)m * CIN + cg) * 9 + tap];
    float wo = w[((size_t)m * CIN + cg + 1) * 9 + tap];
    float heF = __half2float(__float2half_rn(we));
    float hoF = __half2float(__float2half_rn(wo));
    size_t base = ((size_t)cc * M + m) * ASTRW + ks * 16 + qq * 4;
    dst[base + kh]     = f16x2pack(wo, we);               // hi pair
    dst[base + 2 + kh] = f16x2pack(wo - hoF, we - heF);   // lo pair
}

// ------- bnpack: raw NCHW float -> fp16 channel-pair words (BN+LReLU) --------
__global__ void __launch_bounds__(256) bnpack_pair(
    const float* __restrict__ raw,
    const float* __restrict__ scale, const float* __restrict__ shift,
    unsigned* __restrict__ dst, int C, long long total4)
{
    long long i4 = (long long)blockIdx.x * blockDim.x + threadIdx.x;
    if (i4 >= total4) return;
    int plane = (int)(i4 >> 14);            // HW/4 = 16384 quads per plane
    int pq = (int)(i4 & 16383);
    int half = C >> 1;
    int cp = plane % half, b = plane / half;
    int c0 = cp * 2;
    const float4 v0 = *(const float4*)(raw + (((size_t)b * C + c0) << 16) + pq * 4);
    const float4 v1 = *(const float4*)(raw + (((size_t)b * C + c0 + 1) << 16) + pq * 4);
    float s0 = __ldg(&scale[c0]),     h0 = __ldg(&shift[c0]);
    float s1 = __ldg(&scale[c0 + 1]), h1 = __ldg(&shift[c0 + 1]);
    float a0[4] = {v0.x, v0.y, v0.z, v0.w};
    float a1[4] = {v1.x, v1.y, v1.z, v1.w};
    unsigned o[4];
#pragma unroll
    for (int j = 0; j < 4; ++j) {
        float z0 = a0[j] * s0 + h0; z0 = z0 >= 0.f ? z0 : SLOPE * z0;
        float z1 = a1[j] * s1 + h1; z1 = z1 >= 0.f ? z1 : SLOPE * z1;
        o[j] = f16x2pack(z1, z0);           // low half = even channel
    }
    ((uint4*)dst)[i4] = make_uint4(o[0], o[1], o[2], o[3]);
}

// ---------------- TC conv3x3 (fp16 2-term split, pair-plane B) ---------------
// 256 threads = 8 warps = 2 M-warps x 4 N-warps, 2 CTAs/SM.
template <int CIN, int M, bool STORE>
__global__ void __launch_bounds__(256, 2) conv_tc_kernel(
    const unsigned* __restrict__ in,    // fp16 channel-pair activations
    const unsigned* __restrict__ wpk,   // packed fp16 weights [chunk][M][ASTRW]
    const float* __restrict__ bias,
    float* __restrict__ out_raw,
    float* __restrict__ psum,
    float* __restrict__ psq)
{
    constexpr int NMT = M / 32;
    constexpr int NCH = CIN / CCH;
    constexpr int ASZ = M * ASTRW;      // words, single A buffer
    constexpr int BSZ = CP * BCHp;      // words per B buffer (1728)

    extern __shared__ unsigned char smem_raw[];
    unsigned* Apk = (unsigned*)smem_raw;          // ASZ
    unsigned* Bp  = Apk + ASZ;                    // 2 * BSZ
    float* red_s = (float*)(Bp + 2 * BSZ);        // 4*M
    float* red_q = red_s + 4 * M;

    const int tid = threadIdx.x;
    const int lane = tid & 31, wid = tid >> 5;
    const int mw = wid >> 2, nw = wid & 3;
    const int q = lane & 3, g = lane >> 2;
    const int bx = blockIdx.x, by = blockIdx.y, b = blockIdx.z;
    const int h0 = by * TCH, w0 = bx * TCW;

    auto stageB = [&](int cc) {
        const int cpbase = cc * CP;
        unsigned* Bd = Bp + (cc & 1) * BSZ;
        for (int idx = tid; idx < CP * HR * 34; idx += 256) {
            int p   = idx / (HR * 34);
            int rem = idx - p * (HR * 34);
            int r   = rem / 34;
            int col = rem - r * 34;
            int gh = h0 + r - 1, gw = w0 + col - 1;
            bool ok = (unsigned)gh < (unsigned)Himg && (unsigned)gw < (unsigned)Wimg;
            const unsigned* src = ok
                ? &in[(((size_t)b * (CIN / 2) + cpbase + p) << 16) + gh * 256 + gw] : in;
            cp_async4z(Bd + p * BCHp + r * BROW + col, src, ok ? 4 : 0);
        }
        asm volatile("cp.async.commit_group;" ::: "memory");
    };

    // prefetch B(0) before anything else
    stageB(0);

    float acc[NMT][4][4];
#pragma unroll
    for (int t = 0; t < NMT; ++t)
#pragma unroll
        for (int nt = 0; nt < 4; ++nt)
#pragma unroll
            for (int i = 0; i < 4; ++i) acc[t][nt][i] = 0.f;

    const int poffbase = nw * BROW + g;
    const int qrow0 = q * BCHp;             // b0 plane offset
    const int qrow1 = (q + 4) * BCHp;       // b1 plane offset

#pragma unroll 1
    for (int cc = 0; cc < NCH; ++cc) {
        // A(cc): single-buffer cp.async from L2-hot packed weights
        {
            const unsigned* srcA = wpk + (size_t)cc * ASZ;
            for (int idx = tid; idx < ASZ / 4; idx += 256)
                cp_async16(Apk + idx * 4, srcA + idx * 4);
            asm volatile("cp.async.commit_group;" ::: "memory");
        }
        if (cc + 1 < NCH) {
            stageB(cc + 1);
            asm volatile("cp.async.wait_group 1;" ::: "memory");
        } else {
            asm volatile("cp.async.wait_group 0;" ::: "memory");
        }
        __syncthreads();

        const unsigned* Bb = Bp + (cc & 1) * BSZ;

#pragma unroll
        for (int ks = 0; ks < KSTEPS; ++ks) {
            const int kb = ks * 16;
            const int tapoff = (ks / 3) * BROW + (ks % 3);
            const int pbase = tapoff + poffbase;
            unsigned bh[4][2];
#pragma unroll
            for (int nt = 0; nt < 4; ++nt) {
                bh[nt][0] = Bb[qrow0 + pbase + nt * 8];
                bh[nt][1] = Bb[qrow1 + pbase + nt * 8];
            }
#pragma unroll
            for (int t = 0; t < NMT; ++t) {
                const int r0w = (mw * (M / 2) + t * 16 + g) * ASTRW + kb + q * 4;
                const int r1w = r0w + 8 * ASTRW;
                uint2 xh = *(const uint2*)(Apk + r0w);
                uint2 yh = *(const uint2*)(Apk + r1w);
                uint2 xl = *(const uint2*)(Apk + r0w + 2);
                uint2 yl = *(const uint2*)(Apk + r1w + 2);
                unsigned ah[4] = {xh.x, yh.x, xh.y, yh.y};
                unsigned al[4] = {xl.x, yl.x, xl.y, yl.y};
#pragma unroll
                for (int nt = 0; nt < 4; ++nt) {
                    mma_f16(acc[t][nt], ah, bh[nt][0], bh[nt][1]);
                    mma_f16(acc[t][nt], al, bh[nt][0], bh[nt][1]);
                }
            }
        }
        __syncthreads();
    }

    // ---- epilogue: bias, optional store, per-channel stats ----
#pragma unroll
    for (int t = 0; t < NMT; ++t) {
        const int r0 = mw * (M / 2) + t * 16 + g, r1 = r0 + 8;
        const float bv0 = __ldg(&bias[r0]), bv1 = __ldg(&bias[r1]);
        float s0 = 0.f, q0 = 0.f, s1 = 0.f, q1 = 0.f;
#pragma unroll
        for (int nt = 0; nt < 4; ++nt) {
            float v0 = acc[t][nt][0] + bv0, v1 = acc[t][nt][1] + bv0;
            float v2 = acc[t][nt][2] + bv1, v3 = acc[t][nt][3] + bv1;
            if (STORE) {
                int wcol = w0 + nt * 8 + 2 * q;
                int hrow = h0 + nw;
                *(float2*)(out_raw + (((size_t)b * M + r0) * Himg + hrow) * Wimg + wcol) =
                    make_float2(v0, v1);
                *(float2*)(out_raw + (((size_t)b * M + r1) * Himg + hrow) * Wimg + wcol) =
                    make_float2(v2, v3);
            }
            s0 += v0 + v1; q0 += v0 * v0 + v1 * v1;
            s1 += v2 + v3; q1 += v2 * v2 + v3 * v3;
        }
        s0 += __shfl_xor_sync(0xffffffffu, s0, 1);
        s0 += __shfl_xor_sync(0xffffffffu, s0, 2);
        q0 += __shfl_xor_sync(0xffffffffu, q0, 1);
        q0 += __shfl_xor_sync(0xffffffffu, q0, 2);
        s1 += __shfl_xor_sync(0xffffffffu, s1, 1);
        s1 += __shfl_xor_sync(0xffffffffu, s1, 2);
        q1 += __shfl_xor_sync(0xffffffffu, q1, 1);
        q1 += __shfl_xor_sync(0xffffffffu, q1, 2);
        if (q == 0) {
            red_s[nw * M + r0] = s0; red_q[nw * M + r0] = q0;
            red_s[nw * M + r1] = s1; red_q[nw * M + r1] = q1;
        }
    }
    __syncthreads();
    if (tid < M) {
        float s = 0.f, qq = 0.f;
#pragma unroll
        for (int w = 0; w < 4; ++w) { s += red_s[w * M + tid]; qq += red_q[w * M + tid]; }
        int slot = (b * 64 + by) * 8 + bx;
        psum[tid * NSLOT_TC + slot] = s;
        psq [tid * NSLOT_TC + slot] = qq;
    }
}

// -------------------------- conv1 (FFMA, cin=3) ------------------------------
template <int CIN, int CCHUNK>
__global__ void __launch_bounds__(256) conv1_kernel(
    const float* __restrict__ in,
    const float* __restrict__ wgt,
    const float* __restrict__ bias,
    float* __restrict__ out_raw,
    float* __restrict__ psum,
    float* __restrict__ psq,
    int nCoutBlk)
{
    __shared__ float s_in[CCHUNK][TILE + 2][TILE + 2];
    __shared__ float s_w[KOUT * CCHUNK * 9];
    __shared__ float s_rs[KOUT][8];
    __shared__ float s_rq[KOUT][8];

    const int tid = threadIdx.x;
    const int tx = tid & 15, ty = tid >> 4;
    const int bx = blockIdx.x, by = blockIdx.y;
    const int b = blockIdx.z / nCoutBlk;
    const int coutBase = (blockIdx.z % nCoutBlk) * KOUT;
    const int Cout = nCoutBlk * KOUT;
    const int px = tx * 2, py = ty * 2;
    const int h0 = by * TILE, w0 = bx * TILE;

    float acc[KOUT][4];
#pragma unroll
    for (int co = 0; co < KOUT; ++co) {
        acc[co][0] = 0.f; acc[co][1] = 0.f; acc[co][2] = 0.f; acc[co][3] = 0.f;
    }

    for (int idx = tid; idx < CCHUNK * (TILE + 2) * (TILE + 2); idx += 256) {
        int c   = idx / ((TILE + 2) * (TILE + 2));
        int rem = idx - c * (TILE + 2) * (TILE + 2);
        int r   = rem / (TILE + 2);
        int col = rem - r * (TILE + 2);
        int gh = h0 + r - 1, gw = w0 + col - 1;
        float v = 0.f;
        if ((unsigned)gh < (unsigned)Himg && (unsigned)gw < (unsigned)Wimg)
            v = in[(((size_t)b * CIN + c) * Himg + gh) * Wimg + gw];
        (&s_in[0][0][0])[idx] = v;
    }
    for (int idx = tid; idx < KOUT * CCHUNK * 9; idx += 256) {
        int co  = idx / (CCHUNK * 9);
        int rem = idx - co * (CCHUNK * 9);
        s_w[idx] = wgt[((size_t)(coutBase + co) * CIN) * 9 + rem];
    }
    __syncthreads();

#pragma unroll
    for (int c = 0; c < CCHUNK; ++c)
#pragma unroll
        for (int dy = 0; dy < 3; ++dy)
#pragma unroll
            for (int dx = 0; dx < 3; ++dx) {
                float i00 = s_in[c][py + dy][px + dx];
                float i01 = s_in[c][py + dy][px + dx + 1];
                float i10 = s_in[c][py + dy + 1][px + dx];
                float i11 = s_in[c][py + dy + 1][px + dx + 1];
#pragma unroll
                for (int co = 0; co < KOUT; ++co) {
                    float wv = s_w[(co * CCHUNK + c) * 9 + dy * 3 + dx];
                    acc[co][0] = fmaf(i00, wv, acc[co][0]);
                    acc[co][1] = fmaf(i01, wv, acc[co][1]);
                    acc[co][2] = fmaf(i10, wv, acc[co][2]);
                    acc[co][3] = fmaf(i11, wv, acc[co][3]);
                }
            }

    const int lane = tid & 31, wrp = tid >> 5;
#pragma unroll 1
    for (int co = 0; co < KOUT; ++co) {
        float bv = __ldg(&bias[coutBase + co]);
        float v0 = acc[co][0] + bv, v1 = acc[co][1] + bv;
        float v2 = acc[co][2] + bv, v3 = acc[co][3] + bv;
        size_t rowb = ((size_t)b * Cout + coutBase + co) * Himg;
        out_raw[(rowb + h0 + py) * Wimg + w0 + px]         = v0;
        out_raw[(rowb + h0 + py) * Wimg + w0 + px + 1]     = v1;
        out_raw[(rowb + h0 + py + 1) * Wimg + w0 + px]     = v2;
        out_raw[(rowb + h0 + py + 1) * Wimg + w0 + px + 1] = v3;
        float s = v0 + v1 + v2 + v3;
        float qv = v0 * v0 + v1 * v1 + v2 * v2 + v3 * v3;
#pragma unroll
        for (int o = 16; o > 0; o >>= 1) {
            s  += __shfl_down_sync(0xffffffffu, s, o);
            qv += __shfl_down_sync(0xffffffffu, qv, o);
        }
        if (lane == 0) { s_rs[co][wrp] = s; s_rq[co][wrp] = qv; }
    }
    __syncthreads();
    if (tid < KOUT) {
        float s = 0.f, qv = 0.f;
#pragma unroll
        for (int w = 0; w < 8; ++w) { s += s_rs[tid][w]; qv += s_rq[tid][w]; }
        int slot = (by * gridDim.x + bx) * Bsz + b;
        psum[(coutBase + tid) * NSLOT1 + slot] = s;
        psq [(coutBase + tid) * NSLOT1 + slot] = qv;
    }
}

// ------------------------- BN stats finalize ---------------------------------
__global__ void __launch_bounds__(256) bnfin_kernel(
    const float* __restrict__ psum, const float* __restrict__ psq,
    const float* __restrict__ gamma, const float* __restrict__ beta,
    float* __restrict__ scale, float* __restrict__ shift, int nslot)
{
    __shared__ float ss[256], sq[256];
    int c = blockIdx.x;
    float s = 0.f, q = 0.f;
    for (int i = threadIdx.x; i < nslot; i += 256) {
        s += psum[c * nslot + i];
        q += psq [c * nslot + i];
    }
    ss[threadIdx.x] = s; sq[threadIdx.x] = q;
    __syncthreads();
    for (int o = 128; o > 0; o >>= 1) {
        if (threadIdx.x < o) {
            ss[threadIdx.x] += ss[threadIdx.x + o];
            sq[threadIdx.x] += sq[threadIdx.x + o];
        }
        __syncthreads();
    }
    if (threadIdx.x == 0) {
        float mean = ss[0] / NPIX;
        float var  = sq[0] / NPIX - mean * mean;
        float sc   = gamma[c] * rsqrtf(var + EPSV);
        scale[c] = sc;
        shift[c] = beta[c] - mean * sc;
    }
}

// ---------------- final: 32 point z3 vectors + recon + patches ---------------
__global__ void __launch_bounds__(160) points_kernel(
    const float* __restrict__ x,
    const int* __restrict__ anchors,
    const int* __restrict__ positives,
    const float* __restrict__ w3, const float* __restrict__ b3,
    const float* __restrict__ recon_w, const float* __restrict__ recon_b,
    float* __restrict__ out)
{
    __shared__ float s_in[C2 * 9];
    __shared__ float s_z[C3];
    const int kind = blockIdx.x & 1;
    const int b = blockIdx.x >> 1;
    const int* pts = kind ? positives : anchors;
    const int h = pts[b * 8 + 6];
    const int w = pts[b * 8 + 7];
    const int tid = threadIdx.x;

    // z2 neighborhood from raw y2 float + BN2 (exact)
    for (int idx = tid; idx < C2 * 9; idx += 160) {
        int c = idx / 9, tap = idx - c * 9;
        int dy = tap / 3, dx = tap - dy * 3;
        float v = g_y2[(((size_t)b * C2 + c) * Himg + (h + dy - 1)) * Wimg + (w + dx - 1)];
        float z = v * g_scale2[c] + g_shift2[c];
        s_in[idx] = z >= 0.f ? z : SLOPE * z;
    }
    __syncthreads();

    if (tid < C3) {
        float a = b3[tid];
        const float* wr = w3 + (size_t)tid * C2 * 9;
#pragma unroll 4
        for (int i = 0; i < C2 * 9; ++i) a = fmaf(s_in[i], __ldg(&wr[i]), a);
        float z = a * g_scale3[tid] + g_shift3[tid];
        z = z >= 0.f ? z : SLOPE * z;
        s_z[tid] = z;
        out[(kind ? OFF_ZP : OFF_ZA) + b * C3 + tid] = z;
    }
    __syncthreads();

    if (kind == 0) {
        for (int j = tid; j < 147; j += 160) {
            float r = recon_b[j];
            const float* wr = recon_w + (size_t)j * C3;
#pragma unroll 4
            for (int k = 0; k < C3; ++k) r = fmaf(s_z[k], __ldg(&wr[k]), r);
            out[OFF_XR + b * 147 + j] = r;
        }
        for (int idx = tid; idx < 147; idx += 160) {
            int c = idx / 49, rem = idx - c * 49;
            int pyy = rem / 7, pxx = rem - pyy * 7;
            out[OFF_XA + b * 147 + idx] =
                x[(((size_t)b * C0 + c) * Himg + (h - 3 + pyy)) * Wimg + (w - 3 + pxx)];
        }
    }
}

// --------------------------------- launch ------------------------------------
extern "C" void kernel_launch(void* const* d_in, const int* in_sizes, int n_in,
                              void* d_out, int out_size)
{
    const float* x        = (const float*)d_in[0];
    const int*   anchors  = (const int*)  d_in[1];
    const int*   positives= (const int*)  d_in[2];
    const float* c1w = (const float*)d_in[3];
    const float* c1b = (const float*)d_in[4];
    const float* g1  = (const float*)d_in[5];
    const float* be1 = (const float*)d_in[6];
    const float* c2w = (const float*)d_in[7];
    const float* c2b = (const float*)d_in[8];
    const float* g2  = (const float*)d_in[9];
    const float* be2 = (const float*)d_in[10];
    const float* c3w = (const float*)d_in[11];
    const float* c3b = (const float*)d_in[12];
    const float* g3  = (const float*)d_in[13];
    const float* be3 = (const float*)d_in[14];
    const float* rw  = (const float*)d_in[15];
    const float* rb  = (const float*)d_in[16];
    float* out = (float*)d_out;

    float *y1p, *y2p; unsigned *y1pk, *y2pk, *w2pk, *w3pk;
    float *ps1, *pq1, *ps2, *pq2, *ps3, *pq3;
    float *sc1, *sh1, *sc2, *sh2, *sc3, *sh3;
    cudaGetSymbolAddress((void**)&y1p, g_y1);
    cudaGetSymbolAddress((void**)&y2p, g_y2);
    cudaGetSymbolAddress((void**)&y1pk, g_y1pk);
    cudaGetSymbolAddress((void**)&y2pk, g_y2pk);
    cudaGetSymbolAddress((void**)&w2pk, g_w2pk);
    cudaGetSymbolAddress((void**)&w3pk, g_w3pk);
    cudaGetSymbolAddress((void**)&ps1, g_ps1);
    cudaGetSymbolAddress((void**)&pq1, g_pq1);
    cudaGetSymbolAddress((void**)&ps2, g_ps2);
    cudaGetSymbolAddress((void**)&pq2, g_pq2);
    cudaGetSymbolAddress((void**)&ps3, g_ps3);
    cudaGetSymbolAddress((void**)&pq3, g_pq3);
    cudaGetSymbolAddress((void**)&sc1, g_scale1);
    cudaGetSymbolAddress((void**)&sh1, g_shift1);
    cudaGetSymbolAddress((void**)&sc2, g_scale2);
    cudaGetSymbolAddress((void**)&sh2, g_shift2);
    cudaGetSymbolAddress((void**)&sc3, g_scale3);
    cudaGetSymbolAddress((void**)&sh3, g_shift3);

    // dynamic smem: A + 2*B + reductions (words)
    const int smem2 = (C2 * ASTRW + 2 * CP * BCHp + 8 * C2) * 4;
    const int smem3 = (C3 * ASTRW + 2 * CP * BCHp + 8 * C3) * 4;
    cudaFuncSetAttribute(conv_tc_kernel<C1, C2, true>,
                         cudaFuncAttributeMaxDynamicSharedMemorySize, smem2);
    cudaFuncSetAttribute(conv_tc_kernel<C2, C3, false>,
                         cudaFuncAttributeMaxDynamicSharedMemorySize, smem3);

    // weight pre-pack (tap-major k)
    {
        int tot2 = (C1 / CCH) * C2 * (KC / 2);
        int tot3 = (C2 / CCH) * C3 * (KC / 2);
        prep_weights<<<(tot2 + 255) / 256, 256>>>(c2w, C1, C2, w2pk);
        prep_weights<<<(tot3 + 255) / 256, 256>>>(c3w, C2, C3, w3pk);
    }

    // conv1 -> raw y1 + stats
    dim3 grid1(8, 8, Bsz * (C1 / KOUT));
    conv1_kernel<C0, 3><<<grid1, 256>>>(x, c1w, c1b, y1p, ps1, pq1, C1 / KOUT);
    bnfin_kernel<<<C1, 256>>>(ps1, pq1, g1, be1, sc1, sh1, NSLOT1);

    // pack bn1(lrelu(y1)) -> fp16 channel pairs
    {
        long long t4 = (long long)Bsz * (C1 / 2) * Himg * Wimg / 4;
        bnpack_pair<<<(unsigned)((t4 + 255) / 256), 256>>>(y1p, sc1, sh1, y1pk, C1, t4);
    }

    // conv2 -> raw y2 + stats
    dim3 gridTC(Wimg / TCW, Himg / TCH, Bsz);   // 8 x 64 x 16
    conv_tc_kernel<C1, C2, true><<<gridTC, 256, smem2>>>(
        y1pk, w2pk, c2b, y2p, ps2, pq2);
    bnfin_kernel<<<C2, 256>>>(ps2, pq2, g2, be2, sc2, sh2, NSLOT_TC);

    // pack bn2(lrelu(y2))
    {
        long long t4 = (long long)Bsz * (C2 / 2) * Himg * Wimg / 4;
        bnpack_pair<<<(unsigned)((t4 + 255) / 256), 256>>>(y2p, sc2, sh2, y2pk, C2, t4);
    }

    // conv3 -> stats only
    conv_tc_kernel<C2, C3, false><<<gridTC, 256, smem3>>>(
        y2pk, w3pk, c3b, nullptr, ps3, pq3);
    bnfin_kernel<<<C3, 256>>>(ps3, pq3, g3, be3, sc3, sh3, NSLOT_TC);

    // final epilogue
    points_kernel<<<32, 160>>>(x, anchors, positives, c3w, c3b, rw, rb, out);
}

// round 13
// speedup vs baseline: 1.9815x; 1.2824x over previous
#include <cuda_runtime.h>
#include <cuda_fp16.h>
#include <cstddef>

// ---------------------------------------------------------------------------
// CUTSEncoder: conv1 (FFMA) -> conv2 (fp16 2-term: Wh*Xh + Wl*Xh) ->
// conv3 (fp16 SINGLE-term Wh*Xh: its output feeds ONLY BN3 statistics; the 32
// needed z3 vectors are recomputed exactly in fp32 by points_kernel) ->
// BN finalize -> point epilogue.
// Activations stored as fp16 channel-pair words (one LDS.32 per mma B operand,
// tap-major k); 2 CTAs/SM; B halo double-buffered via cp.async.
// ---------------------------------------------------------------------------

namespace {
constexpr int Bsz  = 16;
constexpr int Himg = 256;
constexpr int Wimg = 256;
constexpr int C0 = 3, C1 = 32, C2 = 64, C3 = 128;
constexpr float EPSV  = 1e-5f;
constexpr float SLOPE = 0.01f;
constexpr float NPIX  = 16.0f * 256.0f * 256.0f;

// conv1 (FFMA) tiling
constexpr int TILE  = 32;
constexpr int KOUT  = 16;
constexpr int NSLOT1 = 8 * 8 * Bsz;

// TC conv tiling: 128 pixels (4 rows x 32 cols), K chunk = 16 ch x 9 taps
constexpr int TCH = 4, TCW = 32;
constexpr int HR  = TCH + 2;            // 6 halo rows
constexpr int CCH = 16, KC = 144, KSTEPS = 9;
constexpr int CP  = CCH / 2;            // 8 channel-pair planes per chunk
constexpr int ASTR2 = 148;              // A row stride (words), 2-term hi/lo
constexpr int ASTR1 = 76;               // A row stride (words), hi-only
constexpr int BROW = 36;
constexpr int BCHp = HR * BROW;         // 216 words per pair-plane
constexpr int NSLOT_TC = 8 * 64 * Bsz;  // 8192 slots

// output layout
constexpr int OFF_XA = 0;
constexpr int OFF_XR = Bsz * 147;
constexpr int OFF_ZA = OFF_XR + Bsz * 147;
constexpr int OFF_ZP = OFF_ZA + Bsz * C3;
}

// ------------------------- scratch (device globals) -------------------------
__device__ float    g_y1[(size_t)Bsz * C1 * Himg * Wimg];
__device__ float    g_y2[(size_t)Bsz * C2 * Himg * Wimg];
// packed fp16 channel-pair activations: [(b*C/2+cp)*HW + pix] = {c+1, c}
__device__ __align__(16) unsigned g_y1pk[(size_t)Bsz * (C1 / 2) * Himg * Wimg];
__device__ __align__(16) unsigned g_y2pk[(size_t)Bsz * (C2 / 2) * Himg * Wimg];

__device__ __align__(16) unsigned g_w2pk[(C1 / CCH) * C2 * ASTR2];
__device__ __align__(16) unsigned g_w3pk[(C2 / CCH) * C3 * ASTR1];

__device__ float g_ps1[C1 * NSLOT1],   g_pq1[C1 * NSLOT1];
__device__ float g_ps2[C2 * NSLOT_TC], g_pq2[C2 * NSLOT_TC];
__device__ float g_ps3[C3 * NSLOT_TC], g_pq3[C3 * NSLOT_TC];

__device__ float g_scale1[C1], g_shift1[C1];
__device__ float g_scale2[C2], g_shift2[C2];
__device__ float g_scale3[C3], g_shift3[C3];

// ------------------------------- helpers ------------------------------------
__device__ __forceinline__ unsigned f16x2pack(float a, float b) {
    unsigned w;
    asm("cvt.rn.f16x2.f32 %0, %1, %2;" : "=r"(w) : "f"(a), "f"(b));
    return w;  // [31:16]=f16(a), [15:0]=f16(b)
}

__device__ __forceinline__ void mma_f16(float* d, const unsigned* a,
                                        unsigned b0, unsigned b1) {
    asm volatile(
        "mma.sync.aligned.m16n8k16.row.col.f32.f16.f16.f32 "
        "{%0,%1,%2,%3}, {%4,%5,%6,%7}, {%8,%9}, {%0,%1,%2,%3};"
        : "+f"(d[0]), "+f"(d[1]), "+f"(d[2]), "+f"(d[3])
        : "r"(a[0]), "r"(a[1]), "r"(a[2]), "r"(a[3]), "r"(b0), "r"(b1));
}

__device__ __forceinline__ void cp_async16(void* smem, const void* gmem) {
    unsigned saddr = (unsigned)__cvta_generic_to_shared(smem);
    asm volatile("cp.async.cg.shared.global [%0], [%1], 16;"
                 :: "r"(saddr), "l"(gmem));
}

__device__ __forceinline__ void cp_async4z(void* smem, const void* gmem, int sz) {
    unsigned saddr = (unsigned)__cvta_generic_to_shared(smem);
    asm volatile("cp.async.ca.shared.global [%0], [%1], 4, %2;"
                 :: "r"(saddr), "l"(gmem), "r"(sz));
}

// --------------- weight pre-pack (fp16, tap-major k) -------------------------
// TERMS=2: per kstep 16 words [q*4 + kh]=hi, [q*4+2+kh]=lo.
// TERMS=1: per kstep  8 words [q*2 + kh]=hi only.
template <int TERMS, int ASTR>
__global__ void prep_weights(const float* __restrict__ w, int CIN, int M,
                             unsigned* __restrict__ dst)
{
    int idx = blockIdx.x * blockDim.x + threadIdx.x;
    int NCH = CIN / CCH;
    int tot = NCH * M * (KC / 2);
    if (idx >= tot) return;
    int cc  = idx / (M * (KC / 2));
    int rem = idx - cc * M * (KC / 2);
    int m   = rem / (KC / 2);
    int pr  = rem - m * (KC / 2);
    int ks = pr >> 3, j = pr & 7, kh = j >> 2, qq = j & 3;
    int ke = ks * 16 + kh * 8 + 2 * qq;      // even k; tap = ke>>4, c = ke&15
    int tap = ke >> 4;
    int c   = ke & 15;
    int cg  = cc * CCH + c;
    float we = w[((size_t)m * CIN + cg) * 9 + tap];
    float wo = w[((size_t)m * CIN + cg + 1) * 9 + tap];
    if (TERMS == 2) {
        float heF = __half2float(__float2half_rn(we));
        float hoF = __half2float(__float2half_rn(wo));
        size_t base = ((size_t)cc * M + m) * ASTR + ks * 16 + qq * 4;
        dst[base + kh]     = f16x2pack(wo, we);
        dst[base + 2 + kh] = f16x2pack(wo - hoF, we - heF);
    } else {
        size_t base = ((size_t)cc * M + m) * ASTR + ks * 8 + qq * 2;
        dst[base + kh] = f16x2pack(wo, we);
    }
}

// ------- bnpack: raw NCHW float -> fp16 channel-pair words (BN+LReLU) --------
__global__ void __launch_bounds__(256) bnpack_pair(
    const float* __restrict__ raw,
    const float* __restrict__ scale, const float* __restrict__ shift,
    unsigned* __restrict__ dst, int C, long long total4)
{
    long long i4 = (long long)blockIdx.x * blockDim.x + threadIdx.x;
    if (i4 >= total4) return;
    int plane = (int)(i4 >> 14);            // HW/4 = 16384 quads per plane
    int pq = (int)(i4 & 16383);
    int half = C >> 1;
    int cp = plane % half, b = plane / half;
    int c0 = cp * 2;
    const float4 v0 = *(const float4*)(raw + (((size_t)b * C + c0) << 16) + pq * 4);
    const float4 v1 = *(const float4*)(raw + (((size_t)b * C + c0 + 1) << 16) + pq * 4);
    float s0 = __ldg(&scale[c0]),     h0 = __ldg(&shift[c0]);
    float s1 = __ldg(&scale[c0 + 1]), h1 = __ldg(&shift[c0 + 1]);
    float a0[4] = {v0.x, v0.y, v0.z, v0.w};
    float a1[4] = {v1.x, v1.y, v1.z, v1.w};
    unsigned o[4];
#pragma unroll
    for (int j = 0; j < 4; ++j) {
        float z0 = a0[j] * s0 + h0; z0 = z0 >= 0.f ? z0 : SLOPE * z0;
        float z1 = a1[j] * s1 + h1; z1 = z1 >= 0.f ? z1 : SLOPE * z1;
        o[j] = f16x2pack(z1, z0);           // low half = even channel
    }
    ((uint4*)dst)[i4] = make_uint4(o[0], o[1], o[2], o[3]);
}

// ---------------- TC conv3x3 (fp16, TERMS-term split, pair-plane B) ----------
// 256 threads = 8 warps = 2 M-warps x 4 N-warps, 2 CTAs/SM.
template <int CIN, int M, bool STORE, int TERMS, int ASTR>
__global__ void __launch_bounds__(256, 2) conv_tc_kernel(
    const unsigned* __restrict__ in,    // fp16 channel-pair activations
    const unsigned* __restrict__ wpk,   // packed fp16 weights [chunk][M][ASTR]
    const float* __restrict__ bias,
    float* __restrict__ out_raw,
    float* __restrict__ psum,
    float* __restrict__ psq)
{
    constexpr int NMT = M / 32;
    constexpr int NCH = CIN / CCH;
    constexpr int ASZ = M * ASTR;       // words, single A buffer
    constexpr int BSZ = CP * BCHp;      // words per B buffer (1728)

    extern __shared__ unsigned char smem_raw[];
    unsigned* Apk = (unsigned*)smem_raw;          // ASZ
    unsigned* Bp  = Apk + ASZ;                    // 2 * BSZ
    float* red_s = (float*)(Bp + 2 * BSZ);        // 4*M
    float* red_q = red_s + 4 * M;

    const int tid = threadIdx.x;
    const int lane = tid & 31, wid = tid >> 5;
    const int mw = wid >> 2, nw = wid & 3;
    const int q = lane & 3, g = lane >> 2;
    const int bx = blockIdx.x, by = blockIdx.y, b = blockIdx.z;
    const int h0 = by * TCH, w0 = bx * TCW;

    auto stageB = [&](int cc) {
        const int cpbase = cc * CP;
        unsigned* Bd = Bp + (cc & 1) * BSZ;
        for (int idx = tid; idx < CP * HR * 34; idx += 256) {
            int p   = idx / (HR * 34);
            int rem = idx - p * (HR * 34);
            int r   = rem / 34;
            int col = rem - r * 34;
            int gh = h0 + r - 1, gw = w0 + col - 1;
            bool ok = (unsigned)gh < (unsigned)Himg && (unsigned)gw < (unsigned)Wimg;
            const unsigned* src = ok
                ? &in[(((size_t)b * (CIN / 2) + cpbase + p) << 16) + gh * 256 + gw] : in;
            cp_async4z(Bd + p * BCHp + r * BROW + col, src, ok ? 4 : 0);
        }
        asm volatile("cp.async.commit_group;" ::: "memory");
    };

    // prefetch B(0) before anything else
    stageB(0);

    float acc[NMT][4][4];
#pragma unroll
    for (int t = 0; t < NMT; ++t)
#pragma unroll
        for (int nt = 0; nt < 4; ++nt)
#pragma unroll
            for (int i = 0; i < 4; ++i) acc[t][nt][i] = 0.f;

    const int poffbase = nw * BROW + g;
    const int qrow0 = q * BCHp;             // b0 plane offset
    const int qrow1 = (q + 4) * BCHp;       // b1 plane offset

#pragma unroll 1
    for (int cc = 0; cc < NCH; ++cc) {
        // A(cc): single-buffer cp.async from L2-hot packed weights
        {
            const unsigned* srcA = wpk + (size_t)cc * ASZ;
            for (int idx = tid; idx < ASZ / 4; idx += 256)
                cp_async16(Apk + idx * 4, srcA + idx * 4);
            asm volatile("cp.async.commit_group;" ::: "memory");
        }
        if (cc + 1 < NCH) {
            stageB(cc + 1);
            asm volatile("cp.async.wait_group 1;" ::: "memory");
        } else {
            asm volatile("cp.async.wait_group 0;" ::: "memory");
        }
        __syncthreads();

        const unsigned* Bb = Bp + (cc & 1) * BSZ;

#pragma unroll
        for (int ks = 0; ks < KSTEPS; ++ks) {
            const int tapoff = (ks / 3) * BROW + (ks % 3);
            const int pbase = tapoff + poffbase;
            const int abase = (TERMS == 2) ? (ks * 16 + q * 4) : (ks * 8 + q * 2);
            unsigned bh[4][2];
#pragma unroll
            for (int nt = 0; nt < 4; ++nt) {
                bh[nt][0] = Bb[qrow0 + pbase + nt * 8];
                bh[nt][1] = Bb[qrow1 + pbase + nt * 8];
            }
#pragma unroll
            for (int t = 0; t < NMT; ++t) {
                const int r0w = (mw * (M / 2) + t * 16 + g) * ASTR + abase;
                const int r1w = r0w + 8 * ASTR;
                uint2 xh = *(const uint2*)(Apk + r0w);
                uint2 yh = *(const uint2*)(Apk + r1w);
                unsigned ah[4] = {xh.x, yh.x, xh.y, yh.y};
                if (TERMS == 2) {
                    uint2 xl = *(const uint2*)(Apk + r0w + 2);
                    uint2 yl = *(const uint2*)(Apk + r1w + 2);
                    unsigned al[4] = {xl.x, yl.x, xl.y, yl.y};
#pragma unroll
                    for (int nt = 0; nt < 4; ++nt) {
                        mma_f16(acc[t][nt], ah, bh[nt][0], bh[nt][1]);
                        mma_f16(acc[t][nt], al, bh[nt][0], bh[nt][1]);
                    }
                } else {
#pragma unroll
                    for (int nt = 0; nt < 4; ++nt)
                        mma_f16(acc[t][nt], ah, bh[nt][0], bh[nt][1]);
                }
            }
        }
        __syncthreads();
    }

    // ---- epilogue: bias, optional store, per-channel stats ----
#pragma unroll
    for (int t = 0; t < NMT; ++t) {
        const int r0 = mw * (M / 2) + t * 16 + g, r1 = r0 + 8;
        const float bv0 = __ldg(&bias[r0]), bv1 = __ldg(&bias[r1]);
        float s0 = 0.f, q0 = 0.f, s1 = 0.f, q1 = 0.f;
#pragma unroll
        for (int nt = 0; nt < 4; ++nt) {
            float v0 = acc[t][nt][0] + bv0, v1 = acc[t][nt][1] + bv0;
            float v2 = acc[t][nt][2] + bv1, v3 = acc[t][nt][3] + bv1;
            if (STORE) {
                int wcol = w0 + nt * 8 + 2 * q;
                int hrow = h0 + nw;
                *(float2*)(out_raw + (((size_t)b * M + r0) * Himg + hrow) * Wimg + wcol) =
                    make_float2(v0, v1);
                *(float2*)(out_raw + (((size_t)b * M + r1) * Himg + hrow) * Wimg + wcol) =
                    make_float2(v2, v3);
            }
            s0 += v0 + v1; q0 += v0 * v0 + v1 * v1;
            s1 += v2 + v3; q1 += v2 * v2 + v3 * v3;
        }
        s0 += __shfl_xor_sync(0xffffffffu, s0, 1);
        s0 += __shfl_xor_sync(0xffffffffu, s0, 2);
        q0 += __shfl_xor_sync(0xffffffffu, q0, 1);
        q0 += __shfl_xor_sync(0xffffffffu, q0, 2);
        s1 += __shfl_xor_sync(0xffffffffu, s1, 1);
        s1 += __shfl_xor_sync(0xffffffffu, s1, 2);
        q1 += __shfl_xor_sync(0xffffffffu, q1, 1);
        q1 += __shfl_xor_sync(0xffffffffu, q1, 2);
        if (q == 0) {
            red_s[nw * M + r0] = s0; red_q[nw * M + r0] = q0;
            red_s[nw * M + r1] = s1; red_q[nw * M + r1] = q1;
        }
    }
    __syncthreads();
    if (tid < M) {
        float s = 0.f, qq = 0.f;
#pragma unroll
        for (int w = 0; w < 4; ++w) { s += red_s[w * M + tid]; qq += red_q[w * M + tid]; }
        int slot = (b * 64 + by) * 8 + bx;
        psum[tid * NSLOT_TC + slot] = s;
        psq [tid * NSLOT_TC + slot] = qq;
    }
}

// -------------------------- conv1 (FFMA, cin=3) ------------------------------
template <int CIN, int CCHUNK>
__global__ void __launch_bounds__(256) conv1_kernel(
    const float* __restrict__ in,
    const float* __restrict__ wgt,
    const float* __restrict__ bias,
    float* __restrict__ out_raw,
    float* __restrict__ psum,
    float* __restrict__ psq,
    int nCoutBlk)
{
    __shared__ float s_in[CCHUNK][TILE + 2][TILE + 2];
    __shared__ float s_w[KOUT * CCHUNK * 9];
    __shared__ float s_rs[KOUT][8];
    __shared__ float s_rq[KOUT][8];

    const int tid = threadIdx.x;
    const int tx = tid & 15, ty = tid >> 4;
    const int bx = blockIdx.x, by = blockIdx.y;
    const int b = blockIdx.z / nCoutBlk;
    const int coutBase = (blockIdx.z % nCoutBlk) * KOUT;
    const int Cout = nCoutBlk * KOUT;
    const int px = tx * 2, py = ty * 2;
    const int h0 = by * TILE, w0 = bx * TILE;

    float acc[KOUT][4];
#pragma unroll
    for (int co = 0; co < KOUT; ++co) {
        acc[co][0] = 0.f; acc[co][1] = 0.f; acc[co][2] = 0.f; acc[co][3] = 0.f;
    }

    for (int idx = tid; idx < CCHUNK * (TILE + 2) * (TILE + 2); idx += 256) {
        int c   = idx / ((TILE + 2) * (TILE + 2));
        int rem = idx - c * (TILE + 2) * (TILE + 2);
        int r   = rem / (TILE + 2);
        int col = rem - r * (TILE + 2);
        int gh = h0 + r - 1, gw = w0 + col - 1;
        float v = 0.f;
        if ((unsigned)gh < (unsigned)Himg && (unsigned)gw < (unsigned)Wimg)
            v = in[(((size_t)b * CIN + c) * Himg + gh) * Wimg + gw];
        (&s_in[0][0][0])[idx] = v;
    }
    for (int idx = tid; idx < KOUT * CCHUNK * 9; idx += 256) {
        int co  = idx / (CCHUNK * 9);
        int rem = idx - co * (CCHUNK * 9);
        s_w[idx] = wgt[((size_t)(coutBase + co) * CIN) * 9 + rem];
    }
    __syncthreads();

#pragma unroll
    for (int c = 0; c < CCHUNK; ++c)
#pragma unroll
        for (int dy = 0; dy < 3; ++dy)
#pragma unroll
            for (int dx = 0; dx < 3; ++dx) {
                float i00 = s_in[c][py + dy][px + dx];
                float i01 = s_in[c][py + dy][px + dx + 1];
                float i10 = s_in[c][py + dy + 1][px + dx];
                float i11 = s_in[c][py + dy + 1][px + dx + 1];
#pragma unroll
                for (int co = 0; co < KOUT; ++co) {
                    float wv = s_w[(co * CCHUNK + c) * 9 + dy * 3 + dx];
                    acc[co][0] = fmaf(i00, wv, acc[co][0]);
                    acc[co][1] = fmaf(i01, wv, acc[co][1]);
                    acc[co][2] = fmaf(i10, wv, acc[co][2]);
                    acc[co][3] = fmaf(i11, wv, acc[co][3]);
                }
            }

    const int lane = tid & 31, wrp = tid >> 5;
#pragma unroll 1
    for (int co = 0; co < KOUT; ++co) {
        float bv = __ldg(&bias[coutBase + co]);
        float v0 = acc[co][0] + bv, v1 = acc[co][1] + bv;
        float v2 = acc[co][2] + bv, v3 = acc[co][3] + bv;
        size_t rowb = ((size_t)b * Cout + coutBase + co) * Himg;
        out_raw[(rowb + h0 + py) * Wimg + w0 + px]         = v0;
        out_raw[(rowb + h0 + py) * Wimg + w0 + px + 1]     = v1;
        out_raw[(rowb + h0 + py + 1) * Wimg + w0 + px]     = v2;
        out_raw[(rowb + h0 + py + 1) * Wimg + w0 + px + 1] = v3;
        float s = v0 + v1 + v2 + v3;
        float qv = v0 * v0 + v1 * v1 + v2 * v2 + v3 * v3;
#pragma unroll
        for (int o = 16; o > 0; o >>= 1) {
            s  += __shfl_down_sync(0xffffffffu, s, o);
            qv += __shfl_down_sync(0xffffffffu, qv, o);
        }
        if (lane == 0) { s_rs[co][wrp] = s; s_rq[co][wrp] = qv; }
    }
    __syncthreads();
    if (tid < KOUT) {
        float s = 0.f, qv = 0.f;
#pragma unroll
        for (int w = 0; w < 8; ++w) { s += s_rs[tid][w]; qv += s_rq[tid][w]; }
        int slot = (by * gridDim.x + bx) * Bsz + b;
        psum[(coutBase + tid) * NSLOT1 + slot] = s;
        psq [(coutBase + tid) * NSLOT1 + slot] = qv;
    }
}

// ------------------------- BN stats finalize ---------------------------------
__global__ void __launch_bounds__(256) bnfin_kernel(
    const float* __restrict__ psum, const float* __restrict__ psq,
    const float* __restrict__ gamma, const float* __restrict__ beta,
    float* __restrict__ scale, float* __restrict__ shift, int nslot)
{
    __shared__ float ss[256], sq[256];
    int c = blockIdx.x;
    float s = 0.f, q = 0.f;
    for (int i = threadIdx.x; i < nslot; i += 256) {
        s += psum[c * nslot + i];
        q += psq [c * nslot + i];
    }
    ss[threadIdx.x] = s; sq[threadIdx.x] = q;
    __syncthreads();
    for (int o = 128; o > 0; o >>= 1) {
        if (threadIdx.x < o) {
            ss[threadIdx.x] += ss[threadIdx.x + o];
            sq[threadIdx.x] += sq[threadIdx.x + o];
        }
        __syncthreads();
    }
    if (threadIdx.x == 0) {
        float mean = ss[0] / NPIX;
        float var  = sq[0] / NPIX - mean * mean;
        float sc   = gamma[c] * rsqrtf(var + EPSV);
        scale[c] = sc;
        shift[c] = beta[c] - mean * sc;
    }
}

// ---------------- final: 32 point z3 vectors + recon + patches ---------------
__global__ void __launch_bounds__(160) points_kernel(
    const float* __restrict__ x,
    const int* __restrict__ anchors,
    const int* __restrict__ positives,
    const float* __restrict__ w3, const float* __restrict__ b3,
    const float* __restrict__ recon_w, const float* __restrict__ recon_b,
    float* __restrict__ out)
{
    __shared__ float s_in[C2 * 9];
    __shared__ float s_z[C3];
    const int kind = blockIdx.x & 1;
    const int b = blockIdx.x >> 1;
    const int* pts = kind ? positives : anchors;
    const int h = pts[b * 8 + 6];
    const int w = pts[b * 8 + 7];
    const int tid = threadIdx.x;

    // z2 neighborhood from raw y2 float + BN2 (exact)
    for (int idx = tid; idx < C2 * 9; idx += 160) {
        int c = idx / 9, tap = idx - c * 9;
        int dy = tap / 3, dx = tap - dy * 3;
        float v = g_y2[(((size_t)b * C2 + c) * Himg + (h + dy - 1)) * Wimg + (w + dx - 1)];
        float z = v * g_scale2[c] + g_shift2[c];
        s_in[idx] = z >= 0.f ? z : SLOPE * z;
    }
    __syncthreads();

    if (tid < C3) {
        float a = b3[tid];
        const float* wr = w3 + (size_t)tid * C2 * 9;
#pragma unroll 4
        for (int i = 0; i < C2 * 9; ++i) a = fmaf(s_in[i], __ldg(&wr[i]), a);
        float z = a * g_scale3[tid] + g_shift3[tid];
        z = z >= 0.f ? z : SLOPE * z;
        s_z[tid] = z;
        out[(kind ? OFF_ZP : OFF_ZA) + b * C3 + tid] = z;
    }
    __syncthreads();

    if (kind == 0) {
        for (int j = tid; j < 147; j += 160) {
            float r = recon_b[j];
            const float* wr = recon_w + (size_t)j * C3;
#pragma unroll 4
            for (int k = 0; k < C3; ++k) r = fmaf(s_z[k], __ldg(&wr[k]), r);
            out[OFF_XR + b * 147 + j] = r;
        }
        for (int idx = tid; idx < 147; idx += 160) {
            int c = idx / 49, rem = idx - c * 49;
            int pyy = rem / 7, pxx = rem - pyy * 7;
            out[OFF_XA + b * 147 + idx] =
                x[(((size_t)b * C0 + c) * Himg + (h - 3 + pyy)) * Wimg + (w - 3 + pxx)];
        }
    }
}

// --------------------------------- launch ------------------------------------
extern "C" void kernel_launch(void* const* d_in, const int* in_sizes, int n_in,
                              void* d_out, int out_size)
{
    const float* x        = (const float*)d_in[0];
    const int*   anchors  = (const int*)  d_in[1];
    const int*   positives= (const int*)  d_in[2];
    const float* c1w = (const float*)d_in[3];
    const float* c1b = (const float*)d_in[4];
    const float* g1  = (const float*)d_in[5];
    const float* be1 = (const float*)d_in[6];
    const float* c2w = (const float*)d_in[7];
    const float* c2b = (const float*)d_in[8];
    const float* g2  = (const float*)d_in[9];
    const float* be2 = (const float*)d_in[10];
    const float* c3w = (const float*)d_in[11];
    const float* c3b = (const float*)d_in[12];
    const float* g3  = (const float*)d_in[13];
    const float* be3 = (const float*)d_in[14];
    const float* rw  = (const float*)d_in[15];
    const float* rb  = (const float*)d_in[16];
    float* out = (float*)d_out;

    float *y1p, *y2p; unsigned *y1pk, *y2pk, *w2pk, *w3pk;
    float *ps1, *pq1, *ps2, *pq2, *ps3, *pq3;
    float *sc1, *sh1, *sc2, *sh2, *sc3, *sh3;
    cudaGetSymbolAddress((void**)&y1p, g_y1);
    cudaGetSymbolAddress((void**)&y2p, g_y2);
    cudaGetSymbolAddress((void**)&y1pk, g_y1pk);
    cudaGetSymbolAddress((void**)&y2pk, g_y2pk);
    cudaGetSymbolAddress((void**)&w2pk, g_w2pk);
    cudaGetSymbolAddress((void**)&w3pk, g_w3pk);
    cudaGetSymbolAddress((void**)&ps1, g_ps1);
    cudaGetSymbolAddress((void**)&pq1, g_pq1);
    cudaGetSymbolAddress((void**)&ps2, g_ps2);
    cudaGetSymbolAddress((void**)&pq2, g_pq2);
    cudaGetSymbolAddress((void**)&ps3, g_ps3);
    cudaGetSymbolAddress((void**)&pq3, g_pq3);
    cudaGetSymbolAddress((void**)&sc1, g_scale1);
    cudaGetSymbolAddress((void**)&sh1, g_shift1);
    cudaGetSymbolAddress((void**)&sc2, g_scale2);
    cudaGetSymbolAddress((void**)&sh2, g_shift2);
    cudaGetSymbolAddress((void**)&sc3, g_scale3);
    cudaGetSymbolAddress((void**)&sh3, g_shift3);

    // dynamic smem: A + 2*B + reductions (words)
    const int smem2 = (C2 * ASTR2 + 2 * CP * BCHp + 8 * C2) * 4;
    const int smem3 = (C3 * ASTR1 + 2 * CP * BCHp + 8 * C3) * 4;
    cudaFuncSetAttribute(conv_tc_kernel<C1, C2, true, 2, ASTR2>,
                         cudaFuncAttributeMaxDynamicSharedMemorySize, smem2);
    cudaFuncSetAttribute(conv_tc_kernel<C2, C3, false, 1, ASTR1>,
                         cudaFuncAttributeMaxDynamicSharedMemorySize, smem3);

    // weight pre-pack (tap-major k)
    {
        int tot2 = (C1 / CCH) * C2 * (KC / 2);
        int tot3 = (C2 / CCH) * C3 * (KC / 2);
        prep_weights<2, ASTR2><<<(tot2 + 255) / 256, 256>>>(c2w, C1, C2, w2pk);
        prep_weights<1, ASTR1><<<(tot3 + 255) / 256, 256>>>(c3w, C2, C3, w3pk);
    }

    // conv1 -> raw y1 + stats
    dim3 grid1(8, 8, Bsz * (C1 / KOUT));
    conv1_kernel<C0, 3><<<grid1, 256>>>(x, c1w, c1b, y1p, ps1, pq1, C1 / KOUT);
    bnfin_kernel<<<C1, 256>>>(ps1, pq1, g1, be1, sc1, sh1, NSLOT1);

    // pack bn1(lrelu(y1)) -> fp16 channel pairs
    {
        long long t4 = (long long)Bsz * (C1 / 2) * Himg * Wimg / 4;
        bnpack_pair<<<(unsigned)((t4 + 255) / 256), 256>>>(y1p, sc1, sh1, y1pk, C1, t4);
    }

    // conv2 -> raw y2 + stats (2-term)
    dim3 gridTC(Wimg / TCW, Himg / TCH, Bsz);   // 8 x 64 x 16
    conv_tc_kernel<C1, C2, true, 2, ASTR2><<<gridTC, 256, smem2>>>(
        y1pk, w2pk, c2b, y2p, ps2, pq2);
    bnfin_kernel<<<C2, 256>>>(ps2, pq2, g2, be2, sc2, sh2, NSLOT_TC);

    // pack bn2(lrelu(y2))
    {
        long long t4 = (long long)Bsz * (C2 / 2) * Himg * Wimg / 4;
        bnpack_pair<<<(unsigned)((t4 + 255) / 256), 256>>>(y2p, sc2, sh2, y2pk, C2, t4);
    }

    // conv3 -> stats only (single-term: stats tolerate fp16 weight rounding)
    conv_tc_kernel<C2, C3, false, 1, ASTR1><<<gridTC, 256, smem3>>>(
        y2pk, w3pk, c3b, nullptr, ps3, pq3);
    bnfin_kernel<<<C3, 256>>>(ps3, pq3, g3, be3, sc3, sh3, NSLOT_TC);

    // final epilogue
    points_kernel<<<32, 160>>>(x, anchors, positives, c3w, c3b, rw, rb, out);
}

// round 14
// speedup vs baseline: 2.1614x; 1.0908x over previous
#include <cuda_runtime.h>
#include <cuda_fp16.h>
#include <cstddef>

// ---------------------------------------------------------------------------
// CUTSEncoder: conv1 (FFMA) -> conv2/conv3 (fp16 SINGLE-term Wh*Xh implicit
// GEMM; exact fp32 z-path recomputation at the 32 points bounds the error) ->
// BN finalize -> point epilogue.
// Activations fp16 channel-pair words (one LDS.32 per mma B operand,
// tap-major k); y2 stored fp16; 2 CTAs/SM; B halo double-buffered cp.async.
// ---------------------------------------------------------------------------

namespace {
constexpr int Bsz  = 16;
constexpr int Himg = 256;
constexpr int Wimg = 256;
constexpr int C0 = 3, C1 = 32, C2 = 64, C3 = 128;
constexpr float EPSV  = 1e-5f;
constexpr float SLOPE = 0.01f;
constexpr float NPIX  = 16.0f * 256.0f * 256.0f;

// conv1 (FFMA) tiling
constexpr int TILE  = 32;
constexpr int KOUT  = 16;
constexpr int NSLOT1 = 8 * 8 * Bsz;

// TC conv tiling: 128 pixels (4 rows x 32 cols), K chunk = 16 ch x 9 taps
constexpr int TCH = 4, TCW = 32;
constexpr int HR  = TCH + 2;            // 6 halo rows
constexpr int CCH = 16, KC = 144, KSTEPS = 9;
constexpr int CP  = CCH / 2;            // 8 channel-pair planes per chunk
constexpr int ASTR1 = 76;               // A row stride (words), hi-only
constexpr int BROW = 36;
constexpr int BCHp = HR * BROW;         // 216 words per pair-plane
constexpr int NSLOT_TC = 8 * 64 * Bsz;  // 8192 slots

// output layout
constexpr int OFF_XA = 0;
constexpr int OFF_XR = Bsz * 147;
constexpr int OFF_ZA = OFF_XR + Bsz * 147;
constexpr int OFF_ZP = OFF_ZA + Bsz * C3;
}

// ------------------------- scratch (device globals) -------------------------
__device__ float  g_y1[(size_t)Bsz * C1 * Himg * Wimg];          // raw conv1 (fp32)
__device__ __align__(16) __half g_y2h[(size_t)Bsz * C2 * Himg * Wimg]; // raw conv2 (fp16)
// packed fp16 channel-pair activations: [(b*C/2+cp)*HW + pix] = {c+1, c}
__device__ __align__(16) unsigned g_y1pk[(size_t)Bsz * (C1 / 2) * Himg * Wimg];
__device__ __align__(16) unsigned g_y2pk[(size_t)Bsz * (C2 / 2) * Himg * Wimg];

__device__ __align__(16) unsigned g_w2pk[(C1 / CCH) * C2 * ASTR1];
__device__ __align__(16) unsigned g_w3pk[(C2 / CCH) * C3 * ASTR1];

__device__ float g_ps1[C1 * NSLOT1],   g_pq1[C1 * NSLOT1];
__device__ float g_ps2[C2 * NSLOT_TC], g_pq2[C2 * NSLOT_TC];
__device__ float g_ps3[C3 * NSLOT_TC], g_pq3[C3 * NSLOT_TC];

__device__ float g_scale1[C1], g_shift1[C1];
__device__ float g_scale2[C2], g_shift2[C2];
__device__ float g_scale3[C3], g_shift3[C3];

// ------------------------------- helpers ------------------------------------
__device__ __forceinline__ unsigned f16x2pack(float a, float b) {
    unsigned w;
    asm("cvt.rn.f16x2.f32 %0, %1, %2;" : "=r"(w) : "f"(a), "f"(b));
    return w;  // [31:16]=f16(a), [15:0]=f16(b)
}

__device__ __forceinline__ void mma_f16(float* d, const unsigned* a,
                                        unsigned b0, unsigned b1) {
    asm volatile(
        "mma.sync.aligned.m16n8k16.row.col.f32.f16.f16.f32 "
        "{%0,%1,%2,%3}, {%4,%5,%6,%7}, {%8,%9}, {%0,%1,%2,%3};"
        : "+f"(d[0]), "+f"(d[1]), "+f"(d[2]), "+f"(d[3])
        : "r"(a[0]), "r"(a[1]), "r"(a[2]), "r"(a[3]), "r"(b0), "r"(b1));
}

__device__ __forceinline__ void cp_async16(void* smem, const void* gmem) {
    unsigned saddr = (unsigned)__cvta_generic_to_shared(smem);
    asm volatile("cp.async.cg.shared.global [%0], [%1], 16;"
                 :: "r"(saddr), "l"(gmem));
}

__device__ __forceinline__ void cp_async4z(void* smem, const void* gmem, int sz) {
    unsigned saddr = (unsigned)__cvta_generic_to_shared(smem);
    asm volatile("cp.async.ca.shared.global [%0], [%1], 4, %2;"
                 :: "r"(saddr), "l"(gmem), "r"(sz));
}

// --------------- weight pre-pack (fp16 hi-only, tap-major k) -----------------
__global__ void prep_weights(const float* __restrict__ w, int CIN, int M,
                             unsigned* __restrict__ dst)
{
    int idx = blockIdx.x * blockDim.x + threadIdx.x;
    int NCH = CIN / CCH;
    int tot = NCH * M * (KC / 2);
    if (idx >= tot) return;
    int cc  = idx / (M * (KC / 2));
    int rem = idx - cc * M * (KC / 2);
    int m   = rem / (KC / 2);
    int pr  = rem - m * (KC / 2);
    int ks = pr >> 3, j = pr & 7, kh = j >> 2, qq = j & 3;
    int ke = ks * 16 + kh * 8 + 2 * qq;      // even k; tap = ke>>4, c = ke&15
    int tap = ke >> 4;
    int c   = ke & 15;
    int cg  = cc * CCH + c;
    float we = w[((size_t)m * CIN + cg) * 9 + tap];
    float wo = w[((size_t)m * CIN + cg + 1) * 9 + tap];
    size_t base = ((size_t)cc * M + m) * ASTR1 + ks * 8 + qq * 2;
    dst[base + kh] = f16x2pack(wo, we);
}

// ------- bnpack (fp32 src): NCHW float -> fp16 channel-pair words ------------
__global__ void __launch_bounds__(256) bnpack_pair_f(
    const float* __restrict__ raw,
    const float* __restrict__ scale, const float* __restrict__ shift,
    unsigned* __restrict__ dst, int C, long long total4)
{
    long long i4 = (long long)blockIdx.x * blockDim.x + threadIdx.x;
    if (i4 >= total4) return;
    int plane = (int)(i4 >> 14);
    int pq = (int)(i4 & 16383);
    int half = C >> 1;
    int cp = plane % half, b = plane / half;
    int c0 = cp * 2;
    const float4 v0 = *(const float4*)(raw + (((size_t)b * C + c0) << 16) + pq * 4);
    const float4 v1 = *(const float4*)(raw + (((size_t)b * C + c0 + 1) << 16) + pq * 4);
    float s0 = __ldg(&scale[c0]),     h0 = __ldg(&shift[c0]);
    float s1 = __ldg(&scale[c0 + 1]), h1 = __ldg(&shift[c0 + 1]);
    float a0[4] = {v0.x, v0.y, v0.z, v0.w};
    float a1[4] = {v1.x, v1.y, v1.z, v1.w};
    unsigned o[4];
#pragma unroll
    for (int j = 0; j < 4; ++j) {
        float z0 = a0[j] * s0 + h0; z0 = z0 >= 0.f ? z0 : SLOPE * z0;
        float z1 = a1[j] * s1 + h1; z1 = z1 >= 0.f ? z1 : SLOPE * z1;
        o[j] = f16x2pack(z1, z0);
    }
    ((uint4*)dst)[i4] = make_uint4(o[0], o[1], o[2], o[3]);
}

// ------- bnpack (fp16 src): NCHW half -> fp16 channel-pair words -------------
__global__ void __launch_bounds__(256) bnpack_pair_h(
    const __half* __restrict__ raw,
    const float* __restrict__ scale, const float* __restrict__ shift,
    unsigned* __restrict__ dst, int C, long long total4)
{
    long long i4 = (long long)blockIdx.x * blockDim.x + threadIdx.x;
    if (i4 >= total4) return;
    int plane = (int)(i4 >> 14);
    int pq = (int)(i4 & 16383);
    int half = C >> 1;
    int cp = plane % half, b = plane / half;
    int c0 = cp * 2;
    const __half2* s0p = (const __half2*)(raw + (((size_t)b * C + c0) << 16)) + pq * 2;
    const __half2* s1p = (const __half2*)(raw + (((size_t)b * C + c0 + 1) << 16)) + pq * 2;
    float2 p00 = __half22float2(s0p[0]), p01 = __half22float2(s0p[1]);
    float2 p10 = __half22float2(s1p[0]), p11 = __half22float2(s1p[1]);
    float s0 = __ldg(&scale[c0]),     h0 = __ldg(&shift[c0]);
    float s1 = __ldg(&scale[c0 + 1]), h1 = __ldg(&shift[c0 + 1]);
    float a0[4] = {p00.x, p00.y, p01.x, p01.y};
    float a1[4] = {p10.x, p10.y, p11.x, p11.y};
    unsigned o[4];
#pragma unroll
    for (int j = 0; j < 4; ++j) {
        float z0 = a0[j] * s0 + h0; z0 = z0 >= 0.f ? z0 : SLOPE * z0;
        float z1 = a1[j] * s1 + h1; z1 = z1 >= 0.f ? z1 : SLOPE * z1;
        o[j] = f16x2pack(z1, z0);
    }
    ((uint4*)dst)[i4] = make_uint4(o[0], o[1], o[2], o[3]);
}

// ---------------- TC conv3x3 (fp16 single-term, pair-plane B) ----------------
// 256 threads = 8 warps = 2 M-warps x 4 N-warps, 2 CTAs/SM.
template <int CIN, int M, bool STORE>
__global__ void __launch_bounds__(256, 2) conv_tc_kernel(
    const unsigned* __restrict__ in,    // fp16 channel-pair activations
    const unsigned* __restrict__ wpk,   // packed fp16 weights [chunk][M][ASTR1]
    const float* __restrict__ bias,
    __half* __restrict__ out_h,         // raw conv output (fp16, NCHW)
    float* __restrict__ psum,
    float* __restrict__ psq)
{
    constexpr int NMT = M / 32;
    constexpr int NCH = CIN / CCH;
    constexpr int ASZ = M * ASTR1;      // words, single A buffer
    constexpr int BSZ = CP * BCHp;      // words per B buffer (1728)

    extern __shared__ unsigned char smem_raw[];
    unsigned* Apk = (unsigned*)smem_raw;          // ASZ
    unsigned* Bp  = Apk + ASZ;                    // 2 * BSZ
    float* red_s = (float*)(Bp + 2 * BSZ);        // 4*M
    float* red_q = red_s + 4 * M;

    const int tid = threadIdx.x;
    const int lane = tid & 31, wid = tid >> 5;
    const int mw = wid >> 2, nw = wid & 3;
    const int q = lane & 3, g = lane >> 2;
    const int bx = blockIdx.x, by = blockIdx.y, b = blockIdx.z;
    const int h0 = by * TCH, w0 = bx * TCW;

    auto stageB = [&](int cc) {
        const int cpbase = cc * CP;
        unsigned* Bd = Bp + (cc & 1) * BSZ;
        for (int idx = tid; idx < CP * HR * 34; idx += 256) {
            int p   = idx / (HR * 34);
            int rem = idx - p * (HR * 34);
            int r   = rem / 34;
            int col = rem - r * 34;
            int gh = h0 + r - 1, gw = w0 + col - 1;
            bool ok = (unsigned)gh < (unsigned)Himg && (unsigned)gw < (unsigned)Wimg;
            const unsigned* src = ok
                ? &in[(((size_t)b * (CIN / 2) + cpbase + p) << 16) + gh * 256 + gw] : in;
            cp_async4z(Bd + p * BCHp + r * BROW + col, src, ok ? 4 : 0);
        }
        asm volatile("cp.async.commit_group;" ::: "memory");
    };

    // prefetch B(0) before anything else
    stageB(0);

    float acc[NMT][4][4];
#pragma unroll
    for (int t = 0; t < NMT; ++t)
#pragma unroll
        for (int nt = 0; nt < 4; ++nt)
#pragma unroll
            for (int i = 0; i < 4; ++i) acc[t][nt][i] = 0.f;

    const int poffbase = nw * BROW + g;
    const int qrow0 = q * BCHp;             // b0 plane offset
    const int qrow1 = (q + 4) * BCHp;       // b1 plane offset

#pragma unroll 1
    for (int cc = 0; cc < NCH; ++cc) {
        // A(cc): single-buffer cp.async from L2-hot packed weights
        {
            const unsigned* srcA = wpk + (size_t)cc * ASZ;
            for (int idx = tid; idx < ASZ / 4; idx += 256)
                cp_async16(Apk + idx * 4, srcA + idx * 4);
            asm volatile("cp.async.commit_group;" ::: "memory");
        }
        if (cc + 1 < NCH) {
            stageB(cc + 1);
            asm volatile("cp.async.wait_group 1;" ::: "memory");
        } else {
            asm volatile("cp.async.wait_group 0;" ::: "memory");
        }
        __syncthreads();

        const unsigned* Bb = Bp + (cc & 1) * BSZ;

#pragma unroll
        for (int ks = 0; ks < KSTEPS; ++ks) {
            const int tapoff = (ks / 3) * BROW + (ks % 3);
            const int pbase = tapoff + poffbase;
            const int abase = ks * 8 + q * 2;
            unsigned bh[4][2];
#pragma unroll
            for (int nt = 0; nt < 4; ++nt) {
                bh[nt][0] = Bb[qrow0 + pbase + nt * 8];
                bh[nt][1] = Bb[qrow1 + pbase + nt * 8];
            }
#pragma unroll
            for (int t = 0; t < NMT; ++t) {
                const int r0w = (mw * (M / 2) + t * 16 + g) * ASTR1 + abase;
                const int r1w = r0w + 8 * ASTR1;
                uint2 xh = *(const uint2*)(Apk + r0w);
                uint2 yh = *(const uint2*)(Apk + r1w);
                unsigned ah[4] = {xh.x, yh.x, xh.y, yh.y};
#pragma unroll
                for (int nt = 0; nt < 4; ++nt)
                    mma_f16(acc[t][nt], ah, bh[nt][0], bh[nt][1]);
            }
        }
        __syncthreads();
    }

    // ---- epilogue: bias, optional fp16 store, per-channel stats ----
#pragma unroll
    for (int t = 0; t < NMT; ++t) {
        const int r0 = mw * (M / 2) + t * 16 + g, r1 = r0 + 8;
        const float bv0 = __ldg(&bias[r0]), bv1 = __ldg(&bias[r1]);
        float s0 = 0.f, q0 = 0.f, s1 = 0.f, q1 = 0.f;
#pragma unroll
        for (int nt = 0; nt < 4; ++nt) {
            float v0 = acc[t][nt][0] + bv0, v1 = acc[t][nt][1] + bv0;
            float v2 = acc[t][nt][2] + bv1, v3 = acc[t][nt][3] + bv1;
            if (STORE) {
                int wcol = w0 + nt * 8 + 2 * q;
                int hrow = h0 + nw;
                *(unsigned*)(out_h + (((size_t)b * M + r0) * Himg + hrow) * Wimg + wcol) =
                    f16x2pack(v1, v0);
                *(unsigned*)(out_h + (((size_t)b * M + r1) * Himg + hrow) * Wimg + wcol) =
                    f16x2pack(v3, v2);
            }
            s0 += v0 + v1; q0 += v0 * v0 + v1 * v1;
            s1 += v2 + v3; q1 += v2 * v2 + v3 * v3;
        }
        s0 += __shfl_xor_sync(0xffffffffu, s0, 1);
        s0 += __shfl_xor_sync(0xffffffffu, s0, 2);
        q0 += __shfl_xor_sync(0xffffffffu, q0, 1);
        q0 += __shfl_xor_sync(0xffffffffu, q0, 2);
        s1 += __shfl_xor_sync(0xffffffffu, s1, 1);
        s1 += __shfl_xor_sync(0xffffffffu, s1, 2);
        q1 += __shfl_xor_sync(0xffffffffu, q1, 1);
        q1 += __shfl_xor_sync(0xffffffffu, q1, 2);
        if (q == 0) {
            red_s[nw * M + r0] = s0; red_q[nw * M + r0] = q0;
            red_s[nw * M + r1] = s1; red_q[nw * M + r1] = q1;
        }
    }
    __syncthreads();
    if (tid < M) {
        float s = 0.f, qq = 0.f;
#pragma unroll
        for (int w = 0; w < 4; ++w) { s += red_s[w * M + tid]; qq += red_q[w * M + tid]; }
        int slot = (b * 64 + by) * 8 + bx;
        psum[tid * NSLOT_TC + slot] = s;
        psq [tid * NSLOT_TC + slot] = qq;
    }
}

// -------------------------- conv1 (FFMA, cin=3) ------------------------------
template <int CIN, int CCHUNK>
__global__ void __launch_bounds__(256) conv1_kernel(
    const float* __restrict__ in,
    const float* __restrict__ wgt,
    const float* __restrict__ bias,
    float* __restrict__ out_raw,
    float* __restrict__ psum,
    float* __restrict__ psq,
    int nCoutBlk)
{
    __shared__ float s_in[CCHUNK][TILE + 2][TILE + 2];
    __shared__ float s_w[KOUT * CCHUNK * 9];
    __shared__ float s_rs[KOUT][8];
    __shared__ float s_rq[KOUT][8];

    const int tid = threadIdx.x;
    const int tx = tid & 15, ty = tid >> 4;
    const int bx = blockIdx.x, by = blockIdx.y;
    const int b = blockIdx.z / nCoutBlk;
    const int coutBase = (blockIdx.z % nCoutBlk) * KOUT;
    const int Cout = nCoutBlk * KOUT;
    const int px = tx * 2, py = ty * 2;
    const int h0 = by * TILE, w0 = bx * TILE;

    float acc[KOUT][4];
#pragma unroll
    for (int co = 0; co < KOUT; ++co) {
        acc[co][0] = 0.f; acc[co][1] = 0.f; acc[co][2] = 0.f; acc[co][3] = 0.f;
    }

    for (int idx = tid; idx < CCHUNK * (TILE + 2) * (TILE + 2); idx += 256) {
        int c   = idx / ((TILE + 2) * (TILE + 2));
        int rem = idx - c * (TILE + 2) * (TILE + 2);
        int r   = rem / (TILE + 2);
        int col = rem - r * (TILE + 2);
        int gh = h0 + r - 1, gw = w0 + col - 1;
        float v = 0.f;
        if ((unsigned)gh < (unsigned)Himg && (unsigned)gw < (unsigned)Wimg)
            v = in[(((size_t)b * CIN + c) * Himg + gh) * Wimg + gw];
        (&s_in[0][0][0])[idx] = v;
    }
    for (int idx = tid; idx < KOUT * CCHUNK * 9; idx += 256) {
        int co  = idx / (CCHUNK * 9);
        int rem = idx - co * (CCHUNK * 9);
        s_w[idx] = wgt[((size_t)(coutBase + co) * CIN) * 9 + rem];
    }
    __syncthreads();

#pragma unroll
    for (int c = 0; c < CCHUNK; ++c)
#pragma unroll
        for (int dy = 0; dy < 3; ++dy)
#pragma unroll
            for (int dx = 0; dx < 3; ++dx) {
                float i00 = s_in[c][py + dy][px + dx];
                float i01 = s_in[c][py + dy][px + dx + 1];
                float i10 = s_in[c][py + dy + 1][px + dx];
                float i11 = s_in[c][py + dy + 1][px + dx + 1];
#pragma unroll
                for (int co = 0; co < KOUT; ++co) {
                    float wv = s_w[(co * CCHUNK + c) * 9 + dy * 3 + dx];
                    acc[co][0] = fmaf(i00, wv, acc[co][0]);
                    acc[co][1] = fmaf(i01, wv, acc[co][1]);
                    acc[co][2] = fmaf(i10, wv, acc[co][2]);
                    acc[co][3] = fmaf(i11, wv, acc[co][3]);
                }
            }

    const int lane = tid & 31, wrp = tid >> 5;
#pragma unroll 1
    for (int co = 0; co < KOUT; ++co) {
        float bv = __ldg(&bias[coutBase + co]);
        float v0 = acc[co][0] + bv, v1 = acc[co][1] + bv;
        float v2 = acc[co][2] + bv, v3 = acc[co][3] + bv;
        size_t rowb = ((size_t)b * Cout + coutBase + co) * Himg;
        out_raw[(rowb + h0 + py) * Wimg + w0 + px]         = v0;
        out_raw[(rowb + h0 + py) * Wimg + w0 + px + 1]     = v1;
        out_raw[(rowb + h0 + py + 1) * Wimg + w0 + px]     = v2;
        out_raw[(rowb + h0 + py + 1) * Wimg + w0 + px + 1] = v3;
        float s = v0 + v1 + v2 + v3;
        float qv = v0 * v0 + v1 * v1 + v2 * v2 + v3 * v3;
#pragma unroll
        for (int o = 16; o > 0; o >>= 1) {
            s  += __shfl_down_sync(0xffffffffu, s, o);
            qv += __shfl_down_sync(0xffffffffu, qv, o);
        }
        if (lane == 0) { s_rs[co][wrp] = s; s_rq[co][wrp] = qv; }
    }
    __syncthreads();
    if (tid < KOUT) {
        float s = 0.f, qv = 0.f;
#pragma unroll
        for (int w = 0; w < 8; ++w) { s += s_rs[tid][w]; qv += s_rq[tid][w]; }
        int slot = (by * gridDim.x + bx) * Bsz + b;
        psum[(coutBase + tid) * NSLOT1 + slot] = s;
        psq [(coutBase + tid) * NSLOT1 + slot] = qv;
    }
}

// ------------------------- BN stats finalize ---------------------------------
__global__ void __launch_bounds__(256) bnfin_kernel(
    const float* __restrict__ psum, const float* __restrict__ psq,
    const float* __restrict__ gamma, const float* __restrict__ beta,
    float* __restrict__ scale, float* __restrict__ shift, int nslot)
{
    __shared__ float ss[256], sq[256];
    int c = blockIdx.x;
    float s = 0.f, q = 0.f;
    for (int i = threadIdx.x; i < nslot; i += 256) {
        s += psum[c * nslot + i];
        q += psq [c * nslot + i];
    }
    ss[threadIdx.x] = s; sq[threadIdx.x] = q;
    __syncthreads();
    for (int o = 128; o > 0; o >>= 1) {
        if (threadIdx.x < o) {
            ss[threadIdx.x] += ss[threadIdx.x + o];
            sq[threadIdx.x] += sq[threadIdx.x + o];
        }
        __syncthreads();
    }
    if (threadIdx.x == 0) {
        float mean = ss[0] / NPIX;
        float var  = sq[0] / NPIX - mean * mean;
        float sc   = gamma[c] * rsqrtf(var + EPSV);
        scale[c] = sc;
        shift[c] = beta[c] - mean * sc;
    }
}

// ---------------- final: 32 point z3 vectors + recon + patches ---------------
__global__ void __launch_bounds__(160) points_kernel(
    const float* __restrict__ x,
    const int* __restrict__ anchors,
    const int* __restrict__ positives,
    const float* __restrict__ w3, const float* __restrict__ b3,
    const float* __restrict__ recon_w, const float* __restrict__ recon_b,
    float* __restrict__ out)
{
    __shared__ float s_in[C2 * 9];
    __shared__ float s_z[C3];
    const int kind = blockIdx.x & 1;
    const int b = blockIdx.x >> 1;
    const int* pts = kind ? positives : anchors;
    const int h = pts[b * 8 + 6];
    const int w = pts[b * 8 + 7];
    const int tid = threadIdx.x;

    // z2 neighborhood from fp16 y2 + BN2 (fp32 affine)
    for (int idx = tid; idx < C2 * 9; idx += 160) {
        int c = idx / 9, tap = idx - c * 9;
        int dy = tap / 3, dx = tap - dy * 3;
        float v = __half2float(
            g_y2h[(((size_t)b * C2 + c) * Himg + (h + dy - 1)) * Wimg + (w + dx - 1)]);
        float z = v * g_scale2[c] + g_shift2[c];
        s_in[idx] = z >= 0.f ? z : SLOPE * z;
    }
    __syncthreads();

    if (tid < C3) {
        float a = b3[tid];
        const float* wr = w3 + (size_t)tid * C2 * 9;
#pragma unroll 4
        for (int i = 0; i < C2 * 9; ++i) a = fmaf(s_in[i], __ldg(&wr[i]), a);
        float z = a * g_scale3[tid] + g_shift3[tid];
        z = z >= 0.f ? z : SLOPE * z;
        s_z[tid] = z;
        out[(kind ? OFF_ZP : OFF_ZA) + b * C3 + tid] = z;
    }
    __syncthreads();

    if (kind == 0) {
        for (int j = tid; j < 147; j += 160) {
            float r = recon_b[j];
            const float* wr = recon_w + (size_t)j * C3;
#pragma unroll 4
            for (int k = 0; k < C3; ++k) r = fmaf(s_z[k], __ldg(&wr[k]), r);
            out[OFF_XR + b * 147 + j] = r;
        }
        for (int idx = tid; idx < 147; idx += 160) {
            int c = idx / 49, rem = idx - c * 49;
            int pyy = rem / 7, pxx = rem - pyy * 7;
            out[OFF_XA + b * 147 + idx] =
                x[(((size_t)b * C0 + c) * Himg + (h - 3 + pyy)) * Wimg + (w - 3 + pxx)];
        }
    }
}

// --------------------------------- launch ------------------------------------
extern "C" void kernel_launch(void* const* d_in, const int* in_sizes, int n_in,
                              void* d_out, int out_size)
{
    const float* x        = (const float*)d_in[0];
    const int*   anchors  = (const int*)  d_in[1];
    const int*   positives= (const int*)  d_in[2];
    const float* c1w = (const float*)d_in[3];
    const float* c1b = (const float*)d_in[4];
    const float* g1  = (const float*)d_in[5];
    const float* be1 = (const float*)d_in[6];
    const float* c2w = (const float*)d_in[7];
    const float* c2b = (const float*)d_in[8];
    const float* g2  = (const float*)d_in[9];
    const float* be2 = (const float*)d_in[10];
    const float* c3w = (const float*)d_in[11];
    const float* c3b = (const float*)d_in[12];
    const float* g3  = (const float*)d_in[13];
    const float* be3 = (const float*)d_in[14];
    const float* rw  = (const float*)d_in[15];
    const float* rb  = (const float*)d_in[16];
    float* out = (float*)d_out;

    float *y1p; __half *y2hp; unsigned *y1pk, *y2pk, *w2pk, *w3pk;
    float *ps1, *pq1, *ps2, *pq2, *ps3, *pq3;
    float *sc1, *sh1, *sc2, *sh2, *sc3, *sh3;
    cudaGetSymbolAddress((void**)&y1p, g_y1);
    cudaGetSymbolAddress((void**)&y2hp, g_y2h);
    cudaGetSymbolAddress((void**)&y1pk, g_y1pk);
    cudaGetSymbolAddress((void**)&y2pk, g_y2pk);
    cudaGetSymbolAddress((void**)&w2pk, g_w2pk);
    cudaGetSymbolAddress((void**)&w3pk, g_w3pk);
    cudaGetSymbolAddress((void**)&ps1, g_ps1);
    cudaGetSymbolAddress((void**)&pq1, g_pq1);
    cudaGetSymbolAddress((void**)&ps2, g_ps2);
    cudaGetSymbolAddress((void**)&pq2, g_pq2);
    cudaGetSymbolAddress((void**)&ps3, g_ps3);
    cudaGetSymbolAddress((void**)&pq3, g_pq3);
    cudaGetSymbolAddress((void**)&sc1, g_scale1);
    cudaGetSymbolAddress((void**)&sh1, g_shift1);
    cudaGetSymbolAddress((void**)&sc2, g_scale2);
    cudaGetSymbolAddress((void**)&sh2, g_shift2);
    cudaGetSymbolAddress((void**)&sc3, g_scale3);
    cudaGetSymbolAddress((void**)&sh3, g_shift3);

    // dynamic smem: A + 2*B + reductions (words)
    const int smem2 = (C2 * ASTR1 + 2 * CP * BCHp + 8 * C2) * 4;
    const int smem3 = (C3 * ASTR1 + 2 * CP * BCHp + 8 * C3) * 4;
    cudaFuncSetAttribute(conv_tc_kernel<C1, C2, true>,
                         cudaFuncAttributeMaxDynamicSharedMemorySize, smem2);
    cudaFuncSetAttribute(conv_tc_kernel<C2, C3, false>,
                         cudaFuncAttributeMaxDynamicSharedMemorySize, smem3);

    // weight pre-pack (hi-only, tap-major k)
    {
        int tot2 = (C1 / CCH) * C2 * (KC / 2);
        int tot3 = (C2 / CCH) * C3 * (KC / 2);
        prep_weights<<<(tot2 + 255) / 256, 256>>>(c2w, C1, C2, w2pk);
        prep_weights<<<(tot3 + 255) / 256, 256>>>(c3w, C2, C3, w3pk);
    }

    // conv1 -> raw y1 (fp32) + stats
    dim3 grid1(8, 8, Bsz * (C1 / KOUT));
    conv1_kernel<C0, 3><<<grid1, 256>>>(x, c1w, c1b, y1p, ps1, pq1, C1 / KOUT);
    bnfin_kernel<<<C1, 256>>>(ps1, pq1, g1, be1, sc1, sh1, NSLOT1);

    // pack bn1(lrelu(y1)) -> fp16 channel pairs
    {
        long long t4 = (long long)Bsz * (C1 / 2) * Himg * Wimg / 4;
        bnpack_pair_f<<<(unsigned)((t4 + 255) / 256), 256>>>(y1p, sc1, sh1, y1pk, C1, t4);
    }

    // conv2 -> raw y2 (fp16) + stats (single-term)
    dim3 gridTC(Wimg / TCW, Himg / TCH, Bsz);   // 8 x 64 x 16
    conv_tc_kernel<C1, C2, true><<<gridTC, 256, smem2>>>(
        y1pk, w2pk, c2b, y2hp, ps2, pq2);
    bnfin_kernel<<<C2, 256>>>(ps2, pq2, g2, be2, sc2, sh2, NSLOT_TC);

    // pack bn2(lrelu(y2)) from fp16 source
    {
        long long t4 = (long long)Bsz * (C2 / 2) * Himg * Wimg / 4;
        bnpack_pair_h<<<(unsigned)((t4 + 255) / 256), 256>>>(y2hp, sc2, sh2, y2pk, C2, t4);
    }

    // conv3 -> stats only (single-term)
    conv_tc_kernel<C2, C3, false><<<gridTC, 256, smem3>>>(
        y2pk, w3pk, c3b, nullptr, ps3, pq3);
    bnfin_kernel<<<C3, 256>>>(ps3, pq3, g3, be3, sc3, sh3, NSLOT_TC);

    // final epilogue
    points_kernel<<<32, 160>>>(x, anchors, positives, c3w, c3b, rw, rb, out);
}

// round 16
// speedup vs baseline: 2.2386x; 1.0357x over previous
#include <cuda_runtime.h>
#include <cuda_fp16.h>
#include <cstddef>

// ---------------------------------------------------------------------------
// CUTSEncoder: conv1 (FFMA, fp16 out) -> conv2 (fp16 mma, f32 acc) ->
// conv3 (fp16 mma, f16 acc: output feeds ONLY BN3 stats, noise averages out)
// -> BN finalize -> point epilogue (exact fp32 recompute of the 32 z3 points).
// Single-term Wh*Xh; activations fp16 channel-pair words (one LDS.32 per mma
// B operand, tap-major k); 2 CTAs/SM; B halo double-buffered cp.async.
// ---------------------------------------------------------------------------

namespace {
constexpr int Bsz  = 16;
constexpr int Himg = 256;
constexpr int Wimg = 256;
constexpr int C0 = 3, C1 = 32, C2 = 64, C3 = 128;
constexpr float EPSV  = 1e-5f;
constexpr float SLOPE = 0.01f;
constexpr float NPIX  = 16.0f * 256.0f * 256.0f;

// conv1 (FFMA) tiling
constexpr int TILE  = 32;
constexpr int KOUT  = 16;
constexpr int NSLOT1 = 8 * 8 * Bsz;

// TC conv tiling: 128 pixels (4 rows x 32 cols), K chunk = 16 ch x 9 taps
constexpr int TCH = 4, TCW = 32;
constexpr int HR  = TCH + 2;            // 6 halo rows
constexpr int CCH = 16, KC = 144, KSTEPS = 9;
constexpr int CP  = CCH / 2;            // 8 channel-pair planes per chunk
constexpr int ASTR1 = 76;               // A row stride (words), hi-only
constexpr int BROW = 36;
constexpr int BCHp = HR * BROW;         // 216 words per pair-plane
constexpr int NSLOT_TC = 8 * 64 * Bsz;  // 8192 slots

// output layout
constexpr int OFF_XA = 0;
constexpr int OFF_XR = Bsz * 147;
constexpr int OFF_ZA = OFF_XR + Bsz * 147;
constexpr int OFF_ZP = OFF_ZA + Bsz * C3;
}

// ------------------------- scratch (device globals) -------------------------
__device__ __align__(16) __half g_y1h[(size_t)Bsz * C1 * Himg * Wimg]; // raw conv1 (fp16)
__device__ __align__(16) __half g_y2h[(size_t)Bsz * C2 * Himg * Wimg]; // raw conv2 (fp16)
// packed fp16 channel-pair activations: [(b*C/2+cp)*HW + pix] = {c+1, c}
__device__ __align__(16) unsigned g_y1pk[(size_t)Bsz * (C1 / 2) * Himg * Wimg];
__device__ __align__(16) unsigned g_y2pk[(size_t)Bsz * (C2 / 2) * Himg * Wimg];

__device__ __align__(16) unsigned g_w2pk[(C1 / CCH) * C2 * ASTR1];
__device__ __align__(16) unsigned g_w3pk[(C2 / CCH) * C3 * ASTR1];

__device__ float g_ps1[C1 * NSLOT1],   g_pq1[C1 * NSLOT1];
__device__ float g_ps2[C2 * NSLOT_TC], g_pq2[C2 * NSLOT_TC];
__device__ float g_ps3[C3 * NSLOT_TC], g_pq3[C3 * NSLOT_TC];

__device__ float g_scale1[C1], g_shift1[C1];
__device__ float g_scale2[C2], g_shift2[C2];
__device__ float g_scale3[C3], g_shift3[C3];

// ------------------------------- helpers ------------------------------------
__device__ __forceinline__ unsigned f16x2pack(float a, float b) {
    unsigned w;
    asm("cvt.rn.f16x2.f32 %0, %1, %2;" : "=r"(w) : "f"(a), "f"(b));
    return w;  // [31:16]=f16(a), [15:0]=f16(b)
}

__device__ __forceinline__ void mma_f16(float* d, const unsigned* a,
                                        unsigned b0, unsigned b1) {
    asm volatile(
        "mma.sync.aligned.m16n8k16.row.col.f32.f16.f16.f32 "
        "{%0,%1,%2,%3}, {%4,%5,%6,%7}, {%8,%9}, {%0,%1,%2,%3};"
        : "+f"(d[0]), "+f"(d[1]), "+f"(d[2]), "+f"(d[3])
        : "r"(a[0]), "r"(a[1]), "r"(a[2]), "r"(a[3]), "r"(b0), "r"(b1));
}

// fp16-accumulate variant (2x HMMA rate on most parts)
__device__ __forceinline__ void mma_f16h(unsigned* d, const unsigned* a,
                                         unsigned b0, unsigned b1) {
    asm volatile(
        "mma.sync.aligned.m16n8k16.row.col.f16.f16.f16.f16 "
        "{%0,%1}, {%2,%3,%4,%5}, {%6,%7}, {%0,%1};"
        : "+r"(d[0]), "+r"(d[1])
        : "r"(a[0]), "r"(a[1]), "r"(a[2]), "r"(a[3]), "r"(b0), "r"(b1));
}

__device__ __forceinline__ void cp_async16(void* smem, const void* gmem) {
    unsigned saddr = (unsigned)__cvta_generic_to_shared(smem);
    asm volatile("cp.async.cg.shared.global [%0], [%1], 16;"
                 :: "r"(saddr), "l"(gmem));
}

__device__ __forceinline__ void cp_async4z(void* smem, const void* gmem, int sz) {
    unsigned saddr = (unsigned)__cvta_generic_to_shared(smem);
    asm volatile("cp.async.ca.shared.global [%0], [%1], 4, %2;"
                 :: "r"(saddr), "l"(gmem), "r"(sz));
}

// --------------- weight pre-pack (fp16 hi-only, tap-major k) -----------------
__global__ void prep_weights(const float* __restrict__ w, int CIN, int M,
                             unsigned* __restrict__ dst)
{
    int idx = blockIdx.x * blockDim.x + threadIdx.x;
    int NCH = CIN / CCH;
    int tot = NCH * M * (KC / 2);
    if (idx >= tot) return;
    int cc  = idx / (M * (KC / 2));
    int rem = idx - cc * M * (KC / 2);
    int m   = rem / (KC / 2);
    int pr  = rem - m * (KC / 2);
    int ks = pr >> 3, j = pr & 7, kh = j >> 2, qq = j & 3;
    int ke = ks * 16 + kh * 8 + 2 * qq;      // even k; tap = ke>>4, c = ke&15
    int tap = ke >> 4;
    int c   = ke & 15;
    int cg  = cc * CCH + c;
    float we = w[((size_t)m * CIN + cg) * 9 + tap];
    float wo = w[((size_t)m * CIN + cg + 1) * 9 + tap];
    size_t base = ((size_t)cc * M + m) * ASTR1 + ks * 8 + qq * 2;
    dst[base + kh] = f16x2pack(wo, we);
}

// ------- bnpack (fp16 src): NCHW half -> fp16 channel-pair words -------------
__global__ void __launch_bounds__(256) bnpack_pair_h(
    const __half* __restrict__ raw,
    const float* __restrict__ scale, const float* __restrict__ shift,
    unsigned* __restrict__ dst, int C, long long total4)
{
    long long i4 = (long long)blockIdx.x * blockDim.x + threadIdx.x;
    if (i4 >= total4) return;
    int plane = (int)(i4 >> 14);
    int pq = (int)(i4 & 16383);
    int half = C >> 1;
    int cp = plane % half, b = plane / half;
    int c0 = cp * 2;
    const __half2* s0p = (const __half2*)(raw + (((size_t)b * C + c0) << 16)) + pq * 2;
    const __half2* s1p = (const __half2*)(raw + (((size_t)b * C + c0 + 1) << 16)) + pq * 2;
    float2 p00 = __half22float2(s0p[0]), p01 = __half22float2(s0p[1]);
    float2 p10 = __half22float2(s1p[0]), p11 = __half22float2(s1p[1]);
    float s0 = __ldg(&scale[c0]),     h0 = __ldg(&shift[c0]);
    float s1 = __ldg(&scale[c0 + 1]), h1 = __ldg(&shift[c0 + 1]);
    float a0[4] = {p00.x, p00.y, p01.x, p01.y};
    float a1[4] = {p10.x, p10.y, p11.x, p11.y};
    unsigned o[4];
#pragma unroll
    for (int j = 0; j < 4; ++j) {
        float z0 = a0[j] * s0 + h0; z0 = z0 >= 0.f ? z0 : SLOPE * z0;
        float z1 = a1[j] * s1 + h1; z1 = z1 >= 0.f ? z1 : SLOPE * z1;
        o[j] = f16x2pack(z1, z0);
    }
    ((uint4*)dst)[i4] = make_uint4(o[0], o[1], o[2], o[3]);
}

// ---------------- TC conv3x3 (fp16 single-term, pair-plane B) ----------------
// 256 threads = 8 warps = 2 M-warps x 4 N-warps, 2 CTAs/SM.
// HACC: fp16 accumulators (conv3 / stats-only path).
template <int CIN, int M, bool STORE, bool HACC>
__global__ void __launch_bounds__(256, 2) conv_tc_kernel(
    const unsigned* __restrict__ in,    // fp16 channel-pair activations
    const unsigned* __restrict__ wpk,   // packed fp16 weights [chunk][M][ASTR1]
    const float* __restrict__ bias,
    __half* __restrict__ out_h,         // raw conv output (fp16, NCHW)
    float* __restrict__ psum,
    float* __restrict__ psq)
{
    constexpr int NMT = M / 32;
    constexpr int NCH = CIN / CCH;
    constexpr int ASZ = M * ASTR1;      // words, single A buffer
    constexpr int BSZ = CP * BCHp;      // words per B buffer (1728)

    extern __shared__ unsigned char smem_raw[];
    unsigned* Apk = (unsigned*)smem_raw;          // ASZ
    unsigned* Bp  = Apk + ASZ;                    // 2 * BSZ
    float* red_s = (float*)(Bp + 2 * BSZ);        // 4*M
    float* red_q = red_s + 4 * M;

    const int tid = threadIdx.x;
    const int lane = tid & 31, wid = tid >> 5;
    const int mw = wid >> 2, nw = wid & 3;
    const int q = lane & 3, g = lane >> 2;
    const int bx = blockIdx.x, by = blockIdx.y, b = blockIdx.z;
    const int h0 = by * TCH, w0 = bx * TCW;

    auto stageB = [&](int cc) {
        const int cpbase = cc * CP;
        unsigned* Bd = Bp + (cc & 1) * BSZ;
        for (int idx = tid; idx < CP * HR * 34; idx += 256) {
            int p   = idx / (HR * 34);
            int rem = idx - p * (HR * 34);
            int r   = rem / 34;
            int col = rem - r * 34;
            int gh = h0 + r - 1, gw = w0 + col - 1;
            bool ok = (unsigned)gh < (unsigned)Himg && (unsigned)gw < (unsigned)Wimg;
            const unsigned* src = ok
                ? &in[(((size_t)b * (CIN / 2) + cpbase + p) << 16) + gh * 256 + gw] : in;
            cp_async4z(Bd + p * BCHp + r * BROW + col, src, ok ? 4 : 0);
        }
        asm volatile("cp.async.commit_group;" ::: "memory");
    };

    // prefetch B(0) before anything else
    stageB(0);

    float    accf[HACC ? 1 : NMT][4][4];
    unsigned acch[HACC ? NMT : 1][4][2];
#pragma unroll
    for (int t = 0; t < (HACC ? NMT : 1); ++t)
#pragma unroll
        for (int nt = 0; nt < 4; ++nt) { acch[t][nt][0] = 0u; acch[t][nt][1] = 0u; }
#pragma unroll
    for (int t = 0; t < (HACC ? 1 : NMT); ++t)
#pragma unroll
        for (int nt = 0; nt < 4; ++nt)
#pragma unroll
            for (int i = 0; i < 4; ++i) accf[t][nt][i] = 0.f;

    const int poffbase = nw * BROW + g;
    const int qrow0 = q * BCHp;             // b0 plane offset
    const int qrow1 = (q + 4) * BCHp;       // b1 plane offset

#pragma unroll 1
    for (int cc = 0; cc < NCH; ++cc) {
        // A(cc): single-buffer cp.async from L2-hot packed weights
        {
            const unsigned* srcA = wpk + (size_t)cc * ASZ;
            for (int idx = tid; idx < ASZ / 4; idx += 256)
                cp_async16(Apk + idx * 4, srcA + idx * 4);
            asm volatile("cp.async.commit_group;" ::: "memory");
        }
        if (cc + 1 < NCH) {
            stageB(cc + 1);
            asm volatile("cp.async.wait_group 1;" ::: "memory");
        } else {
            asm volatile("cp.async.wait_group 0;" ::: "memory");
        }
        __syncthreads();

        const unsigned* Bb = Bp + (cc & 1) * BSZ;

#pragma unroll
        for (int ks = 0; ks < KSTEPS; ++ks) {
            const int tapoff = (ks / 3) * BROW + (ks % 3);
            const int pbase = tapoff + poffbase;
            const int abase = ks * 8 + q * 2;
            unsigned bh[4][2];
#pragma unroll
            for (int nt = 0; nt < 4; ++nt) {
                bh[nt][0] = Bb[qrow0 + pbase + nt * 8];
                bh[nt][1] = Bb[qrow1 + pbase + nt * 8];
            }
#pragma unroll
            for (int t = 0; t < NMT; ++t) {
                const int r0w = (mw * (M / 2) + t * 16 + g) * ASTR1 + abase;
                const int r1w = r0w + 8 * ASTR1;
                uint2 xh = *(const uint2*)(Apk + r0w);
                uint2 yh = *(const uint2*)(Apk + r1w);
                unsigned ah[4] = {xh.x, yh.x, xh.y, yh.y};
                if (HACC) {
#pragma unroll
                    for (int nt = 0; nt < 4; ++nt)
                        mma_f16h(acch[t][nt], ah, bh[nt][0], bh[nt][1]);
                } else {
#pragma unroll
                    for (int nt = 0; nt < 4; ++nt)
                        mma_f16(accf[t][nt], ah, bh[nt][0], bh[nt][1]);
                }
            }
        }
        __syncthreads();
    }

    // ---- epilogue: bias, optional fp16 store, per-channel stats ----
#pragma unroll
    for (int t = 0; t < NMT; ++t) {
        const int r0 = mw * (M / 2) + t * 16 + g, r1 = r0 + 8;
        const float bv0 = __ldg(&bias[r0]), bv1 = __ldg(&bias[r1]);
        float s0 = 0.f, q0 = 0.f, s1 = 0.f, q1 = 0.f;
#pragma unroll
        for (int nt = 0; nt < 4; ++nt) {
            float v0, v1, v2, v3;
            if (HACC) {
                float2 f01 = __half22float2(*(__half2*)&acch[t][nt][0]);
                float2 f23 = __half22float2(*(__half2*)&acch[t][nt][1]);
                v0 = f01.x + bv0; v1 = f01.y + bv0;
                v2 = f23.x + bv1; v3 = f23.y + bv1;
            } else {
                v0 = accf[t][nt][0] + bv0; v1 = accf[t][nt][1] + bv0;
                v2 = accf[t][nt][2] + bv1; v3 = accf[t][nt][3] + bv1;
            }
            if (STORE) {
                int wcol = w0 + nt * 8 + 2 * q;
                int hrow = h0 + nw;
                *(unsigned*)(out_h + (((size_t)b * M + r0) * Himg + hrow) * Wimg + wcol) =
                    f16x2pack(v1, v0);
                *(unsigned*)(out_h + (((size_t)b * M + r1) * Himg + hrow) * Wimg + wcol) =
                    f16x2pack(v3, v2);
            }
            s0 += v0 + v1; q0 += v0 * v0 + v1 * v1;
            s1 += v2 + v3; q1 += v2 * v2 + v3 * v3;
        }
        s0 += __shfl_xor_sync(0xffffffffu, s0, 1);
        s0 += __shfl_xor_sync(0xffffffffu, s0, 2);
        q0 += __shfl_xor_sync(0xffffffffu, q0, 1);
        q0 += __shfl_xor_sync(0xffffffffu, q0, 2);
        s1 += __shfl_xor_sync(0xffffffffu, s1, 1);
        s1 += __shfl_xor_sync(0xffffffffu, s1, 2);
        q1 += __shfl_xor_sync(0xffffffffu, q1, 1);
        q1 += __shfl_xor_sync(0xffffffffu, q1, 2);
        if (q == 0) {
            red_s[nw * M + r0] = s0; red_q[nw * M + r0] = q0;
            red_s[nw * M + r1] = s1; red_q[nw * M + r1] = q1;
        }
    }
    __syncthreads();
    if (tid < M) {
        float s = 0.f, qq = 0.f;
#pragma unroll
        for (int w = 0; w < 4; ++w) { s += red_s[w * M + tid]; qq += red_q[w * M + tid]; }
        int slot = (b * 64 + by) * 8 + bx;
        psum[tid * NSLOT_TC + slot] = s;
        psq [tid * NSLOT_TC + slot] = qq;
    }
}

// -------------------------- conv1 (FFMA, cin=3, fp16 out) --------------------
template <int CIN, int CCHUNK>
__global__ void __launch_bounds__(256) conv1_kernel(
    const float* __restrict__ in,
    const float* __restrict__ wgt,
    const float* __restrict__ bias,
    __half* __restrict__ out_h,
    float* __restrict__ psum,
    float* __restrict__ psq,
    int nCoutBlk)
{
    __shared__ float s_in[CCHUNK][TILE + 2][TILE + 2];
    __shared__ float s_w[KOUT * CCHUNK * 9];
    __shared__ float s_rs[KOUT][8];
    __shared__ float s_rq[KOUT][8];

    const int tid = threadIdx.x;
    const int tx = tid & 15, ty = tid >> 4;
    const int bx = blockIdx.x, by = blockIdx.y;
    const int b = blockIdx.z / nCoutBlk;
    const int coutBase = (blockIdx.z % nCoutBlk) * KOUT;
    const int Cout = nCoutBlk * KOUT;
    const int px = tx * 2, py = ty * 2;
    const int h0 = by * TILE, w0 = bx * TILE;

    float acc[KOUT][4];
#pragma unroll
    for (int co = 0; co < KOUT; ++co) {
        acc[co][0] = 0.f; acc[co][1] = 0.f; acc[co][2] = 0.f; acc[co][3] = 0.f;
    }

    for (int idx = tid; idx < CCHUNK * (TILE + 2) * (TILE + 2); idx += 256) {
        int c   = idx / ((TILE + 2) * (TILE + 2));
        int rem = idx - c * (TILE + 2) * (TILE + 2);
        int r   = rem / (TILE + 2);
        int col = rem - r * (TILE + 2);
        int gh = h0 + r - 1, gw = w0 + col - 1;
        float v = 0.f;
        if ((unsigned)gh < (unsigned)Himg && (unsigned)gw < (unsigned)Wimg)
            v = in[(((size_t)b * CIN + c) * Himg + gh) * Wimg + gw];
        (&s_in[0][0][0])[idx] = v;
    }
    for (int idx = tid; idx < KOUT * CCHUNK * 9; idx += 256) {
        int co  = idx / (CCHUNK * 9);
        int rem = idx - co * (CCHUNK * 9);
        s_w[idx] = wgt[((size_t)(coutBase + co) * CIN) * 9 + rem];
    }
    __syncthreads();

#pragma unroll
    for (int c = 0; c < CCHUNK; ++c)
#pragma unroll
        for (int dy = 0; dy < 3; ++dy)
#pragma unroll
            for (int dx = 0; dx < 3; ++dx) {
                float i00 = s_in[c][py + dy][px + dx];
                float i01 = s_in[c][py + dy][px + dx + 1];
                float i10 = s_in[c][py + dy + 1][px + dx];
                float i11 = s_in[c][py + dy + 1][px + dx + 1];
#pragma unroll
                for (int co = 0; co < KOUT; ++co) {
                    float wv = s_w[(co * CCHUNK + c) * 9 + dy * 3 + dx];
                    acc[co][0] = fmaf(i00, wv, acc[co][0]);
                    acc[co][1] = fmaf(i01, wv, acc[co][1]);
                    acc[co][2] = fmaf(i10, wv, acc[co][2]);
                    acc[co][3] = fmaf(i11, wv, acc[co][3]);
                }
            }

    const int lane = tid & 31, wrp = tid >> 5;
#pragma unroll 1
    for (int co = 0; co < KOUT; ++co) {
        float bv = __ldg(&bias[coutBase + co]);
        float v0 = acc[co][0] + bv, v1 = acc[co][1] + bv;
        float v2 = acc[co][2] + bv, v3 = acc[co][3] + bv;
        size_t rowb = ((size_t)b * Cout + coutBase + co) * Himg;
        *(unsigned*)(out_h + (rowb + h0 + py) * Wimg + w0 + px)     = f16x2pack(v1, v0);
        *(unsigned*)(out_h + (rowb + h0 + py + 1) * Wimg + w0 + px) = f16x2pack(v3, v2);
        float s = v0 + v1 + v2 + v3;
        float qv = v0 * v0 + v1 * v1 + v2 * v2 + v3 * v3;
#pragma unroll
        for (int o = 16; o > 0; o >>= 1) {
            s  += __shfl_down_sync(0xffffffffu, s, o);
            qv += __shfl_down_sync(0xffffffffu, qv, o);
        }
        if (lane == 0) { s_rs[co][wrp] = s; s_rq[co][wrp] = qv; }
    }
    __syncthreads();
    if (tid < KOUT) {
        float s = 0.f, qv = 0.f;
#pragma unroll
        for (int w = 0; w < 8; ++w) { s += s_rs[tid][w]; qv += s_rq[tid][w]; }
        int slot = (by * gridDim.x + bx) * Bsz + b;
        psum[(coutBase + tid) * NSLOT1 + slot] = s;
        psq [(coutBase + tid) * NSLOT1 + slot] = qv;
    }
}

// ------------------------- BN stats finalize ---------------------------------
__global__ void __launch_bounds__(256) bnfin_kernel(
    const float* __restrict__ psum, const float* __restrict__ psq,
    const float* __restrict__ gamma, const float* __restrict__ beta,
    float* __restrict__ scale, float* __restrict__ shift, int nslot)
{
    __shared__ float ss[256], sq[256];
    int c = blockIdx.x;
    float s = 0.f, q = 0.f;
    for (int i = threadIdx.x; i < nslot; i += 256) {
        s += psum[c * nslot + i];
        q += psq [c * nslot + i];
    }
    ss[threadIdx.x] = s; sq[threadIdx.x] = q;
    __syncthreads();
    for (int o = 128; o > 0; o >>= 1) {
        if (threadIdx.x < o) {
            ss[threadIdx.x] += ss[threadIdx.x + o];
            sq[threadIdx.x] += sq[threadIdx.x + o];
        }
        __syncthreads();
    }
    if (threadIdx.x == 0) {
        float mean = ss[0] / NPIX;
        float var  = sq[0] / NPIX - mean * mean;
        float sc   = gamma[c] * rsqrtf(var + EPSV);
        scale[c] = sc;
        shift[c] = beta[c] - mean * sc;
    }
}

// ---------------- final: 32 point z3 vectors + recon + patches ---------------
__global__ void __launch_bounds__(160) points_kernel(
    const float* __restrict__ x,
    const int* __restrict__ anchors,
    const int* __restrict__ positives,
    const float* __restrict__ w3, const float* __restrict__ b3,
    const float* __restrict__ recon_w, const float* __restrict__ recon_b,
    float* __restrict__ out)
{
    __shared__ float s_in[C2 * 9];
    __shared__ float s_z[C3];
    const int kind = blockIdx.x & 1;
    const int b = blockIdx.x >> 1;
    const int* pts = kind ? positives : anchors;
    const int h = pts[b * 8 + 6];
    const int w = pts[b * 8 + 7];
    const int tid = threadIdx.x;

    // z2 neighborhood from fp16 y2 + BN2 (fp32 affine)
    for (int idx = tid; idx < C2 * 9; idx += 160) {
        int c = idx / 9, tap = idx - c * 9;
        int dy = tap / 3, dx = tap - dy * 3;
        float v = __half2float(
            g_y2h[(((size_t)b * C2 + c) * Himg + (h + dy - 1)) * Wimg + (w + dx - 1)]);
        float z = v * g_scale2[c] + g_shift2[c];
        s_in[idx] = z >= 0.f ? z : SLOPE * z;
    }
    __syncthreads();

    if (tid < C3) {
        float a = b3[tid];
        const float* wr = w3 + (size_t)tid * C2 * 9;
#pragma unroll 4
        for (int i = 0; i < C2 * 9; ++i) a = fmaf(s_in[i], __ldg(&wr[i]), a);
        float z = a * g_scale3[tid] + g_shift3[tid];
        z = z >= 0.f ? z : SLOPE * z;
        s_z[tid] = z;
        out[(kind ? OFF_ZP : OFF_ZA) + b * C3 + tid] = z;
    }
    __syncthreads();

    if (kind == 0) {
        for (int j = tid; j < 147; j += 160) {
            float r = recon_b[j];
            const float* wr = recon_w + (size_t)j * C3;
#pragma unroll 4
            for (int k = 0; k < C3; ++k) r = fmaf(s_z[k], __ldg(&wr[k]), r);
            out[OFF_XR + b * 147 + j] = r;
        }
        for (int idx = tid; idx < 147; idx += 160) {
            int c = idx / 49, rem = idx - c * 49;
            int pyy = rem / 7, pxx = rem - pyy * 7;
            out[OFF_XA + b * 147 + idx] =
                x[(((size_t)b * C0 + c) * Himg + (h - 3 + pyy)) * Wimg + (w - 3 + pxx)];
        }
    }
}

// --------------------------------- launch ------------------------------------
extern "C" void kernel_launch(void* const* d_in, const int* in_sizes, int n_in,
                              void* d_out, int out_size)
{
    const float* x        = (const float*)d_in[0];
    const int*   anchors  = (const int*)  d_in[1];
    const int*   positives= (const int*)  d_in[2];
    const float* c1w = (const float*)d_in[3];
    const float* c1b = (const float*)d_in[4];
    const float* g1  = (const float*)d_in[5];
    const float* be1 = (const float*)d_in[6];
    const float* c2w = (const float*)d_in[7];
    const float* c2b = (const float*)d_in[8];
    const float* g2  = (const float*)d_in[9];
    const float* be2 = (const float*)d_in[10];
    const float* c3w = (const float*)d_in[11];
    const float* c3b = (const float*)d_in[12];
    const float* g3  = (const float*)d_in[13];
    const float* be3 = (const float*)d_in[14];
    const float* rw  = (const float*)d_in[15];
    const float* rb  = (const float*)d_in[16];
    float* out = (float*)d_out;

    __half *y1hp, *y2hp; unsigned *y1pk, *y2pk, *w2pk, *w3pk;
    float *ps1, *pq1, *ps2, *pq2, *ps3, *pq3;
    float *sc1, *sh1, *sc2, *sh2, *sc3, *sh3;
    cudaGetSymbolAddress((void**)&y1hp, g_y1h);
    cudaGetSymbolAddress((void**)&y2hp, g_y2h);
    cudaGetSymbolAddress((void**)&y1pk, g_y1pk);
    cudaGetSymbolAddress((void**)&y2pk, g_y2pk);
    cudaGetSymbolAddress((void**)&w2pk, g_w2pk);
    cudaGetSymbolAddress((void**)&w3pk, g_w3pk);
    cudaGetSymbolAddress((void**)&ps1, g_ps1);
    cudaGetSymbolAddress((void**)&pq1, g_pq1);
    cudaGetSymbolAddress((void**)&ps2, g_ps2);
    cudaGetSymbolAddress((void**)&pq2, g_pq2);
    cudaGetSymbolAddress((void**)&ps3, g_ps3);
    cudaGetSymbolAddress((void**)&pq3, g_pq3);
    cudaGetSymbolAddress((void**)&sc1, g_scale1);
    cudaGetSymbolAddress((void**)&sh1, g_shift1);
    cudaGetSymbolAddress((void**)&sc2, g_scale2);
    cudaGetSymbolAddress((void**)&sh2, g_shift2);
    cudaGetSymbolAddress((void**)&sc3, g_scale3);
    cudaGetSymbolAddress((void**)&sh3, g_shift3);

    // dynamic smem: A + 2*B + reductions (words)
    const int smem2 = (C2 * ASTR1 + 2 * CP * BCHp + 8 * C2) * 4;
    const int smem3 = (C3 * ASTR1 + 2 * CP * BCHp + 8 * C3) * 4;
    cudaFuncSetAttribute(conv_tc_kernel<C1, C2, true, false>,
                         cudaFuncAttributeMaxDynamicSharedMemorySize, smem2);
    cudaFuncSetAttribute(conv_tc_kernel<C2, C3, false, true>,
                         cudaFuncAttributeMaxDynamicSharedMemorySize, smem3);

    // weight pre-pack (hi-only, tap-major k)
    {
        int tot2 = (C1 / CCH) * C2 * (KC / 2);
        int tot3 = (C2 / CCH) * C3 * (KC / 2);
        prep_weights<<<(tot2 + 255) / 256, 256>>>(c2w, C1, C2, w2pk);
        prep_weights<<<(tot3 + 255) / 256, 256>>>(c3w, C2, C3, w3pk);
    }

    // conv1 -> raw y1 (fp16) + stats
    dim3 grid1(8, 8, Bsz * (C1 / KOUT));
    conv1_kernel<C0, 3><<<grid1, 256>>>(x, c1w, c1b, y1hp, ps1, pq1, C1 / KOUT);
    bnfin_kernel<<<C1, 256>>>(ps1, pq1, g1, be1, sc1, sh1, NSLOT1);

    // pack bn1(lrelu(y1)) -> fp16 channel pairs
    {
        long long t4 = (long long)Bsz * (C1 / 2) * Himg * Wimg / 4;
        bnpack_pair_h<<<(unsigned)((t4 + 255) / 256), 256>>>(y1hp, sc1, sh1, y1pk, C1, t4);
    }

    // conv2 -> raw y2 (fp16) + stats (single-term, f32 acc)
    dim3 gridTC(Wimg / TCW, Himg / TCH, Bsz);   // 8 x 64 x 16
    conv_tc_kernel<C1, C2, true, false><<<gridTC, 256, smem2>>>(
        y1pk, w2pk, c2b, y2hp, ps2, pq2);
    bnfin_kernel<<<C2, 256>>>(ps2, pq2, g2, be2, sc2, sh2, NSLOT_TC);

    // pack bn2(lrelu(y2)) from fp16 source
    {
        long long t4 = (long long)Bsz * (C2 / 2) * Himg * Wimg / 4;
        bnpack_pair_h<<<(unsigned)((t4 + 255) / 256), 256>>>(y2hp, sc2, sh2, y2pk, C2, t4);
    }

    // conv3 -> stats only (single-term, f16 acc: 2x HMMA rate)
    conv_tc_kernel<C2, C3, false, true><<<gridTC, 256, smem3>>>(
        y2pk, w3pk, c3b, nullptr, ps3, pq3);
    bnfin_kernel<<<C3, 256>>>(ps3, pq3, g3, be3, sc3, sh3, NSLOT_TC);

    // final epilogue
    points_kernel<<<32, 160>>>(x, anchors, positives, c3w, c3b, rw, rb, out);
}

// round 17
// speedup vs baseline: 2.4885x; 1.1116x over previous
#include <cuda_runtime.h>
#include <cuda_fp16.h>
#include <cstddef>

// ---------------------------------------------------------------------------
// CUTSEncoder: conv1 (FFMA, fp16 out) -> conv2 (fp16 mma, f32 acc) ->
// conv3 (fp16 mma, f16 acc; stats only) -> BN finalize -> point epilogue
// (exact fp32 recompute of the 32 z3 points).
// Single-term Wh*Xh; fp16 channel-pair activations (one LDS.32 per mma B
// operand, tap-major k); 8x32 pixel tile (8 n-tiles per warp), 2 CTAs/SM;
// B halo double-buffered cp.async.
// ---------------------------------------------------------------------------

namespace {
constexpr int Bsz  = 16;
constexpr int Himg = 256;
constexpr int Wimg = 256;
constexpr int C0 = 3, C1 = 32, C2 = 64, C3 = 128;
constexpr float EPSV  = 1e-5f;
constexpr float SLOPE = 0.01f;
constexpr float NPIX  = 16.0f * 256.0f * 256.0f;

// conv1 (FFMA) tiling
constexpr int TILE  = 32;
constexpr int KOUT  = 16;
constexpr int NSLOT1 = 8 * 8 * Bsz;

// TC conv tiling: 256 pixels (8 rows x 32 cols), K chunk = 16 ch x 9 taps
constexpr int TCH = 8, TCW = 32;
constexpr int HR  = TCH + 2;            // 10 halo rows
constexpr int CCH = 16, KC = 144, KSTEPS = 9;
constexpr int CP  = CCH / 2;            // 8 channel-pair planes per chunk
constexpr int ASTR1 = 76;               // A row stride (words), hi-only
constexpr int BROW = 36;
constexpr int BCHp = HR * BROW;         // 360 words per pair-plane
constexpr int NSLOT_TC = 8 * 32 * Bsz;  // 4096 slots

// output layout
constexpr int OFF_XA = 0;
constexpr int OFF_XR = Bsz * 147;
constexpr int OFF_ZA = OFF_XR + Bsz * 147;
constexpr int OFF_ZP = OFF_ZA + Bsz * C3;
}

// ------------------------- scratch (device globals) -------------------------
__device__ __align__(16) __half g_y1h[(size_t)Bsz * C1 * Himg * Wimg];
__device__ __align__(16) __half g_y2h[(size_t)Bsz * C2 * Himg * Wimg];
// packed fp16 channel-pair activations: [(b*C/2+cp)*HW + pix] = {c+1, c}
__device__ __align__(16) unsigned g_y1pk[(size_t)Bsz * (C1 / 2) * Himg * Wimg];
__device__ __align__(16) unsigned g_y2pk[(size_t)Bsz * (C2 / 2) * Himg * Wimg];

__device__ __align__(16) unsigned g_w2pk[(C1 / CCH) * C2 * ASTR1];
__device__ __align__(16) unsigned g_w3pk[(C2 / CCH) * C3 * ASTR1];

__device__ float g_ps1[C1 * NSLOT1],   g_pq1[C1 * NSLOT1];
__device__ float g_ps2[C2 * NSLOT_TC], g_pq2[C2 * NSLOT_TC];
__device__ float g_ps3[C3 * NSLOT_TC], g_pq3[C3 * NSLOT_TC];

__device__ float g_scale1[C1], g_shift1[C1];
__device__ float g_scale2[C2], g_shift2[C2];
__device__ float g_scale3[C3], g_shift3[C3];

// ------------------------------- helpers ------------------------------------
__device__ __forceinline__ unsigned f16x2pack(float a, float b) {
    unsigned w;
    asm("cvt.rn.f16x2.f32 %0, %1, %2;" : "=r"(w) : "f"(a), "f"(b));
    return w;  // [31:16]=f16(a), [15:0]=f16(b)
}

__device__ __forceinline__ void mma_f16(float* d, const unsigned* a,
                                        unsigned b0, unsigned b1) {
    asm volatile(
        "mma.sync.aligned.m16n8k16.row.col.f32.f16.f16.f32 "
        "{%0,%1,%2,%3}, {%4,%5,%6,%7}, {%8,%9}, {%0,%1,%2,%3};"
        : "+f"(d[0]), "+f"(d[1]), "+f"(d[2]), "+f"(d[3])
        : "r"(a[0]), "r"(a[1]), "r"(a[2]), "r"(a[3]), "r"(b0), "r"(b1));
}

__device__ __forceinline__ void mma_f16h(unsigned* d, const unsigned* a,
                                         unsigned b0, unsigned b1) {
    asm volatile(
        "mma.sync.aligned.m16n8k16.row.col.f16.f16.f16.f16 "
        "{%0,%1}, {%2,%3,%4,%5}, {%6,%7}, {%0,%1};"
        : "+r"(d[0]), "+r"(d[1])
        : "r"(a[0]), "r"(a[1]), "r"(a[2]), "r"(a[3]), "r"(b0), "r"(b1));
}

__device__ __forceinline__ void cp_async16(void* smem, const void* gmem) {
    unsigned saddr = (unsigned)__cvta_generic_to_shared(smem);
    asm volatile("cp.async.cg.shared.global [%0], [%1], 16;"
                 :: "r"(saddr), "l"(gmem));
}

__device__ __forceinline__ void cp_async4z(void* smem, const void* gmem, int sz) {
    unsigned saddr = (unsigned)__cvta_generic_to_shared(smem);
    asm volatile("cp.async.ca.shared.global [%0], [%1], 4, %2;"
                 :: "r"(saddr), "l"(gmem), "r"(sz));
}

// --------------- weight pre-pack (fp16 hi-only, tap-major k) -----------------
__global__ void prep_weights(const float* __restrict__ w, int CIN, int M,
                             unsigned* __restrict__ dst)
{
    int idx = blockIdx.x * blockDim.x + threadIdx.x;
    int NCH = CIN / CCH;
    int tot = NCH * M * (KC / 2);
    if (idx >= tot) return;
    int cc  = idx / (M * (KC / 2));
    int rem = idx - cc * M * (KC / 2);
    int m   = rem / (KC / 2);
    int pr  = rem - m * (KC / 2);
    int ks = pr >> 3, j = pr & 7, kh = j >> 2, qq = j & 3;
    int ke = ks * 16 + kh * 8 + 2 * qq;      // even k; tap = ke>>4, c = ke&15
    int tap = ke >> 4;
    int c   = ke & 15;
    int cg  = cc * CCH + c;
    float we = w[((size_t)m * CIN + cg) * 9 + tap];
    float wo = w[((size_t)m * CIN + cg + 1) * 9 + tap];
    size_t base = ((size_t)cc * M + m) * ASTR1 + ks * 8 + qq * 2;
    dst[base + kh] = f16x2pack(wo, we);
}

// ------- bnpack (fp16 src): NCHW half -> fp16 channel-pair words -------------
__global__ void __launch_bounds__(256) bnpack_pair_h(
    const __half* __restrict__ raw,
    const float* __restrict__ scale, const float* __restrict__ shift,
    unsigned* __restrict__ dst, int C, long long total4)
{
    long long i4 = (long long)blockIdx.x * blockDim.x + threadIdx.x;
    if (i4 >= total4) return;
    int plane = (int)(i4 >> 14);
    int pq = (int)(i4 & 16383);
    int half = C >> 1;
    int cp = plane % half, b = plane / half;
    int c0 = cp * 2;
    const __half2* s0p = (const __half2*)(raw + (((size_t)b * C + c0) << 16)) + pq * 2;
    const __half2* s1p = (const __half2*)(raw + (((size_t)b * C + c0 + 1) << 16)) + pq * 2;
    float2 p00 = __half22float2(s0p[0]), p01 = __half22float2(s0p[1]);
    float2 p10 = __half22float2(s1p[0]), p11 = __half22float2(s1p[1]);
    float s0 = __ldg(&scale[c0]),     h0 = __ldg(&shift[c0]);
    float s1 = __ldg(&scale[c0 + 1]), h1 = __ldg(&shift[c0 + 1]);
    float a0[4] = {p00.x, p00.y, p01.x, p01.y};
    float a1[4] = {p10.x, p10.y, p11.x, p11.y};
    unsigned o[4];
#pragma unroll
    for (int j = 0; j < 4; ++j) {
        float z0 = a0[j] * s0 + h0; z0 = z0 >= 0.f ? z0 : SLOPE * z0;
        float z1 = a1[j] * s1 + h1; z1 = z1 >= 0.f ? z1 : SLOPE * z1;
        o[j] = f16x2pack(z1, z0);
    }
    ((uint4*)dst)[i4] = make_uint4(o[0], o[1], o[2], o[3]);
}

// ---------------- TC conv3x3 (fp16 single-term, 8x32 tile) -------------------
// 256 threads = 8 warps = 2 M-warps x 4 N-warps; each N-warp covers rows
// {nw, nw+4} -> 8 n-tiles per warp. 2 CTAs/SM.
template <int CIN, int M, bool STORE, bool HACC>
__global__ void __launch_bounds__(256, 2) conv_tc_kernel(
    const unsigned* __restrict__ in,    // fp16 channel-pair activations
    const unsigned* __restrict__ wpk,   // packed fp16 weights [chunk][M][ASTR1]
    const float* __restrict__ bias,
    __half* __restrict__ out_h,         // raw conv output (fp16, NCHW)
    float* __restrict__ psum,
    float* __restrict__ psq)
{
    constexpr int NMT = M / 32;
    constexpr int NCH = CIN / CCH;
    constexpr int ASZ = M * ASTR1;      // words, single A buffer
    constexpr int BSZ = CP * BCHp;      // words per B buffer (2880)

    extern __shared__ unsigned char smem_raw[];
    unsigned* Apk = (unsigned*)smem_raw;          // ASZ
    unsigned* Bp  = Apk + ASZ;                    // 2 * BSZ
    float* red_s = (float*)(Bp + 2 * BSZ);        // 4*M
    float* red_q = red_s + 4 * M;

    const int tid = threadIdx.x;
    const int lane = tid & 31, wid = tid >> 5;
    const int mw = wid >> 2, nw = wid & 3;
    const int q = lane & 3, g = lane >> 2;
    const int bx = blockIdx.x, by = blockIdx.y, b = blockIdx.z;
    const int h0 = by * TCH, w0 = bx * TCW;

    auto stageB = [&](int cc) {
        const int cpbase = cc * CP;
        unsigned* Bd = Bp + (cc & 1) * BSZ;
        for (int idx = tid; idx < CP * HR * 34; idx += 256) {
            int p   = idx / (HR * 34);
            int rem = idx - p * (HR * 34);
            int r   = rem / 34;
            int col = rem - r * 34;
            int gh = h0 + r - 1, gw = w0 + col - 1;
            bool ok = (unsigned)gh < (unsigned)Himg && (unsigned)gw < (unsigned)Wimg;
            const unsigned* src = ok
                ? &in[(((size_t)b * (CIN / 2) + cpbase + p) << 16) + gh * 256 + gw] : in;
            cp_async4z(Bd + p * BCHp + r * BROW + col, src, ok ? 4 : 0);
        }
        asm volatile("cp.async.commit_group;" ::: "memory");
    };

    stageB(0);

    float    accf[HACC ? 1 : NMT][8][4];
    unsigned acch[HACC ? NMT : 1][8][2];
#pragma unroll
    for (int t = 0; t < (HACC ? NMT : 1); ++t)
#pragma unroll
        for (int nt = 0; nt < 8; ++nt) { acch[t][nt][0] = 0u; acch[t][nt][1] = 0u; }
#pragma unroll
    for (int t = 0; t < (HACC ? 1 : NMT); ++t)
#pragma unroll
        for (int nt = 0; nt < 8; ++nt)
#pragma unroll
            for (int i = 0; i < 4; ++i) accf[t][nt][i] = 0.f;

    // n-tile nt: row (nw + (nt>>2)*4), cols (nt&3)*8
    const int poff0 = nw * BROW + g;
    const int poff1 = (nw + 4) * BROW + g;
    const int qrow0 = q * BCHp;
    const int qrow1 = (q + 4) * BCHp;

#pragma unroll 1
    for (int cc = 0; cc < NCH; ++cc) {
        {
            const unsigned* srcA = wpk + (size_t)cc * ASZ;
            for (int idx = tid; idx < ASZ / 4; idx += 256)
                cp_async16(Apk + idx * 4, srcA + idx * 4);
            asm volatile("cp.async.commit_group;" ::: "memory");
        }
        if (cc + 1 < NCH) {
            stageB(cc + 1);
            asm volatile("cp.async.wait_group 1;" ::: "memory");
        } else {
            asm volatile("cp.async.wait_group 0;" ::: "memory");
        }
        __syncthreads();

        const unsigned* Bb = Bp + (cc & 1) * BSZ;

#pragma unroll
        for (int ks = 0; ks < KSTEPS; ++ks) {
            const int tapoff = (ks / 3) * BROW + (ks % 3);
            const int abase = ks * 8 + q * 2;
            unsigned bh[8][2];
#pragma unroll
            for (int nt = 0; nt < 8; ++nt) {
                const int p = ((nt < 4) ? poff0 : poff1) + tapoff + (nt & 3) * 8;
                bh[nt][0] = Bb[qrow0 + p];
                bh[nt][1] = Bb[qrow1 + p];
            }
#pragma unroll
            for (int t = 0; t < NMT; ++t) {
                const int r0w = (mw * (M / 2) + t * 16 + g) * ASTR1 + abase;
                const int r1w = r0w + 8 * ASTR1;
                uint2 xh = *(const uint2*)(Apk + r0w);
                uint2 yh = *(const uint2*)(Apk + r1w);
                unsigned ah[4] = {xh.x, yh.x, xh.y, yh.y};
                if (HACC) {
#pragma unroll
                    for (int nt = 0; nt < 8; ++nt)
                        mma_f16h(acch[t][nt], ah, bh[nt][0], bh[nt][1]);
                } else {
#pragma unroll
                    for (int nt = 0; nt < 8; ++nt)
                        mma_f16(accf[t][nt], ah, bh[nt][0], bh[nt][1]);
                }
            }
        }
        __syncthreads();
    }

    // ---- epilogue: bias, optional fp16 store, per-channel stats ----
#pragma unroll
    for (int t = 0; t < NMT; ++t) {
        const int r0 = mw * (M / 2) + t * 16 + g, r1 = r0 + 8;
        const float bv0 = __ldg(&bias[r0]), bv1 = __ldg(&bias[r1]);
        float s0 = 0.f, q0 = 0.f, s1 = 0.f, q1 = 0.f;
#pragma unroll
        for (int nt = 0; nt < 8; ++nt) {
            float v0, v1, v2, v3;
            if (HACC) {
                float2 f01 = __half22float2(*(__half2*)&acch[t][nt][0]);
                float2 f23 = __half22float2(*(__half2*)&acch[t][nt][1]);
                v0 = f01.x + bv0; v1 = f01.y + bv0;
                v2 = f23.x + bv1; v3 = f23.y + bv1;
            } else {
                v0 = accf[t][nt][0] + bv0; v1 = accf[t][nt][1] + bv0;
                v2 = accf[t][nt][2] + bv1; v3 = accf[t][nt][3] + bv1;
            }
            if (STORE) {
                int wcol = w0 + (nt & 3) * 8 + 2 * q;
                int hrow = h0 + nw + ((nt >> 2) << 2);
                *(unsigned*)(out_h + (((size_t)b * M + r0) * Himg + hrow) * Wimg + wcol) =
                    f16x2pack(v1, v0);
                *(unsigned*)(out_h + (((size_t)b * M + r1) * Himg + hrow) * Wimg + wcol) =
                    f16x2pack(v3, v2);
            }
            s0 += v0 + v1; q0 += v0 * v0 + v1 * v1;
            s1 += v2 + v3; q1 += v2 * v2 + v3 * v3;
        }
        s0 += __shfl_xor_sync(0xffffffffu, s0, 1);
        s0 += __shfl_xor_sync(0xffffffffu, s0, 2);
        q0 += __shfl_xor_sync(0xffffffffu, q0, 1);
        q0 += __shfl_xor_sync(0xffffffffu, q0, 2);
        s1 += __shfl_xor_sync(0xffffffffu, s1, 1);
        s1 += __shfl_xor_sync(0xffffffffu, s1, 2);
        q1 += __shfl_xor_sync(0xffffffffu, q1, 1);
        q1 += __shfl_xor_sync(0xffffffffu, q1, 2);
        if (q == 0) {
            red_s[nw * M + r0] = s0; red_q[nw * M + r0] = q0;
            red_s[nw * M + r1] = s1; red_q[nw * M + r1] = q1;
        }
    }
    __syncthreads();
    if (tid < M) {
        float s = 0.f, qq = 0.f;
#pragma unroll
        for (int w = 0; w < 4; ++w) { s += red_s[w * M + tid]; qq += red_q[w * M + tid]; }
        int slot = (b * 32 + by) * 8 + bx;
        psum[tid * NSLOT_TC + slot] = s;
        psq [tid * NSLOT_TC + slot] = qq;
    }
}

// -------------------------- conv1 (FFMA, cin=3, fp16 out) --------------------
template <int CIN, int CCHUNK>
__global__ void __launch_bounds__(256) conv1_kernel(
    const float* __restrict__ in,
    const float* __restrict__ wgt,
    const float* __restrict__ bias,
    __half* __restrict__ out_h,
    float* __restrict__ psum,
    float* __restrict__ psq,
    int nCoutBlk)
{
    __shared__ float s_in[CCHUNK][TILE + 2][TILE + 2];
    __shared__ float s_w[KOUT * CCHUNK * 9];
    __shared__ float s_rs[KOUT][8];
    __shared__ float s_rq[KOUT][8];

    const int tid = threadIdx.x;
    const int tx = tid & 15, ty = tid >> 4;
    const int bx = blockIdx.x, by = blockIdx.y;
    const int b = blockIdx.z / nCoutBlk;
    const int coutBase = (blockIdx.z % nCoutBlk) * KOUT;
    const int Cout = nCoutBlk * KOUT;
    const int px = tx * 2, py = ty * 2;
    const int h0 = by * TILE, w0 = bx * TILE;

    float acc[KOUT][4];
#pragma unroll
    for (int co = 0; co < KOUT; ++co) {
        acc[co][0] = 0.f; acc[co][1] = 0.f; acc[co][2] = 0.f; acc[co][3] = 0.f;
    }

    for (int idx = tid; idx < CCHUNK * (TILE + 2) * (TILE + 2); idx += 256) {
        int c   = idx / ((TILE + 2) * (TILE + 2));
        int rem = idx - c * (TILE + 2) * (TILE + 2);
        int r   = rem / (TILE + 2);
        int col = rem - r * (TILE + 2);
        int gh = h0 + r - 1, gw = w0 + col - 1;
        float v = 0.f;
        if ((unsigned)gh < (unsigned)Himg && (unsigned)gw < (unsigned)Wimg)
            v = in[(((size_t)b * CIN + c) * Himg + gh) * Wimg + gw];
        (&s_in[0][0][0])[idx] = v;
    }
    for (int idx = tid; idx < KOUT * CCHUNK * 9; idx += 256) {
        int co  = idx / (CCHUNK * 9);
        int rem = idx - co * (CCHUNK * 9);
        s_w[idx] = wgt[((size_t)(coutBase + co) * CIN) * 9 + rem];
    }
    __syncthreads();

#pragma unroll
    for (int c = 0; c < CCHUNK; ++c)
#pragma unroll
        for (int dy = 0; dy < 3; ++dy)
#pragma unroll
            for (int dx = 0; dx < 3; ++dx) {
                float i00 = s_in[c][py + dy][px + dx];
                float i01 = s_in[c][py + dy][px + dx + 1];
                float i10 = s_in[c][py + dy + 1][px + dx];
                float i11 = s_in[c][py + dy + 1][px + dx + 1];
#pragma unroll
                for (int co = 0; co < KOUT; ++co) {
                    float wv = s_w[(co * CCHUNK + c) * 9 + dy * 3 + dx];
                    acc[co][0] = fmaf(i00, wv, acc[co][0]);
                    acc[co][1] = fmaf(i01, wv, acc[co][1]);
                    acc[co][2] = fmaf(i10, wv, acc[co][2]);
                    acc[co][3] = fmaf(i11, wv, acc[co][3]);
                }
            }

    const int lane = tid & 31, wrp = tid >> 5;
#pragma unroll 1
    for (int co = 0; co < KOUT; ++co) {
        float bv = __ldg(&bias[coutBase + co]);
        float v0 = acc[co][0] + bv, v1 = acc[co][1] + bv;
        float v2 = acc[co][2] + bv, v3 = acc[co][3] + bv;
        size_t rowb = ((size_t)b * Cout + coutBase + co) * Himg;
        *(unsigned*)(out_h + (rowb + h0 + py) * Wimg + w0 + px)     = f16x2pack(v1, v0);
        *(unsigned*)(out_h + (rowb + h0 + py + 1) * Wimg + w0 + px) = f16x2pack(v3, v2);
        float s = v0 + v1 + v2 + v3;
        float qv = v0 * v0 + v1 * v1 + v2 * v2 + v3 * v3;
#pragma unroll
        for (int o = 16; o > 0; o >>= 1) {
            s  += __shfl_down_sync(0xffffffffu, s, o);
            qv += __shfl_down_sync(0xffffffffu, qv, o);
        }
        if (lane == 0) { s_rs[co][wrp] = s; s_rq[co][wrp] = qv; }
    }
    __syncthreads();
    if (tid < KOUT) {
        float s = 0.f, qv = 0.f;
#pragma unroll
        for (int w = 0; w < 8; ++w) { s += s_rs[tid][w]; qv += s_rq[tid][w]; }
        int slot = (by * gridDim.x + bx) * Bsz + b;
        psum[(coutBase + tid) * NSLOT1 + slot] = s;
        psq [(coutBase + tid) * NSLOT1 + slot] = qv;
    }
}

// ------------------------- BN stats finalize ---------------------------------
__global__ void __launch_bounds__(256) bnfin_kernel(
    const float* __restrict__ psum, const float* __restrict__ psq,
    const float* __restrict__ gamma, const float* __restrict__ beta,
    float* __restrict__ scale, float* __restrict__ shift, int nslot)
{
    __shared__ float ss[256], sq[256];
    int c = blockIdx.x;
    float s = 0.f, q = 0.f;
    for (int i = threadIdx.x; i < nslot; i += 256) {
        s += psum[c * nslot + i];
        q += psq [c * nslot + i];
    }
    ss[threadIdx.x] = s; sq[threadIdx.x] = q;
    __syncthreads();
    for (int o = 128; o > 0; o >>= 1) {
        if (threadIdx.x < o) {
            ss[threadIdx.x] += ss[threadIdx.x + o];
            sq[threadIdx.x] += sq[threadIdx.x + o];
        }
        __syncthreads();
    }
    if (threadIdx.x == 0) {
        float mean = ss[0] / NPIX;
        float var  = sq[0] / NPIX - mean * mean;
        float sc   = gamma[c] * rsqrtf(var + EPSV);
        scale[c] = sc;
        shift[c] = beta[c] - mean * sc;
    }
}

// ---------------- final: 32 point z3 vectors + recon + patches ---------------
__global__ void __launch_bounds__(160) points_kernel(
    const float* __restrict__ x,
    const int* __restrict__ anchors,
    const int* __restrict__ positives,
    const float* __restrict__ w3, const float* __restrict__ b3,
    const float* __restrict__ recon_w, const float* __restrict__ recon_b,
    float* __restrict__ out)
{
    __shared__ float s_in[C2 * 9];
    __shared__ float s_z[C3];
    const int kind = blockIdx.x & 1;
    const int b = blockIdx.x >> 1;
    const int* pts = kind ? positives : anchors;
    const int h = pts[b * 8 + 6];
    const int w = pts[b * 8 + 7];
    const int tid = threadIdx.x;

    for (int idx = tid; idx < C2 * 9; idx += 160) {
        int c = idx / 9, tap = idx - c * 9;
        int dy = tap / 3, dx = tap - dy * 3;
        float v = __half2float(
            g_y2h[(((size_t)b * C2 + c) * Himg + (h + dy - 1)) * Wimg + (w + dx - 1)]);
        float z = v * g_scale2[c] + g_shift2[c];
        s_in[idx] = z >= 0.f ? z : SLOPE * z;
    }
    __syncthreads();

    if (tid < C3) {
        float a = b3[tid];
        const float* wr = w3 + (size_t)tid * C2 * 9;
#pragma unroll 4
        for (int i = 0; i < C2 * 9; ++i) a = fmaf(s_in[i], __ldg(&wr[i]), a);
        float z = a * g_scale3[tid] + g_shift3[tid];
        z = z >= 0.f ? z : SLOPE * z;
        s_z[tid] = z;
        out[(kind ? OFF_ZP : OFF_ZA) + b * C3 + tid] = z;
    }
    __syncthreads();

    if (kind == 0) {
        for (int j = tid; j < 147; j += 160) {
            float r = recon_b[j];
            const float* wr = recon_w + (size_t)j * C3;
#pragma unroll 4
            for (int k = 0; k < C3; ++k) r = fmaf(s_z[k], __ldg(&wr[k]), r);
            out[OFF_XR + b * 147 + j] = r;
        }
        for (int idx = tid; idx < 147; idx += 160) {
            int c = idx / 49, rem = idx - c * 49;
            int pyy = rem / 7, pxx = rem - pyy * 7;
            out[OFF_XA + b * 147 + idx] =
                x[(((size_t)b * C0 + c) * Himg + (h - 3 + pyy)) * Wimg + (w - 3 + pxx)];
        }
    }
}

// --------------------------------- launch ------------------------------------
extern "C" void kernel_launch(void* const* d_in, const int* in_sizes, int n_in,
                              void* d_out, int out_size)
{
    const float* x        = (const float*)d_in[0];
    const int*   anchors  = (const int*)  d_in[1];
    const int*   positives= (const int*)  d_in[2];
    const float* c1w = (const float*)d_in[3];
    const float* c1b = (const float*)d_in[4];
    const float* g1  = (const float*)d_in[5];
    const float* be1 = (const float*)d_in[6];
    const float* c2w = (const float*)d_in[7];
    const float* c2b = (const float*)d_in[8];
    const float* g2  = (const float*)d_in[9];
    const float* be2 = (const float*)d_in[10];
    const float* c3w = (const float*)d_in[11];
    const float* c3b = (const float*)d_in[12];
    const float* g3  = (const float*)d_in[13];
    const float* be3 = (const float*)d_in[14];
    const float* rw  = (const float*)d_in[15];
    const float* rb  = (const float*)d_in[16];
    float* out = (float*)d_out;

    __half *y1hp, *y2hp; unsigned *y1pk, *y2pk, *w2pk, *w3pk;
    float *ps1, *pq1, *ps2, *pq2, *ps3, *pq3;
    float *sc1, *sh1, *sc2, *sh2, *sc3, *sh3;
    cudaGetSymbolAddress((void**)&y1hp, g_y1h);
    cudaGetSymbolAddress((void**)&y2hp, g_y2h);
    cudaGetSymbolAddress((void**)&y1pk, g_y1pk);
    cudaGetSymbolAddress((void**)&y2pk, g_y2pk);
    cudaGetSymbolAddress((void**)&w2pk, g_w2pk);
    cudaGetSymbolAddress((void**)&w3pk, g_w3pk);
    cudaGetSymbolAddress((void**)&ps1, g_ps1);
    cudaGetSymbolAddress((void**)&pq1, g_pq1);
    cudaGetSymbolAddress((void**)&ps2, g_ps2);
    cudaGetSymbolAddress((void**)&pq2, g_pq2);
    cudaGetSymbolAddress((void**)&ps3, g_ps3);
    cudaGetSymbolAddress((void**)&pq3, g_pq3);
    cudaGetSymbolAddress((void**)&sc1, g_scale1);
    cudaGetSymbolAddress((void**)&sh1, g_shift1);
    cudaGetSymbolAddress((void**)&sc2, g_scale2);
    cudaGetSymbolAddress((void**)&sh2, g_shift2);
    cudaGetSymbolAddress((void**)&sc3, g_scale3);
    cudaGetSymbolAddress((void**)&sh3, g_shift3);

    // dynamic smem: A + 2*B + reductions (words)
    const int smem2 = (C2 * ASTR1 + 2 * CP * BCHp + 8 * C2) * 4;
    const int smem3 = (C3 * ASTR1 + 2 * CP * BCHp + 8 * C3) * 4;
    cudaFuncSetAttribute(conv_tc_kernel<C1, C2, true, false>,
                         cudaFuncAttributeMaxDynamicSharedMemorySize, smem2);
    cudaFuncSetAttribute(conv_tc_kernel<C2, C3, false, true>,
                         cudaFuncAttributeMaxDynamicSharedMemorySize, smem3);

    // weight pre-pack (hi-only, tap-major k)
    {
        int tot2 = (C1 / CCH) * C2 * (KC / 2);
        int tot3 = (C2 / CCH) * C3 * (KC / 2);
        prep_weights<<<(tot2 + 255) / 256, 256>>>(c2w, C1, C2, w2pk);
        prep_weights<<<(tot3 + 255) / 256, 256>>>(c3w, C2, C3, w3pk);
    }

    // conv1 -> raw y1 (fp16) + stats
    dim3 grid1(8, 8, Bsz * (C1 / KOUT));
    conv1_kernel<C0, 3><<<grid1, 256>>>(x, c1w, c1b, y1hp, ps1, pq1, C1 / KOUT);
    bnfin_kernel<<<C1, 256>>>(ps1, pq1, g1, be1, sc1, sh1, NSLOT1);

    // pack bn1(lrelu(y1)) -> fp16 channel pairs
    {
        long long t4 = (long long)Bsz * (C1 / 2) * Himg * Wimg / 4;
        bnpack_pair_h<<<(unsigned)((t4 + 255) / 256), 256>>>(y1hp, sc1, sh1, y1pk, C1, t4);
    }

    // conv2 -> raw y2 (fp16) + stats (single-term, f32 acc)
    dim3 gridTC(Wimg / TCW, Himg / TCH, Bsz);   // 8 x 32 x 16
    conv_tc_kernel<C1, C2, true, false><<<gridTC, 256, smem2>>>(
        y1pk, w2pk, c2b, y2hp, ps2, pq2);
    bnfin_kernel<<<C2, 256>>>(ps2, pq2, g2, be2, sc2, sh2, NSLOT_TC);

    // pack bn2(lrelu(y2)) from fp16 source
    {
        long long t4 = (long long)Bsz * (C2 / 2) * Himg * Wimg / 4;
        bnpack_pair_h<<<(unsigned)((t4 + 255) / 256), 256>>>(y2hp, sc2, sh2, y2pk, C2, t4);
    }

    // conv3 -> stats only (single-term, f16 acc)
    conv_tc_kernel<C2, C3, false, true><<<gridTC, 256, smem3>>>(
        y2pk, w3pk, c3b, nullptr, ps3, pq3);
    bnfin_kernel<<<C3, 256>>>(ps3, pq3, g3, be3, sc3, sh3, NSLOT_TC);

    // final epilogue
    points_kernel<<<32, 160>>>(x, anchors, positives, c3w, c3b, rw, rb, out);
}